// round 1
// baseline (speedup 1.0000x reference)
#include <cuda_runtime.h>
#include <math.h>

#define ED   1024
#define NH   16
#define HD   64
#define SEQ  577
#define BATCH 16
#define MROWS (BATCH * SEQ)   // 9232

// Scratch (no runtime allocation allowed)
__device__ float g_q[(size_t)MROWS * ED];
__device__ float g_k[(size_t)MROWS * ED];
__device__ float g_v[(size_t)MROWS * ED];
__device__ float g_o[(size_t)MROWS * ED];

// C[m][n] = sum_k A[m][k] * W[n][k] + bias[n]
// A: [M,1024] row-major, W: [1024,1024] row-major (both K-contiguous → "NT" GEMM)
__global__ __launch_bounds__(256) void gemm_nt_kernel(
    const float* __restrict__ A, const float* __restrict__ W,
    const float* __restrict__ bias, float* __restrict__ C, int M)
{
    // K-transposed tiles so the micro-kernel reads are contiguous float4s.
    // stride 68 floats = 272 B (16B-aligned per row).
    __shared__ float As[32][68];
    __shared__ float Ws[32][68];

    int tid = threadIdx.x;
    int tx = tid & 15, ty = tid >> 4;
    int bm = blockIdx.y * 64, bn = blockIdx.x * 64;

    float acc[4][4] = {};

    int lrow = tid >> 5;   // 0..7
    int lk   = tid & 31;   // 0..31

    for (int k0 = 0; k0 < ED; k0 += 32) {
        #pragma unroll
        for (int i = 0; i < 8; i++) {
            int row = i * 8 + lrow;          // 0..63
            int am = bm + row;
            float av = (am < M) ? A[(size_t)am * ED + k0 + lk] : 0.f;
            As[lk][row] = av;
            Ws[lk][row] = W[(size_t)(bn + row) * ED + k0 + lk];
        }
        __syncthreads();

        #pragma unroll
        for (int kk = 0; kk < 32; kk++) {
            float4 a4 = *(const float4*)&As[kk][ty * 4];
            float4 b4 = *(const float4*)&Ws[kk][tx * 4];
            float a[4] = {a4.x, a4.y, a4.z, a4.w};
            float b[4] = {b4.x, b4.y, b4.z, b4.w};
            #pragma unroll
            for (int i = 0; i < 4; i++)
                #pragma unroll
                for (int j = 0; j < 4; j++)
                    acc[i][j] += a[i] * b[j];
        }
        __syncthreads();
    }

    #pragma unroll
    for (int i = 0; i < 4; i++) {
        int m = bm + ty * 4 + i;
        if (m >= M) continue;
        #pragma unroll
        for (int j = 0; j < 4; j++) {
            int n = bn + tx * 4 + j;
            C[(size_t)m * ED + n] = acc[i][j] + bias[n];
        }
    }
}

// 2D RoPE on q/k, tokens s>=1. Pair (d, d+32), d in [0,32):
//   out[d]    = x[d]*cos(gh*f) - x[d+32]*sin(gh*f)
//   out[d+32] = x[d+32]*cos(gw*f) + x[d]*sin(gw*f)
// where f = 10000^(-(d&15)/16)
__global__ void rope_kernel(float* __restrict__ q, float* __restrict__ k)
{
    int t = blockIdx.x * blockDim.x + threadIdx.x;
    const int total = BATCH * 576 * NH * 32;
    if (t >= total) return;

    int d = t & 31;
    int h = (t >> 5) & 15;
    int p = (t >> 9) % 576;
    int b = t / (576 << 9);
    int gh = p / 24, gw = p % 24;

    // log2(10000) = 13.287712379549449
    float invf = exp2f(-(float)(d & 15) * (13.287712379549449f / 16.f));
    float a1 = (float)gh * invf;
    float a2 = (float)gw * invf;
    float s1, c1, s2, c2;
    sincosf(a1, &s1, &c1);
    sincosf(a2, &s2, &c2);

    size_t base = ((size_t)(b * SEQ + (p + 1)) * ED) + (size_t)h * HD;

    float x1 = q[base + d], x2 = q[base + d + 32];
    q[base + d]      = x1 * c1 - x2 * s1;
    q[base + d + 32] = x2 * c2 + x1 * s2;

    x1 = k[base + d]; x2 = k[base + d + 32];
    k[base + d]      = x1 * c1 - x2 * s1;
    k[base + d + 32] = x2 * c2 + x1 * s2;
}

// Flash attention, fp32. One block = (b, h, 64-query tile); one thread = one query row.
// Online softmax over 10 key tiles of 64.
__global__ __launch_bounds__(64) void attn_kernel(
    const float* __restrict__ q, const float* __restrict__ k,
    const float* __restrict__ v, float* __restrict__ o)
{
    __shared__ float Ks[64][64];
    __shared__ float Vs[64][64];

    int tid = threadIdx.x;
    int b = blockIdx.z, h = blockIdx.y;
    int qi = blockIdx.x * 64 + tid;
    bool active = qi < SEQ;
    int qic = active ? qi : SEQ - 1;

    const float* qrow = q + ((size_t)(b * SEQ + qic) * ED) + (size_t)h * HD;
    float qreg[64], oacc[64];
    #pragma unroll
    for (int d = 0; d < 64; d++) { qreg[d] = qrow[d] * 0.125f; oacc[d] = 0.f; }

    float mval = -1e30f, lval = 0.f;
    const float* kb = k + (size_t)b * SEQ * ED + (size_t)h * HD;
    const float* vb = v + (size_t)b * SEQ * ED + (size_t)h * HD;

    for (int t0 = 0; t0 < SEQ; t0 += 64) {
        __syncthreads();
        #pragma unroll 4
        for (int i = 0; i < 64; i++) {
            bool ok = (t0 + i) < SEQ;
            Ks[i][tid] = ok ? kb[(size_t)(t0 + i) * ED + tid] : 0.f;
            Vs[i][tid] = ok ? vb[(size_t)(t0 + i) * ED + tid] : 0.f;
        }
        __syncthreads();

        float sc[64];
        float mnew = mval;
        #pragma unroll
        for (int j = 0; j < 64; j++) {
            const float4* kr = (const float4*)Ks[j];   // broadcast reads
            float a = 0.f;
            #pragma unroll
            for (int d4 = 0; d4 < 16; d4++) {
                float4 kv = kr[d4];
                a += qreg[4*d4+0]*kv.x + qreg[4*d4+1]*kv.y
                   + qreg[4*d4+2]*kv.z + qreg[4*d4+3]*kv.w;
            }
            sc[j] = (t0 + j < SEQ) ? a : -1e30f;
            mnew = fmaxf(mnew, sc[j]);
        }

        float alpha = __expf(mval - mnew);
        mval = mnew;
        lval *= alpha;
        #pragma unroll
        for (int d = 0; d < 64; d++) oacc[d] *= alpha;

        #pragma unroll
        for (int j = 0; j < 64; j++) {
            float pw = __expf(sc[j] - mnew);
            lval += pw;
            const float4* vr = (const float4*)Vs[j];
            #pragma unroll
            for (int d4 = 0; d4 < 16; d4++) {
                float4 vv = vr[d4];
                oacc[4*d4+0] += pw * vv.x;
                oacc[4*d4+1] += pw * vv.y;
                oacc[4*d4+2] += pw * vv.z;
                oacc[4*d4+3] += pw * vv.w;
            }
        }
    }

    if (active) {
        float inv = 1.f / lval;
        float* orow = o + ((size_t)(b * SEQ + qi) * ED) + (size_t)h * HD;
        #pragma unroll
        for (int d = 0; d < 64; d++) orow[d] = oacc[d] * inv;
    }
}

extern "C" void kernel_launch(void* const* d_in, const int* in_sizes, int n_in,
                              void* d_out, int out_size)
{
    const float* hs = (const float*)d_in[0];
    const float* Wq = (const float*)d_in[1];
    const float* bq = (const float*)d_in[2];
    const float* Wk = (const float*)d_in[3];
    const float* bk = (const float*)d_in[4];
    const float* Wv = (const float*)d_in[5];
    const float* bv = (const float*)d_in[6];
    const float* Wo = (const float*)d_in[7];
    const float* bo = (const float*)d_in[8];
    float* out = (float*)d_out;

    float *qb, *kb, *vb, *ob;
    cudaGetSymbolAddress((void**)&qb, g_q);
    cudaGetSymbolAddress((void**)&kb, g_k);
    cudaGetSymbolAddress((void**)&vb, g_v);
    cudaGetSymbolAddress((void**)&ob, g_o);

    dim3 ggrid(ED / 64, (MROWS + 63) / 64);   // (16, 145)

    gemm_nt_kernel<<<ggrid, 256>>>(hs, Wq, bq, qb, MROWS);
    gemm_nt_kernel<<<ggrid, 256>>>(hs, Wk, bk, kb, MROWS);
    gemm_nt_kernel<<<ggrid, 256>>>(hs, Wv, bv, vb, MROWS);

    int rt = BATCH * 576 * NH * 32;
    rope_kernel<<<(rt + 255) / 256, 256>>>(qb, kb);

    attn_kernel<<<dim3((SEQ + 63) / 64, NH, BATCH), 64>>>(qb, kb, vb, ob);

    gemm_nt_kernel<<<ggrid, 256>>>(ob, Wo, bo, out, MROWS);
}

// round 3
// speedup vs baseline: 1.8036x; 1.8036x over previous
#include <cuda_runtime.h>
#include <cuda_bf16.h>
#include <cstdint>
#include <math.h>

#define ED   1024
#define NH   16
#define HD   64
#define SEQ  577
#define BATCH 16
#define MROWS (BATCH * SEQ)   // 9232

// ---------------- scratch (no runtime allocation allowed) ----------------
__device__ float g_q[(size_t)MROWS * ED];
__device__ float g_k[(size_t)MROWS * ED];
__device__ float g_v[(size_t)MROWS * ED];
__device__ float g_o[(size_t)MROWS * ED];

__device__ __nv_bfloat16 g_hsh[(size_t)MROWS * ED];
__device__ __nv_bfloat16 g_hsl[(size_t)MROWS * ED];
__device__ __nv_bfloat16 g_oh[(size_t)MROWS * ED];
__device__ __nv_bfloat16 g_ol[(size_t)MROWS * ED];
__device__ __nv_bfloat16 g_wh[4][(size_t)ED * ED];
__device__ __nv_bfloat16 g_wl[4][(size_t)ED * ED];

// ---------------- fp32 -> bf16 hi/lo split ----------------
__global__ void cvt_split_kernel(const float* __restrict__ x,
                                 __nv_bfloat16* __restrict__ h,
                                 __nv_bfloat16* __restrict__ l, int n4)
{
    int i = blockIdx.x * blockDim.x + threadIdx.x;
    if (i >= n4) return;
    float4 v = ((const float4*)x)[i];
    __nv_bfloat16 h0 = __float2bfloat16(v.x);
    __nv_bfloat16 h1 = __float2bfloat16(v.y);
    __nv_bfloat16 h2 = __float2bfloat16(v.z);
    __nv_bfloat16 h3 = __float2bfloat16(v.w);
    __nv_bfloat16 l0 = __float2bfloat16(v.x - __bfloat162float(h0));
    __nv_bfloat16 l1 = __float2bfloat16(v.y - __bfloat162float(h1));
    __nv_bfloat16 l2 = __float2bfloat16(v.z - __bfloat162float(h2));
    __nv_bfloat16 l3 = __float2bfloat16(v.w - __bfloat162float(h3));
    ((__nv_bfloat162*)h)[2*i]   = __halves2bfloat162(h0, h1);
    ((__nv_bfloat162*)h)[2*i+1] = __halves2bfloat162(h2, h3);
    ((__nv_bfloat162*)l)[2*i]   = __halves2bfloat162(l0, l1);
    ((__nv_bfloat162*)l)[2*i+1] = __halves2bfloat162(l2, l3);
}

// ---------------- split-bf16 tensor-core GEMM ----------------
// C[m][n] = sum_k A[m][k]*W[n][k] + bias[n],  A:[M,1024], W:[1024,1024]
// A = Ah + Al, W = Wh + Wl (bf16). 3-term product via mma.sync m16n8k16.
#define BM 128
#define BN 64
#define BK 32
#define SAST 40                     // padded row stride (bf16 elems), 80B
#define STAGES 3
#define A_PER_HL (BM * SAST)        // 5120
#define A_PER_ST (2 * A_PER_HL)     // 10240
#define W_PER_HL (BN * SAST)        // 2560
#define W_PER_ST (2 * W_PER_HL)     // 5120
#define W_BASE   (STAGES * A_PER_ST)        // 30720
#define SMEM_ELEMS (W_BASE + STAGES * W_PER_ST)  // 46080 bf16 = 92160 B

#define MMA_OP(d, a, b) asm volatile( \
    "mma.sync.aligned.m16n8k16.row.col.f32.bf16.bf16.f32 " \
    "{%0,%1,%2,%3},{%4,%5,%6,%7},{%8,%9},{%0,%1,%2,%3};" \
    : "+f"(d[0]), "+f"(d[1]), "+f"(d[2]), "+f"(d[3]) \
    : "r"(a[0]), "r"(a[1]), "r"(a[2]), "r"(a[3]), "r"(b[0]), "r"(b[1]))

#define LDSM4(r, addr) asm volatile( \
    "ldmatrix.sync.aligned.m8n8.x4.shared.b16 {%0,%1,%2,%3}, [%4];" \
    : "=r"(r[0]), "=r"(r[1]), "=r"(r[2]), "=r"(r[3]) : "r"(addr))

__device__ __forceinline__ void cp16(uint32_t dst, const void* src, bool pred) {
    int sz = pred ? 16 : 0;
    asm volatile("cp.async.cg.shared.global [%0], [%1], 16, %2;\n"
                 :: "r"(dst), "l"(src), "r"(sz));
}

__global__ __launch_bounds__(256, 2) void gemm_bf16_split(
    const __nv_bfloat16* __restrict__ Ah, const __nv_bfloat16* __restrict__ Al,
    const __nv_bfloat16* __restrict__ Wh, const __nv_bfloat16* __restrict__ Wl,
    const float* __restrict__ bias, float* __restrict__ C, int M)
{
    extern __shared__ __align__(16) __nv_bfloat16 smem[];
    const uint32_t sbase = (uint32_t)__cvta_generic_to_shared(smem);

    const int tid  = threadIdx.x;
    const int lane = tid & 31;
    const int wid  = tid >> 5;
    const int wm   = wid & 3;   // 4 warps over M (32 rows each)
    const int wn   = wid >> 2;  // 2 warps over N (32 cols each)
    const int bm   = blockIdx.y * BM;
    const int bn   = blockIdx.x * BN;

    // ldmatrix lane offsets
    const int a_r = (lane & 7) + ((lane >> 3) & 1) * 8;
    const int a_c = ((lane >> 4) & 1) * 8;
    const int g   = lane >> 3;
    const int b_r = (lane & 7) + (g >> 1) * 8;
    const int b_c = (g & 1) * 8;

    uint32_t aoff[2], boff[2];
#pragma unroll
    for (int i = 0; i < 2; i++)
        aoff[i] = (uint32_t)(((wm * 32 + i * 16 + a_r) * SAST + a_c) * 2);
#pragma unroll
    for (int j = 0; j < 2; j++)
        boff[j] = (uint32_t)((W_BASE + (wn * 32 + j * 16 + b_r) * SAST + b_c) * 2);

    float c[2][4][4];
#pragma unroll
    for (int i = 0; i < 2; i++)
#pragma unroll
        for (int j = 0; j < 4; j++)
#pragma unroll
            for (int r = 0; r < 4; r++) c[i][j][r] = 0.f;

    // stage loader: 1024 A-chunks + 512 W-chunks of 16B
    auto load_stage = [&](int s, int kt) {
        int k0 = kt * BK;
#pragma unroll
        for (int i = 0; i < 4; i++) {
            int idx = tid + 256 * i;
            int hl = idx >> 9, rem = idx & 511;
            int row = rem >> 2, seg = rem & 3;
            const __nv_bfloat16* src =
                (hl ? Al : Ah) + (size_t)(bm + row) * ED + k0 + seg * 8;
            uint32_t dst = sbase +
                (uint32_t)((s * A_PER_ST + hl * A_PER_HL + row * SAST + seg * 8) * 2);
            cp16(dst, src, (bm + row) < M);
        }
#pragma unroll
        for (int i = 0; i < 2; i++) {
            int idx = tid + 256 * i;
            int hl = idx >> 8, rem = idx & 255;
            int row = rem >> 2, seg = rem & 3;
            const __nv_bfloat16* src =
                (hl ? Wl : Wh) + (size_t)(bn + row) * ED + k0 + seg * 8;
            uint32_t dst = sbase +
                (uint32_t)((W_BASE + s * W_PER_ST + hl * W_PER_HL + row * SAST + seg * 8) * 2);
            cp16(dst, src, true);
        }
    };

    const int NK = ED / BK;  // 32
    load_stage(0, 0);
    asm volatile("cp.async.commit_group;");
    load_stage(1, 1);
    asm volatile("cp.async.commit_group;");

    for (int ks = 0; ks < NK; ks++) {
        asm volatile("cp.async.wait_group 1;");
        __syncthreads();
        if (ks + 2 < NK) load_stage((ks + 2) % STAGES, ks + 2);
        asm volatile("cp.async.commit_group;");

        const int s = ks % STAGES;
        const uint32_t sa = sbase + (uint32_t)(s * A_PER_ST * 2);
        const uint32_t sw = sbase + (uint32_t)(s * W_PER_ST * 2);
#pragma unroll
        for (int h = 0; h < 2; h++) {
            uint32_t ah[2][4], al[2][4], bh[2][4], bl[2][4];
#pragma unroll
            for (int i = 0; i < 2; i++) {
                LDSM4(ah[i], sa + aoff[i] + h * 32);
                LDSM4(al[i], sa + (uint32_t)(A_PER_HL * 2) + aoff[i] + h * 32);
            }
#pragma unroll
            for (int j = 0; j < 2; j++) {
                LDSM4(bh[j], sw + boff[j] + h * 32);
                LDSM4(bl[j], sw + (uint32_t)(W_PER_HL * 2) + boff[j] + h * 32);
            }
#pragma unroll
            for (int i = 0; i < 2; i++) {
#pragma unroll
                for (int j = 0; j < 2; j++) {
                    MMA_OP(c[i][j*2],   ah[i], (bh[j] + 0));
                    MMA_OP(c[i][j*2+1], ah[i], (bh[j] + 2));
                    MMA_OP(c[i][j*2],   ah[i], (bl[j] + 0));
                    MMA_OP(c[i][j*2+1], ah[i], (bl[j] + 2));
                    MMA_OP(c[i][j*2],   al[i], (bh[j] + 0));
                    MMA_OP(c[i][j*2+1], al[i], (bh[j] + 2));
                }
            }
        }
    }

    // epilogue
#pragma unroll
    for (int i = 0; i < 2; i++) {
        int m0 = bm + wm * 32 + i * 16 + (lane >> 2);
#pragma unroll
        for (int jn = 0; jn < 4; jn++) {
            int n0 = bn + wn * 32 + jn * 8 + (lane & 3) * 2;
            float bx = bias[n0], by = bias[n0 + 1];
            if (m0 < M) {
                float2 v = make_float2(c[i][jn][0] + bx, c[i][jn][1] + by);
                *(float2*)&C[(size_t)m0 * ED + n0] = v;
            }
            if (m0 + 8 < M) {
                float2 v = make_float2(c[i][jn][2] + bx, c[i][jn][3] + by);
                *(float2*)&C[(size_t)(m0 + 8) * ED + n0] = v;
            }
        }
    }
}

// ---------------- 2D RoPE ----------------
__global__ void rope_kernel(float* __restrict__ q, float* __restrict__ k)
{
    int t = blockIdx.x * blockDim.x + threadIdx.x;
    const int total = BATCH * 576 * NH * 32;
    if (t >= total) return;

    int d = t & 31;
    int h = (t >> 5) & 15;
    int p = (t >> 9) % 576;
    int b = t / (576 << 9);
    int gh = p / 24, gw = p % 24;

    float invf = exp2f(-(float)(d & 15) * (13.287712379549449f / 16.f));
    float a1 = (float)gh * invf;
    float a2 = (float)gw * invf;
    float s1, c1, s2, c2;
    sincosf(a1, &s1, &c1);
    sincosf(a2, &s2, &c2);

    size_t base = ((size_t)(b * SEQ + (p + 1)) * ED) + (size_t)h * HD;

    float x1 = q[base + d], x2 = q[base + d + 32];
    q[base + d]      = x1 * c1 - x2 * s1;
    q[base + d + 32] = x2 * c2 + x1 * s2;

    x1 = k[base + d]; x2 = k[base + d + 32];
    k[base + d]      = x1 * c1 - x2 * s1;
    k[base + d + 32] = x2 * c2 + x1 * s2;
}

// ---------------- flash attention, fp32, 2 threads per query ----------------
__global__ __launch_bounds__(128) void attn_kernel(
    const float* __restrict__ q, const float* __restrict__ k,
    const float* __restrict__ v, float* __restrict__ o)
{
    __shared__ float Ks[64][64];
    __shared__ float Vs[64][64];

    int tid = threadIdx.x;
    int q_loc = tid >> 1, half = tid & 1;
    int b = blockIdx.z, h = blockIdx.y;
    int qi = blockIdx.x * 64 + q_loc;
    bool active = qi < SEQ;
    int qic = active ? qi : SEQ - 1;

    const float* qrow = q + ((size_t)(b * SEQ + qic) * ED) + (size_t)h * HD + half * 32;
    float qreg[32], oacc[32];
#pragma unroll
    for (int d = 0; d < 32; d++) { qreg[d] = qrow[d] * 0.125f; oacc[d] = 0.f; }

    float mval = -1e30f, lval = 0.f;
    const float* kb = k + (size_t)b * SEQ * ED + (size_t)h * HD;
    const float* vb = v + (size_t)b * SEQ * ED + (size_t)h * HD;
    const float4 z4 = make_float4(0.f, 0.f, 0.f, 0.f);

    for (int t0 = 0; t0 < SEQ; t0 += 64) {
        __syncthreads();
#pragma unroll
        for (int i = 0; i < 8; i++) {
            int f = tid + 128 * i;
            int row = f >> 4, c4 = f & 15;
            bool ok = (t0 + row) < SEQ;
            ((float4*)Ks[row])[c4] = ok ? ((const float4*)(kb + (size_t)(t0 + row) * ED))[c4] : z4;
            ((float4*)Vs[row])[c4] = ok ? ((const float4*)(vb + (size_t)(t0 + row) * ED))[c4] : z4;
        }
        __syncthreads();

        float sc[64];
        float mnew = mval;
#pragma unroll
        for (int j = 0; j < 64; j++) {
            const float4* kr = (const float4*)&Ks[j][half * 32];
            float a = 0.f;
#pragma unroll
            for (int d4 = 0; d4 < 8; d4++) {
                float4 kv = kr[d4];
                a += qreg[4*d4+0]*kv.x + qreg[4*d4+1]*kv.y
                   + qreg[4*d4+2]*kv.z + qreg[4*d4+3]*kv.w;
            }
            a += __shfl_xor_sync(0xffffffff, a, 1);
            sc[j] = (t0 + j < SEQ) ? a : -1e30f;
            mnew = fmaxf(mnew, sc[j]);
        }

        float alpha = __expf(mval - mnew);
        mval = mnew;
        lval *= alpha;
#pragma unroll
        for (int d = 0; d < 32; d++) oacc[d] *= alpha;

#pragma unroll
        for (int j = 0; j < 64; j++) {
            float pw = __expf(sc[j] - mnew);
            lval += pw;
            const float4* vr = (const float4*)&Vs[j][half * 32];
#pragma unroll
            for (int d4 = 0; d4 < 8; d4++) {
                float4 vv = vr[d4];
                oacc[4*d4+0] += pw * vv.x;
                oacc[4*d4+1] += pw * vv.y;
                oacc[4*d4+2] += pw * vv.z;
                oacc[4*d4+3] += pw * vv.w;
            }
        }
    }

    if (active) {
        float inv = 1.f / lval;
        float* orow = o + ((size_t)(b * SEQ + qi) * ED) + (size_t)h * HD + half * 32;
#pragma unroll
        for (int d = 0; d < 32; d++) orow[d] = oacc[d] * inv;
    }
}

// ---------------- launch ----------------
extern "C" void kernel_launch(void* const* d_in, const int* in_sizes, int n_in,
                              void* d_out, int out_size)
{
    const float* hs = (const float*)d_in[0];
    const float* Wq = (const float*)d_in[1];
    const float* bq = (const float*)d_in[2];
    const float* Wk = (const float*)d_in[3];
    const float* bk = (const float*)d_in[4];
    const float* Wv = (const float*)d_in[5];
    const float* bv = (const float*)d_in[6];
    const float* Wo = (const float*)d_in[7];
    const float* bo = (const float*)d_in[8];
    float* out = (float*)d_out;

    float *qb, *kb, *vb, *ob;
    cudaGetSymbolAddress((void**)&qb, g_q);
    cudaGetSymbolAddress((void**)&kb, g_k);
    cudaGetSymbolAddress((void**)&vb, g_v);
    cudaGetSymbolAddress((void**)&ob, g_o);
    __nv_bfloat16 *hsh, *hsl, *oh, *ol, *wh, *wl;
    cudaGetSymbolAddress((void**)&hsh, g_hsh);
    cudaGetSymbolAddress((void**)&hsl, g_hsl);
    cudaGetSymbolAddress((void**)&oh, g_oh);
    cudaGetSymbolAddress((void**)&ol, g_ol);
    cudaGetSymbolAddress((void**)&wh, g_wh);
    cudaGetSymbolAddress((void**)&wl, g_wl);

    cudaFuncSetAttribute(gemm_bf16_split,
                         cudaFuncAttributeMaxDynamicSharedMemorySize,
                         SMEM_ELEMS * 2);

    const size_t WSZ = (size_t)ED * ED;
    const int n4_hs = MROWS * ED / 4;
    const int n4_w  = ED * ED / 4;

    // conversions
    cvt_split_kernel<<<(n4_hs + 255) / 256, 256>>>(hs, hsh, hsl, n4_hs);
    cvt_split_kernel<<<(n4_w + 255) / 256, 256>>>(Wq, wh + 0*WSZ, wl + 0*WSZ, n4_w);
    cvt_split_kernel<<<(n4_w + 255) / 256, 256>>>(Wk, wh + 1*WSZ, wl + 1*WSZ, n4_w);
    cvt_split_kernel<<<(n4_w + 255) / 256, 256>>>(Wv, wh + 2*WSZ, wl + 2*WSZ, n4_w);
    cvt_split_kernel<<<(n4_w + 255) / 256, 256>>>(Wo, wh + 3*WSZ, wl + 3*WSZ, n4_w);

    dim3 ggrid(ED / BN, (MROWS + BM - 1) / BM);  // (16, 73)
    size_t gsmem = SMEM_ELEMS * 2;

    gemm_bf16_split<<<ggrid, 256, gsmem>>>(hsh, hsl, wh + 0*WSZ, wl + 0*WSZ, bq, qb, MROWS);
    gemm_bf16_split<<<ggrid, 256, gsmem>>>(hsh, hsl, wh + 1*WSZ, wl + 1*WSZ, bk, kb, MROWS);
    gemm_bf16_split<<<ggrid, 256, gsmem>>>(hsh, hsl, wh + 2*WSZ, wl + 2*WSZ, bv, vb, MROWS);

    int rt = BATCH * 576 * NH * 32;
    rope_kernel<<<(rt + 255) / 256, 256>>>(qb, kb);

    attn_kernel<<<dim3((SEQ + 63) / 64, NH, BATCH), 128>>>(qb, kb, vb, ob);

    cvt_split_kernel<<<(n4_hs + 255) / 256, 256>>>(ob, oh, ol, n4_hs);
    gemm_bf16_split<<<ggrid, 256, gsmem>>>(oh, ol, wh + 3*WSZ, wl + 3*WSZ, bo, out, MROWS);
}

// round 4
// speedup vs baseline: 4.5241x; 2.5084x over previous
#include <cuda_runtime.h>
#include <cuda_bf16.h>
#include <cstdint>
#include <math.h>

#define ED   1024
#define NH   16
#define HD   64
#define SEQ  577
#define BATCH 16
#define MROWS (BATCH * SEQ)   // 9232
#define NT   10               // key tiles of 64
#define QT   10               // query tiles of 64

// ---------------- scratch ----------------
__device__ float g_q[(size_t)MROWS * ED];
__device__ float g_k[(size_t)MROWS * ED];
__device__ float g_v[(size_t)MROWS * ED];

__device__ __nv_bfloat16 g_hsh[(size_t)MROWS * ED];
__device__ __nv_bfloat16 g_hsl[(size_t)MROWS * ED];
__device__ __nv_bfloat16 g_oh[(size_t)MROWS * ED];
__device__ __nv_bfloat16 g_ol[(size_t)MROWS * ED];
__device__ __nv_bfloat16 g_wh[4][(size_t)ED * ED];
__device__ __nv_bfloat16 g_wl[4][(size_t)ED * ED];
__device__ __nv_bfloat16 g_qh[(size_t)MROWS * ED];
__device__ __nv_bfloat16 g_ql[(size_t)MROWS * ED];
__device__ __nv_bfloat16 g_kh[(size_t)MROWS * ED];
__device__ __nv_bfloat16 g_kl[(size_t)MROWS * ED];
__device__ __nv_bfloat16 g_vh[(size_t)MROWS * ED];
__device__ __nv_bfloat16 g_vl[(size_t)MROWS * ED];

// ---------------- helpers ----------------
__device__ __forceinline__ float ex2f(float x) {
    float r;
    asm("ex2.approx.ftz.f32 %0, %1;" : "=f"(r) : "f"(x));
    return r;
}
__device__ __forceinline__ uint32_t packbf2(__nv_bfloat16 a, __nv_bfloat16 b) {
    __nv_bfloat162 v = __halves2bfloat162(a, b);
    return *(uint32_t*)&v;
}
__device__ __forceinline__ void split2(float a, float b, uint32_t& hi, uint32_t& lo) {
    __nv_bfloat16 ha = __float2bfloat16(a), hb = __float2bfloat16(b);
    __nv_bfloat16 la = __float2bfloat16(a - __bfloat162float(ha));
    __nv_bfloat16 lb = __float2bfloat16(b - __bfloat162float(hb));
    hi = packbf2(ha, hb);
    lo = packbf2(la, lb);
}

// ---------------- fp32 -> bf16 hi/lo split ----------------
__global__ void cvt_split_kernel(const float* __restrict__ x,
                                 __nv_bfloat16* __restrict__ h,
                                 __nv_bfloat16* __restrict__ l, int n4)
{
    int i = blockIdx.x * blockDim.x + threadIdx.x;
    if (i >= n4) return;
    float4 v = ((const float4*)x)[i];
    uint32_t h01, l01, h23, l23;
    split2(v.x, v.y, h01, l01);
    split2(v.z, v.w, h23, l23);
    ((uint32_t*)h)[2*i]   = h01;
    ((uint32_t*)h)[2*i+1] = h23;
    ((uint32_t*)l)[2*i]   = l01;
    ((uint32_t*)l)[2*i+1] = l23;
}

// ---------------- MMA / ldmatrix / cp.async primitives ----------------
#define MMA_OP(d, a, b) asm volatile( \
    "mma.sync.aligned.m16n8k16.row.col.f32.bf16.bf16.f32 " \
    "{%0,%1,%2,%3},{%4,%5,%6,%7},{%8,%9},{%0,%1,%2,%3};" \
    : "+f"(d[0]), "+f"(d[1]), "+f"(d[2]), "+f"(d[3]) \
    : "r"(a[0]), "r"(a[1]), "r"(a[2]), "r"(a[3]), "r"(b[0]), "r"(b[1]))

#define LDSM4(r, addr) asm volatile( \
    "ldmatrix.sync.aligned.m8n8.x4.shared.b16 {%0,%1,%2,%3}, [%4];" \
    : "=r"(r[0]), "=r"(r[1]), "=r"(r[2]), "=r"(r[3]) : "r"(addr))

#define LDSM4T(r, addr) asm volatile( \
    "ldmatrix.sync.aligned.m8n8.x4.trans.shared.b16 {%0,%1,%2,%3}, [%4];" \
    : "=r"(r[0]), "=r"(r[1]), "=r"(r[2]), "=r"(r[3]) : "r"(addr))

__device__ __forceinline__ void cp16(uint32_t dst, const void* src, bool pred) {
    int sz = pred ? 16 : 0;
    asm volatile("cp.async.cg.shared.global [%0], [%1], 16, %2;\n"
                 :: "r"(dst), "l"(src), "r"(sz));
}

// ---------------- split-bf16 tensor-core GEMM (unchanged from R3) ----------------
#define BM 128
#define BN 64
#define BK 32
#define SAST 40
#define STAGES 3
#define A_PER_HL (BM * SAST)
#define A_PER_ST (2 * A_PER_HL)
#define W_PER_HL (BN * SAST)
#define W_PER_ST (2 * W_PER_HL)
#define W_BASE   (STAGES * A_PER_ST)
#define SMEM_ELEMS (W_BASE + STAGES * W_PER_ST)   // 46080 bf16 = 92160 B

__global__ __launch_bounds__(256, 2) void gemm_bf16_split(
    const __nv_bfloat16* __restrict__ Ah, const __nv_bfloat16* __restrict__ Al,
    const __nv_bfloat16* __restrict__ Wh, const __nv_bfloat16* __restrict__ Wl,
    const float* __restrict__ bias, float* __restrict__ C, int M)
{
    extern __shared__ __align__(16) __nv_bfloat16 smem[];
    const uint32_t sbase = (uint32_t)__cvta_generic_to_shared(smem);

    const int tid  = threadIdx.x;
    const int lane = tid & 31;
    const int wid  = tid >> 5;
    const int wm   = wid & 3;
    const int wn   = wid >> 2;
    const int bm   = blockIdx.y * BM;
    const int bn   = blockIdx.x * BN;

    const int a_r = (lane & 7) + ((lane >> 3) & 1) * 8;
    const int a_c = ((lane >> 4) & 1) * 8;
    const int g   = lane >> 3;
    const int b_r = (lane & 7) + (g >> 1) * 8;
    const int b_c = (g & 1) * 8;

    uint32_t aoff[2], boff[2];
#pragma unroll
    for (int i = 0; i < 2; i++)
        aoff[i] = (uint32_t)(((wm * 32 + i * 16 + a_r) * SAST + a_c) * 2);
#pragma unroll
    for (int j = 0; j < 2; j++)
        boff[j] = (uint32_t)((W_BASE + (wn * 32 + j * 16 + b_r) * SAST + b_c) * 2);

    float c[2][4][4];
#pragma unroll
    for (int i = 0; i < 2; i++)
#pragma unroll
        for (int j = 0; j < 4; j++)
#pragma unroll
            for (int r = 0; r < 4; r++) c[i][j][r] = 0.f;

    auto load_stage = [&](int s, int kt) {
        int k0 = kt * BK;
#pragma unroll
        for (int i = 0; i < 4; i++) {
            int idx = tid + 256 * i;
            int hl = idx >> 9, rem = idx & 511;
            int row = rem >> 2, seg = rem & 3;
            const __nv_bfloat16* src =
                (hl ? Al : Ah) + (size_t)(bm + row) * ED + k0 + seg * 8;
            uint32_t dst = sbase +
                (uint32_t)((s * A_PER_ST + hl * A_PER_HL + row * SAST + seg * 8) * 2);
            cp16(dst, src, (bm + row) < M);
        }
#pragma unroll
        for (int i = 0; i < 2; i++) {
            int idx = tid + 256 * i;
            int hl = idx >> 8, rem = idx & 255;
            int row = rem >> 2, seg = rem & 3;
            const __nv_bfloat16* src =
                (hl ? Wl : Wh) + (size_t)(bn + row) * ED + k0 + seg * 8;
            uint32_t dst = sbase +
                (uint32_t)((W_BASE + s * W_PER_ST + hl * W_PER_HL + row * SAST + seg * 8) * 2);
            cp16(dst, src, true);
        }
    };

    const int NK = ED / BK;
    load_stage(0, 0);
    asm volatile("cp.async.commit_group;");
    load_stage(1, 1);
    asm volatile("cp.async.commit_group;");

    for (int ks = 0; ks < NK; ks++) {
        asm volatile("cp.async.wait_group 1;");
        __syncthreads();
        if (ks + 2 < NK) load_stage((ks + 2) % STAGES, ks + 2);
        asm volatile("cp.async.commit_group;");

        const int s = ks % STAGES;
        const uint32_t sa = sbase + (uint32_t)(s * A_PER_ST * 2);
        const uint32_t sw = sbase + (uint32_t)(s * W_PER_ST * 2);
#pragma unroll
        for (int h = 0; h < 2; h++) {
            uint32_t ah[2][4], al[2][4], bh[2][4], bl[2][4];
#pragma unroll
            for (int i = 0; i < 2; i++) {
                LDSM4(ah[i], sa + aoff[i] + h * 32);
                LDSM4(al[i], sa + (uint32_t)(A_PER_HL * 2) + aoff[i] + h * 32);
            }
#pragma unroll
            for (int j = 0; j < 2; j++) {
                LDSM4(bh[j], sw + boff[j] + h * 32);
                LDSM4(bl[j], sw + (uint32_t)(W_PER_HL * 2) + boff[j] + h * 32);
            }
#pragma unroll
            for (int i = 0; i < 2; i++) {
#pragma unroll
                for (int j = 0; j < 2; j++) {
                    MMA_OP(c[i][j*2],   ah[i], (bh[j] + 0));
                    MMA_OP(c[i][j*2+1], ah[i], (bh[j] + 2));
                    MMA_OP(c[i][j*2],   ah[i], (bl[j] + 0));
                    MMA_OP(c[i][j*2+1], ah[i], (bl[j] + 2));
                    MMA_OP(c[i][j*2],   al[i], (bh[j] + 0));
                    MMA_OP(c[i][j*2+1], al[i], (bh[j] + 2));
                }
            }
        }
    }

#pragma unroll
    for (int i = 0; i < 2; i++) {
        int m0 = bm + wm * 32 + i * 16 + (lane >> 2);
#pragma unroll
        for (int jn = 0; jn < 4; jn++) {
            int n0 = bn + wn * 32 + jn * 8 + (lane & 3) * 2;
            float bx = bias[n0], by = bias[n0 + 1];
            if (m0 < M) {
                float2 v = make_float2(c[i][jn][0] + bx, c[i][jn][1] + by);
                *(float2*)&C[(size_t)m0 * ED + n0] = v;
            }
            if (m0 + 8 < M) {
                float2 v = make_float2(c[i][jn][2] + bx, c[i][jn][3] + by);
                *(float2*)&C[(size_t)(m0 + 8) * ED + n0] = v;
            }
        }
    }
}

// ---------------- 2D RoPE fused with hi/lo split ----------------
__global__ void rope_split_kernel(const float* __restrict__ q, const float* __restrict__ k,
                                  __nv_bfloat16* __restrict__ qh, __nv_bfloat16* __restrict__ ql,
                                  __nv_bfloat16* __restrict__ kh, __nv_bfloat16* __restrict__ kl)
{
    int t = blockIdx.x * blockDim.x + threadIdx.x;
    const int total = BATCH * SEQ * NH * 32;
    if (t >= total) return;

    int d = t & 31;
    int h = (t >> 5) & 15;
    int s = (t >> 9) % SEQ;
    int b = t / (SEQ << 9);

    size_t base = ((size_t)(b * SEQ + s) * ED) + (size_t)h * HD;

    float q1 = q[base + d], q2 = q[base + d + 32];
    float k1 = k[base + d], k2 = k[base + d + 32];

    if (s > 0) {
        int p = s - 1;
        int gh = p / 24, gw = p % 24;
        float invf = exp2f(-(float)(d & 15) * (13.287712379549449f / 16.f));
        float s1, c1, s2, c2;
        sincosf((float)gh * invf, &s1, &c1);
        sincosf((float)gw * invf, &s2, &c2);

        float nq1 = q1 * c1 - q2 * s1;
        float nq2 = q2 * c2 + q1 * s2;
        float nk1 = k1 * c1 - k2 * s1;
        float nk2 = k2 * c2 + k1 * s2;
        q1 = nq1; q2 = nq2; k1 = nk1; k2 = nk2;
    }

    __nv_bfloat16 hq1 = __float2bfloat16(q1), hq2 = __float2bfloat16(q2);
    __nv_bfloat16 hk1 = __float2bfloat16(k1), hk2 = __float2bfloat16(k2);
    qh[base + d]      = hq1;
    qh[base + d + 32] = hq2;
    ql[base + d]      = __float2bfloat16(q1 - __bfloat162float(hq1));
    ql[base + d + 32] = __float2bfloat16(q2 - __bfloat162float(hq2));
    kh[base + d]      = hk1;
    kh[base + d + 32] = hk2;
    kl[base + d]      = __float2bfloat16(k1 - __bfloat162float(hk1));
    kl[base + d + 32] = __float2bfloat16(k2 - __bfloat162float(hk2));
}

// ---------------- tensor-core flash attention ----------------
#define TSTR 72                   // smem row stride in bf16 elems (144 B)
#define MATB (64 * TSTR * 2)      // 9216 B per 64x64 matrix
#define STGB (4 * MATB)           // 36864 B per stage (Kh,Kl,Vh,Vl)
#define ATT_SMEM (2 * STGB)       // 73728 B

__global__ __launch_bounds__(128) void attn_mma(
    const __nv_bfloat16* __restrict__ qh, const __nv_bfloat16* __restrict__ ql,
    const __nv_bfloat16* __restrict__ kh, const __nv_bfloat16* __restrict__ kl,
    const __nv_bfloat16* __restrict__ vh, const __nv_bfloat16* __restrict__ vl,
    __nv_bfloat16* __restrict__ oh, __nv_bfloat16* __restrict__ ol)
{
    extern __shared__ __align__(16) __nv_bfloat16 asmem[];
    const uint32_t sbase = (uint32_t)__cvta_generic_to_shared(asmem);

    const int tid  = threadIdx.x;
    const int lane = tid & 31;
    const int w    = tid >> 5;
    const int b    = blockIdx.z;
    const int h    = blockIdx.y;
    const int qt   = blockIdx.x;
    const size_t hoff = (size_t)h * HD;
    const size_t bbase = (size_t)b * SEQ;

    const int a_r = (lane & 7) + ((lane >> 3) & 1) * 8;
    const int a_c = ((lane >> 4) & 1) * 8;
    const int g   = lane >> 3;
    const int b_r = (lane & 7) + (g >> 1) * 8;
    const int b_c = (g & 1) * 8;

    // ---- Q tile into smem (stage0 area), ldmatrix to regs ----
    for (int c = tid; c < 1024; c += 128) {
        int mat = c >> 9, row = (c >> 3) & 63, seg = c & 7;
        int qrow = qt * 64 + row;
        if (qrow >= SEQ) qrow = SEQ - 1;
        const __nv_bfloat16* src = (mat ? ql : qh) + (bbase + qrow) * ED + hoff + seg * 8;
        cp16(sbase + mat * MATB + row * 144 + seg * 16, src, true);
    }
    asm volatile("cp.async.commit_group;");
    asm volatile("cp.async.wait_group 0;");
    __syncthreads();

    uint32_t qhf[4][4], qlf[4][4];
#pragma unroll
    for (int kc = 0; kc < 4; kc++) {
        uint32_t base0 = sbase + (uint32_t)((w * 16 + a_r) * 144 + (kc * 16 + a_c) * 2);
        LDSM4(qhf[kc], base0);
        LDSM4(qlf[kc], base0 + MATB);
    }
    __syncthreads();

    // ---- K/V pipeline ----
    auto load_kv = [&](int s, int t) {
        const __nv_bfloat16* mats[4] = {kh, kl, vh, vl};
        for (int c = tid; c < 2048; c += 128) {
            int mat = c >> 9, row = (c >> 3) & 63, seg = c & 7;
            int kr = t * 64 + row;
            int krc = (kr < SEQ) ? kr : 0;
            const __nv_bfloat16* src = mats[mat] + (bbase + krc) * ED + hoff + seg * 8;
            cp16(sbase + s * STGB + mat * MATB + row * 144 + seg * 16, src, kr < SEQ);
        }
    };
    load_kv(0, 0);
    asm volatile("cp.async.commit_group;");
    load_kv(1, 1);
    asm volatile("cp.async.commit_group;");

    float off_[8][4];
#pragma unroll
    for (int ng = 0; ng < 8; ng++)
#pragma unroll
        for (int r = 0; r < 4; r++) off_[ng][r] = 0.f;
    float m_lo = -1e30f, m_hi = -1e30f, l_lo = 0.f, l_hi = 0.f;

    const float SCL = 0.18033688011112042f;  // 0.125 * log2(e)

    for (int t = 0; t < NT; t++) {
        if (t < NT - 1) { asm volatile("cp.async.wait_group 1;"); }
        else            { asm volatile("cp.async.wait_group 0;"); }
        __syncthreads();
        const uint32_t sb = sbase + (uint32_t)((t & 1) * STGB);

        // ---- scores S = Q K^T (3-term split) ----
        float sfr[8][4];
#pragma unroll
        for (int ng = 0; ng < 8; ng++)
#pragma unroll
            for (int r = 0; r < 4; r++) sfr[ng][r] = 0.f;

#pragma unroll
        for (int kc = 0; kc < 4; kc++) {
            uint32_t kf[4][4], lf[4][4];
#pragma unroll
            for (int pp = 0; pp < 4; pp++) {
                uint32_t ad = sb + (uint32_t)((pp * 16 + b_r) * 144 + (kc * 16 + b_c) * 2);
                LDSM4(kf[pp], ad);
                LDSM4(lf[pp], ad + MATB);
            }
#pragma unroll
            for (int ng = 0; ng < 8; ng++) {
                int pp = ng >> 1, sel = (ng & 1) * 2;
                MMA_OP(sfr[ng], qhf[kc], (kf[pp] + sel));
                MMA_OP(sfr[ng], qhf[kc], (lf[pp] + sel));
                MMA_OP(sfr[ng], qlf[kc], (kf[pp] + sel));
            }
        }

        // ---- mask tail keys ----
        if (t * 64 + 64 > SEQ) {
            int tig2 = 2 * (lane & 3);
#pragma unroll
            for (int ng = 0; ng < 8; ng++) {
                int key0 = t * 64 + ng * 8 + tig2;
                if (key0     >= SEQ) { sfr[ng][0] = -1e30f; sfr[ng][2] = -1e30f; }
                if (key0 + 1 >= SEQ) { sfr[ng][1] = -1e30f; sfr[ng][3] = -1e30f; }
            }
        }

        // ---- online softmax ----
        float mx0 = -1e30f, mx1 = -1e30f;
#pragma unroll
        for (int ng = 0; ng < 8; ng++) {
            mx0 = fmaxf(mx0, fmaxf(sfr[ng][0], sfr[ng][1]));
            mx1 = fmaxf(mx1, fmaxf(sfr[ng][2], sfr[ng][3]));
        }
        mx0 = fmaxf(mx0, __shfl_xor_sync(0xffffffff, mx0, 1));
        mx0 = fmaxf(mx0, __shfl_xor_sync(0xffffffff, mx0, 2));
        mx1 = fmaxf(mx1, __shfl_xor_sync(0xffffffff, mx1, 1));
        mx1 = fmaxf(mx1, __shfl_xor_sync(0xffffffff, mx1, 2));
        float mn0 = fmaxf(m_lo, mx0), mn1 = fmaxf(m_hi, mx1);
        float al0 = ex2f((m_lo - mn0) * SCL), al1 = ex2f((m_hi - mn1) * SCL);
        m_lo = mn0; m_hi = mn1;

        float s0 = 0.f, s1 = 0.f;
#pragma unroll
        for (int ng = 0; ng < 8; ng++) {
            sfr[ng][0] = ex2f((sfr[ng][0] - mn0) * SCL);
            sfr[ng][1] = ex2f((sfr[ng][1] - mn0) * SCL);
            sfr[ng][2] = ex2f((sfr[ng][2] - mn1) * SCL);
            sfr[ng][3] = ex2f((sfr[ng][3] - mn1) * SCL);
            s0 += sfr[ng][0] + sfr[ng][1];
            s1 += sfr[ng][2] + sfr[ng][3];
        }
        s0 += __shfl_xor_sync(0xffffffff, s0, 1);
        s0 += __shfl_xor_sync(0xffffffff, s0, 2);
        s1 += __shfl_xor_sync(0xffffffff, s1, 1);
        s1 += __shfl_xor_sync(0xffffffff, s1, 2);
        l_lo = l_lo * al0 + s0;
        l_hi = l_hi * al1 + s1;

#pragma unroll
        for (int ng = 0; ng < 8; ng++) {
            off_[ng][0] *= al0; off_[ng][1] *= al0;
            off_[ng][2] *= al1; off_[ng][3] *= al1;
        }

        // ---- pack P into A-fragments (hi/lo) ----
        uint32_t ph[4][4], pl[4][4];
#pragma unroll
        for (int kc = 0; kc < 4; kc++) {
            split2(sfr[2*kc][0],   sfr[2*kc][1],   ph[kc][0], pl[kc][0]);
            split2(sfr[2*kc][2],   sfr[2*kc][3],   ph[kc][1], pl[kc][1]);
            split2(sfr[2*kc+1][0], sfr[2*kc+1][1], ph[kc][2], pl[kc][2]);
            split2(sfr[2*kc+1][2], sfr[2*kc+1][3], ph[kc][3], pl[kc][3]);
        }

        // ---- O += P V (3-term split), V via ldmatrix.trans ----
#pragma unroll
        for (int kc = 0; kc < 4; kc++) {
            uint32_t vf[4][4], wf[4][4];
#pragma unroll
            for (int dp = 0; dp < 4; dp++) {
                uint32_t ad = sb + (uint32_t)(2 * MATB +
                               (kc * 16 + a_r) * 144 + (dp * 16 + a_c) * 2);
                LDSM4T(vf[dp], ad);
                LDSM4T(wf[dp], ad + MATB);
            }
#pragma unroll
            for (int ng = 0; ng < 8; ng++) {
                int dp = ng >> 1, sel = (ng & 1) * 2;
                MMA_OP(off_[ng], ph[kc], (vf[dp] + sel));
                MMA_OP(off_[ng], pl[kc], (vf[dp] + sel));
                MMA_OP(off_[ng], ph[kc], (wf[dp] + sel));
            }
        }

        __syncthreads();
        if (t + 2 < NT) {
            load_kv(t & 1, t + 2);
            asm volatile("cp.async.commit_group;");
        }
    }

    // ---- epilogue: write oh/ol (split) ----
    float inv0 = 1.f / l_lo, inv1 = 1.f / l_hi;
    int q0 = qt * 64 + w * 16 + (lane >> 2);
    int col = 2 * (lane & 3);
#pragma unroll
    for (int ng = 0; ng < 8; ng++) {
        int n0 = ng * 8 + col;
        if (q0 < SEQ) {
            uint32_t hi, lo;
            split2(off_[ng][0] * inv0, off_[ng][1] * inv0, hi, lo);
            *(uint32_t*)(oh + (bbase + q0) * ED + hoff + n0) = hi;
            *(uint32_t*)(ol + (bbase + q0) * ED + hoff + n0) = lo;
        }
        if (q0 + 8 < SEQ) {
            uint32_t hi, lo;
            split2(off_[ng][2] * inv1, off_[ng][3] * inv1, hi, lo);
            *(uint32_t*)(oh + (bbase + q0 + 8) * ED + hoff + n0) = hi;
            *(uint32_t*)(ol + (bbase + q0 + 8) * ED + hoff + n0) = lo;
        }
    }
}

// ---------------- launch ----------------
extern "C" void kernel_launch(void* const* d_in, const int* in_sizes, int n_in,
                              void* d_out, int out_size)
{
    const float* hs = (const float*)d_in[0];
    const float* Wq = (const float*)d_in[1];
    const float* bq = (const float*)d_in[2];
    const float* Wk = (const float*)d_in[3];
    const float* bk = (const float*)d_in[4];
    const float* Wv = (const float*)d_in[5];
    const float* bv = (const float*)d_in[6];
    const float* Wo = (const float*)d_in[7];
    const float* bo = (const float*)d_in[8];
    float* out = (float*)d_out;

    float *qb, *kb, *vb;
    cudaGetSymbolAddress((void**)&qb, g_q);
    cudaGetSymbolAddress((void**)&kb, g_k);
    cudaGetSymbolAddress((void**)&vb, g_v);
    __nv_bfloat16 *hsh, *hsl, *oh, *ol, *wh, *wl;
    __nv_bfloat16 *qhp, *qlp, *khp, *klp, *vhp, *vlp;
    cudaGetSymbolAddress((void**)&hsh, g_hsh);
    cudaGetSymbolAddress((void**)&hsl, g_hsl);
    cudaGetSymbolAddress((void**)&oh, g_oh);
    cudaGetSymbolAddress((void**)&ol, g_ol);
    cudaGetSymbolAddress((void**)&wh, g_wh);
    cudaGetSymbolAddress((void**)&wl, g_wl);
    cudaGetSymbolAddress((void**)&qhp, g_qh);
    cudaGetSymbolAddress((void**)&qlp, g_ql);
    cudaGetSymbolAddress((void**)&khp, g_kh);
    cudaGetSymbolAddress((void**)&klp, g_kl);
    cudaGetSymbolAddress((void**)&vhp, g_vh);
    cudaGetSymbolAddress((void**)&vlp, g_vl);

    cudaFuncSetAttribute(gemm_bf16_split,
                         cudaFuncAttributeMaxDynamicSharedMemorySize, SMEM_ELEMS * 2);
    cudaFuncSetAttribute(attn_mma,
                         cudaFuncAttributeMaxDynamicSharedMemorySize, ATT_SMEM);

    const size_t WSZ = (size_t)ED * ED;
    const int n4_hs = MROWS * ED / 4;
    const int n4_w  = ED * ED / 4;

    cvt_split_kernel<<<(n4_hs + 255) / 256, 256>>>(hs, hsh, hsl, n4_hs);
    cvt_split_kernel<<<(n4_w + 255) / 256, 256>>>(Wq, wh + 0*WSZ, wl + 0*WSZ, n4_w);
    cvt_split_kernel<<<(n4_w + 255) / 256, 256>>>(Wk, wh + 1*WSZ, wl + 1*WSZ, n4_w);
    cvt_split_kernel<<<(n4_w + 255) / 256, 256>>>(Wv, wh + 2*WSZ, wl + 2*WSZ, n4_w);
    cvt_split_kernel<<<(n4_w + 255) / 256, 256>>>(Wo, wh + 3*WSZ, wl + 3*WSZ, n4_w);

    dim3 ggrid(ED / BN, (MROWS + BM - 1) / BM);
    size_t gsmem = SMEM_ELEMS * 2;

    gemm_bf16_split<<<ggrid, 256, gsmem>>>(hsh, hsl, wh + 0*WSZ, wl + 0*WSZ, bq, qb, MROWS);
    gemm_bf16_split<<<ggrid, 256, gsmem>>>(hsh, hsl, wh + 1*WSZ, wl + 1*WSZ, bk, kb, MROWS);
    gemm_bf16_split<<<ggrid, 256, gsmem>>>(hsh, hsl, wh + 2*WSZ, wl + 2*WSZ, bv, vb, MROWS);

    int rt = BATCH * SEQ * NH * 32;
    rope_split_kernel<<<(rt + 255) / 256, 256>>>(qb, kb, qhp, qlp, khp, klp);
    cvt_split_kernel<<<(n4_hs + 255) / 256, 256>>>(vb, vhp, vlp, n4_hs);

    attn_mma<<<dim3(QT, NH, BATCH), 128, ATT_SMEM>>>(qhp, qlp, khp, klp, vhp, vlp, oh, ol);

    gemm_bf16_split<<<ggrid, 256, gsmem>>>(oh, ol, wh + 3*WSZ, wl + 3*WSZ, bo, out, MROWS);
}

// round 6
// speedup vs baseline: 4.5989x; 1.0165x over previous
#include <cuda_runtime.h>
#include <cuda_bf16.h>
#include <cstdint>
#include <math.h>

#define ED   1024
#define NH   16
#define HD   64
#define SEQ  577
#define BATCH 16
#define MROWS (BATCH * SEQ)   // 9232
#define NT   10
#define QT   10

// ---------------- scratch ----------------
__device__ float g_q[(size_t)MROWS * ED];
__device__ float g_k[(size_t)MROWS * ED];

__device__ __nv_bfloat16 g_hsh[(size_t)MROWS * ED];
__device__ __nv_bfloat16 g_hsl[(size_t)MROWS * ED];
__device__ __nv_bfloat16 g_oh[(size_t)MROWS * ED];
__device__ __nv_bfloat16 g_ol[(size_t)MROWS * ED];
__device__ __nv_bfloat16 g_wh[4][(size_t)ED * ED];
__device__ __nv_bfloat16 g_wl[4][(size_t)ED * ED];
__device__ __nv_bfloat16 g_qh[(size_t)MROWS * ED];
__device__ __nv_bfloat16 g_ql[(size_t)MROWS * ED];
__device__ __nv_bfloat16 g_kh[(size_t)MROWS * ED];
__device__ __nv_bfloat16 g_kl[(size_t)MROWS * ED];
__device__ __nv_bfloat16 g_vh[(size_t)MROWS * ED];
__device__ __nv_bfloat16 g_vl[(size_t)MROWS * ED];

// ---------------- helpers ----------------
__device__ __forceinline__ float ex2f(float x) {
    float r;
    asm("ex2.approx.ftz.f32 %0, %1;" : "=f"(r) : "f"(x));
    return r;
}
__device__ __forceinline__ uint32_t packbf2(__nv_bfloat16 a, __nv_bfloat16 b) {
    __nv_bfloat162 v = __halves2bfloat162(a, b);
    return *(uint32_t*)&v;
}
__device__ __forceinline__ void split2(float a, float b, uint32_t& hi, uint32_t& lo) {
    __nv_bfloat16 ha = __float2bfloat16(a), hb = __float2bfloat16(b);
    __nv_bfloat16 la = __float2bfloat16(a - __bfloat162float(ha));
    __nv_bfloat16 lb = __float2bfloat16(b - __bfloat162float(hb));
    hi = packbf2(ha, hb);
    lo = packbf2(la, lb);
}

// ---------------- fp32 -> bf16 hi/lo split ----------------
__global__ void cvt_split_kernel(const float* __restrict__ x,
                                 __nv_bfloat16* __restrict__ h,
                                 __nv_bfloat16* __restrict__ l, int n4)
{
    int i = blockIdx.x * blockDim.x + threadIdx.x;
    if (i >= n4) return;
    float4 v = ((const float4*)x)[i];
    uint32_t h01, l01, h23, l23;
    split2(v.x, v.y, h01, l01);
    split2(v.z, v.w, h23, l23);
    ((uint32_t*)h)[2*i]   = h01;
    ((uint32_t*)h)[2*i+1] = h23;
    ((uint32_t*)l)[2*i]   = l01;
    ((uint32_t*)l)[2*i+1] = l23;
}

// all 4 weight matrices in one launch
__global__ void cvt_split4_kernel(const float* __restrict__ w0, const float* __restrict__ w1,
                                  const float* __restrict__ w2, const float* __restrict__ w3,
                                  __nv_bfloat16* __restrict__ wh, __nv_bfloat16* __restrict__ wl,
                                  int n4_per)
{
    int i = blockIdx.x * blockDim.x + threadIdx.x;
    if (i >= 4 * n4_per) return;
    int sel = i / n4_per;
    int rem = i - sel * n4_per;
    const float* src = (sel == 0) ? w0 : (sel == 1) ? w1 : (sel == 2) ? w2 : w3;
    size_t base = (size_t)sel * (size_t)ED * ED;
    float4 v = ((const float4*)src)[rem];
    uint32_t h01, l01, h23, l23;
    split2(v.x, v.y, h01, l01);
    split2(v.z, v.w, h23, l23);
    ((uint32_t*)(wh + base))[2*rem]   = h01;
    ((uint32_t*)(wh + base))[2*rem+1] = h23;
    ((uint32_t*)(wl + base))[2*rem]   = l01;
    ((uint32_t*)(wl + base))[2*rem+1] = l23;
}

// ---------------- MMA / ldmatrix / cp.async primitives ----------------
#define MMA_OP(d, a, b) asm volatile( \
    "mma.sync.aligned.m16n8k16.row.col.f32.bf16.bf16.f32 " \
    "{%0,%1,%2,%3},{%4,%5,%6,%7},{%8,%9},{%0,%1,%2,%3};" \
    : "+f"(d[0]), "+f"(d[1]), "+f"(d[2]), "+f"(d[3]) \
    : "r"(a[0]), "r"(a[1]), "r"(a[2]), "r"(a[3]), "r"(b[0]), "r"(b[1]))

#define LDSM4(r, addr) asm volatile( \
    "ldmatrix.sync.aligned.m8n8.x4.shared.b16 {%0,%1,%2,%3}, [%4];" \
    : "=r"(r[0]), "=r"(r[1]), "=r"(r[2]), "=r"(r[3]) : "r"(addr))

#define LDSM4T(r, addr) asm volatile( \
    "ldmatrix.sync.aligned.m8n8.x4.trans.shared.b16 {%0,%1,%2,%3}, [%4];" \
    : "=r"(r[0]), "=r"(r[1]), "=r"(r[2]), "=r"(r[3]) : "r"(addr))

__device__ __forceinline__ void cp16(uint32_t dst, const void* src, bool pred) {
    int sz = pred ? 16 : 0;
    asm volatile("cp.async.cg.shared.global [%0], [%1], 16, %2;\n"
                 :: "r"(dst), "l"(src), "r"(sz));
}

// ---------------- split-bf16 tensor-core GEMM ----------------
// C[m][n] = sum_k A[m][k]*W[n][k] + bias[n]
#define BM 128
#define BN 64
#define BK 32
#define SAST 40
#define STAGES 3
#define A_PER_HL (BM * SAST)
#define A_PER_ST (2 * A_PER_HL)
#define W_PER_HL (BN * SAST)
#define W_PER_ST (2 * W_PER_HL)
#define W_BASE   (STAGES * A_PER_ST)
#define SMEM_ELEMS (W_BASE + STAGES * W_PER_ST)   // 46080 bf16 = 92160 B

// SPLIT_OUT=0: write float C; SPLIT_OUT=1: write bf16 hi/lo (Ch, Cl)
template <int SPLIT_OUT>
__global__ __launch_bounds__(256, 2) void gemm_bf16_split(
    const __nv_bfloat16* __restrict__ Ah, const __nv_bfloat16* __restrict__ Al,
    const __nv_bfloat16* __restrict__ Wh, const __nv_bfloat16* __restrict__ Wl,
    const float* __restrict__ bias, float* __restrict__ C,
    __nv_bfloat16* __restrict__ Ch, __nv_bfloat16* __restrict__ Cl, int M)
{
    extern __shared__ __align__(16) __nv_bfloat16 smem[];
    const uint32_t sbase = (uint32_t)__cvta_generic_to_shared(smem);

    const int tid  = threadIdx.x;
    const int lane = tid & 31;
    const int wid  = tid >> 5;
    const int wm   = wid & 3;
    const int wn   = wid >> 2;
    const int bm   = blockIdx.y * BM;
    const int bn   = blockIdx.x * BN;

    const int a_r = (lane & 7) + ((lane >> 3) & 1) * 8;
    const int a_c = ((lane >> 4) & 1) * 8;
    const int g   = lane >> 3;
    const int b_r = (lane & 7) + (g >> 1) * 8;
    const int b_c = (g & 1) * 8;

    uint32_t aoff[2], boff[2];
#pragma unroll
    for (int i = 0; i < 2; i++)
        aoff[i] = (uint32_t)(((wm * 32 + i * 16 + a_r) * SAST + a_c) * 2);
#pragma unroll
    for (int j = 0; j < 2; j++)
        boff[j] = (uint32_t)((W_BASE + (wn * 32 + j * 16 + b_r) * SAST + b_c) * 2);

    float c[2][4][4];
#pragma unroll
    for (int i = 0; i < 2; i++)
#pragma unroll
        for (int j = 0; j < 4; j++)
#pragma unroll
            for (int r = 0; r < 4; r++) c[i][j][r] = 0.f;

    auto load_stage = [&](int s, int kt) {
        int k0 = kt * BK;
#pragma unroll
        for (int i = 0; i < 4; i++) {
            int idx = tid + 256 * i;
            int hl = idx >> 9, rem = idx & 511;
            int row = rem >> 2, seg = rem & 3;
            const __nv_bfloat16* src =
                (hl ? Al : Ah) + (size_t)(bm + row) * ED + k0 + seg * 8;
            uint32_t dst = sbase +
                (uint32_t)((s * A_PER_ST + hl * A_PER_HL + row * SAST + seg * 8) * 2);
            cp16(dst, src, (bm + row) < M);
        }
#pragma unroll
        for (int i = 0; i < 2; i++) {
            int idx = tid + 256 * i;
            int hl = idx >> 8, rem = idx & 255;
            int row = rem >> 2, seg = rem & 3;
            const __nv_bfloat16* src =
                (hl ? Wl : Wh) + (size_t)(bn + row) * ED + k0 + seg * 8;
            uint32_t dst = sbase +
                (uint32_t)((W_BASE + s * W_PER_ST + hl * W_PER_HL + row * SAST + seg * 8) * 2);
            cp16(dst, src, true);
        }
    };

    const int NK = ED / BK;
    load_stage(0, 0);
    asm volatile("cp.async.commit_group;");
    load_stage(1, 1);
    asm volatile("cp.async.commit_group;");

    for (int ks = 0; ks < NK; ks++) {
        asm volatile("cp.async.wait_group 1;");
        __syncthreads();
        if (ks + 2 < NK) load_stage((ks + 2) % STAGES, ks + 2);
        asm volatile("cp.async.commit_group;");

        const int s = ks % STAGES;
        const uint32_t sa = sbase + (uint32_t)(s * A_PER_ST * 2);
        const uint32_t sw = sbase + (uint32_t)(s * W_PER_ST * 2);
#pragma unroll
        for (int h = 0; h < 2; h++) {
            uint32_t ah[2][4], al[2][4], bh[2][4], bl[2][4];
#pragma unroll
            for (int i = 0; i < 2; i++) {
                LDSM4(ah[i], sa + aoff[i] + h * 32);
                LDSM4(al[i], sa + (uint32_t)(A_PER_HL * 2) + aoff[i] + h * 32);
            }
#pragma unroll
            for (int j = 0; j < 2; j++) {
                LDSM4(bh[j], sw + boff[j] + h * 32);
                LDSM4(bl[j], sw + (uint32_t)(W_PER_HL * 2) + boff[j] + h * 32);
            }
            // term-major: same-accumulator reuse distance = 8 MMAs
#pragma unroll
            for (int i = 0; i < 2; i++)
#pragma unroll
                for (int j = 0; j < 2; j++) {
                    MMA_OP(c[i][j*2],   ah[i], (bh[j] + 0));
                    MMA_OP(c[i][j*2+1], ah[i], (bh[j] + 2));
                }
#pragma unroll
            for (int i = 0; i < 2; i++)
#pragma unroll
                for (int j = 0; j < 2; j++) {
                    MMA_OP(c[i][j*2],   ah[i], (bl[j] + 0));
                    MMA_OP(c[i][j*2+1], ah[i], (bl[j] + 2));
                }
#pragma unroll
            for (int i = 0; i < 2; i++)
#pragma unroll
                for (int j = 0; j < 2; j++) {
                    MMA_OP(c[i][j*2],   al[i], (bh[j] + 0));
                    MMA_OP(c[i][j*2+1], al[i], (bh[j] + 2));
                }
        }
    }

#pragma unroll
    for (int i = 0; i < 2; i++) {
        int m0 = bm + wm * 32 + i * 16 + (lane >> 2);
#pragma unroll
        for (int jn = 0; jn < 4; jn++) {
            int n0 = bn + wn * 32 + jn * 8 + (lane & 3) * 2;
            float bx = bias[n0], by = bias[n0 + 1];
            if (SPLIT_OUT) {
                if (m0 < M) {
                    uint32_t hi, lo;
                    split2(c[i][jn][0] + bx, c[i][jn][1] + by, hi, lo);
                    *(uint32_t*)(Ch + (size_t)m0 * ED + n0) = hi;
                    *(uint32_t*)(Cl + (size_t)m0 * ED + n0) = lo;
                }
                if (m0 + 8 < M) {
                    uint32_t hi, lo;
                    split2(c[i][jn][2] + bx, c[i][jn][3] + by, hi, lo);
                    *(uint32_t*)(Ch + (size_t)(m0 + 8) * ED + n0) = hi;
                    *(uint32_t*)(Cl + (size_t)(m0 + 8) * ED + n0) = lo;
                }
            } else {
                if (m0 < M) {
                    float2 v = make_float2(c[i][jn][0] + bx, c[i][jn][1] + by);
                    *(float2*)&C[(size_t)m0 * ED + n0] = v;
                }
                if (m0 + 8 < M) {
                    float2 v = make_float2(c[i][jn][2] + bx, c[i][jn][3] + by);
                    *(float2*)&C[(size_t)(m0 + 8) * ED + n0] = v;
                }
            }
        }
    }
}

// ---------------- 2D RoPE fused with hi/lo split ----------------
__global__ void rope_split_kernel(const float* __restrict__ q, const float* __restrict__ k,
                                  __nv_bfloat16* __restrict__ qh, __nv_bfloat16* __restrict__ ql,
                                  __nv_bfloat16* __restrict__ kh, __nv_bfloat16* __restrict__ kl)
{
    int t = blockIdx.x * blockDim.x + threadIdx.x;
    const int total = BATCH * SEQ * NH * 32;
    if (t >= total) return;

    int d = t & 31;
    int h = (t >> 5) & 15;
    int s = (t >> 9) % SEQ;
    int b = t / (SEQ << 9);

    size_t base = ((size_t)(b * SEQ + s) * ED) + (size_t)h * HD;

    float q1 = q[base + d], q2 = q[base + d + 32];
    float k1 = k[base + d], k2 = k[base + d + 32];

    if (s > 0) {
        int p = s - 1;
        int gh = p / 24, gw = p % 24;
        float invf = exp2f(-(float)(d & 15) * (13.287712379549449f / 16.f));
        float s1, c1, s2, c2;
        sincosf((float)gh * invf, &s1, &c1);
        sincosf((float)gw * invf, &s2, &c2);
        float nq1 = q1 * c1 - q2 * s1;
        float nq2 = q2 * c2 + q1 * s2;
        float nk1 = k1 * c1 - k2 * s1;
        float nk2 = k2 * c2 + k1 * s2;
        q1 = nq1; q2 = nq2; k1 = nk1; k2 = nk2;
    }

    __nv_bfloat16 hq1 = __float2bfloat16(q1), hq2 = __float2bfloat16(q2);
    __nv_bfloat16 hk1 = __float2bfloat16(k1), hk2 = __float2bfloat16(k2);
    qh[base + d]      = hq1;
    qh[base + d + 32] = hq2;
    ql[base + d]      = __float2bfloat16(q1 - __bfloat162float(hq1));
    ql[base + d + 32] = __float2bfloat16(q2 - __bfloat162float(hq2));
    kh[base + d]      = hk1;
    kh[base + d + 32] = hk2;
    kl[base + d]      = __float2bfloat16(k1 - __bfloat162float(hk1));
    kl[base + d + 32] = __float2bfloat16(k2 - __bfloat162float(hk2));
}

// ---------------- tensor-core flash attention ----------------
#define TSTR 72
#define MATB (64 * TSTR * 2)
#define STGB (4 * MATB)
#define ATT_SMEM (2 * STGB)

__global__ __launch_bounds__(128) void attn_mma(
    const __nv_bfloat16* __restrict__ qh, const __nv_bfloat16* __restrict__ ql,
    const __nv_bfloat16* __restrict__ kh, const __nv_bfloat16* __restrict__ kl,
    const __nv_bfloat16* __restrict__ vh, const __nv_bfloat16* __restrict__ vl,
    __nv_bfloat16* __restrict__ oh, __nv_bfloat16* __restrict__ ol)
{
    extern __shared__ __align__(16) __nv_bfloat16 asmem[];
    const uint32_t sbase = (uint32_t)__cvta_generic_to_shared(asmem);

    const int tid  = threadIdx.x;
    const int lane = tid & 31;
    const int w    = tid >> 5;
    const int b    = blockIdx.z;
    const int h    = blockIdx.y;
    const int qt   = blockIdx.x;
    const size_t hoff = (size_t)h * HD;
    const size_t bbase = (size_t)b * SEQ;

    const int a_r = (lane & 7) + ((lane >> 3) & 1) * 8;
    const int a_c = ((lane >> 4) & 1) * 8;
    const int g   = lane >> 3;
    const int b_r = (lane & 7) + (g >> 1) * 8;
    const int b_c = (g & 1) * 8;

    for (int c = tid; c < 1024; c += 128) {
        int mat = c >> 9, row = (c >> 3) & 63, seg = c & 7;
        int qrow = qt * 64 + row;
        if (qrow >= SEQ) qrow = SEQ - 1;
        const __nv_bfloat16* src = (mat ? ql : qh) + (bbase + qrow) * ED + hoff + seg * 8;
        cp16(sbase + mat * MATB + row * 144 + seg * 16, src, true);
    }
    asm volatile("cp.async.commit_group;");
    asm volatile("cp.async.wait_group 0;");
    __syncthreads();

    uint32_t qhf[4][4], qlf[4][4];
#pragma unroll
    for (int kc = 0; kc < 4; kc++) {
        uint32_t base0 = sbase + (uint32_t)((w * 16 + a_r) * 144 + (kc * 16 + a_c) * 2);
        LDSM4(qhf[kc], base0);
        LDSM4(qlf[kc], base0 + MATB);
    }
    __syncthreads();

    auto load_kv = [&](int s, int t) {
        const __nv_bfloat16* mats[4] = {kh, kl, vh, vl};
        for (int c = tid; c < 2048; c += 128) {
            int mat = c >> 9, row = (c >> 3) & 63, seg = c & 7;
            int kr = t * 64 + row;
            int krc = (kr < SEQ) ? kr : 0;
            const __nv_bfloat16* src = mats[mat] + (bbase + krc) * ED + hoff + seg * 8;
            cp16(sbase + s * STGB + mat * MATB + row * 144 + seg * 16, src, kr < SEQ);
        }
    };
    load_kv(0, 0);
    asm volatile("cp.async.commit_group;");
    load_kv(1, 1);
    asm volatile("cp.async.commit_group;");

    float off_[8][4];
#pragma unroll
    for (int ng = 0; ng < 8; ng++)
#pragma unroll
        for (int r = 0; r < 4; r++) off_[ng][r] = 0.f;
    float m_lo = -1e30f, m_hi = -1e30f, l_lo = 0.f, l_hi = 0.f;

    const float SCL = 0.18033688011112042f;

    for (int t = 0; t < NT; t++) {
        if (t < NT - 1) { asm volatile("cp.async.wait_group 1;"); }
        else            { asm volatile("cp.async.wait_group 0;"); }
        __syncthreads();
        const uint32_t sb2 = sbase + (uint32_t)((t & 1) * STGB);

        float sfr[8][4];
#pragma unroll
        for (int ng = 0; ng < 8; ng++)
#pragma unroll
            for (int r = 0; r < 4; r++) sfr[ng][r] = 0.f;

#pragma unroll
        for (int kc = 0; kc < 4; kc++) {
            uint32_t kf[4][4], lf[4][4];
#pragma unroll
            for (int pp = 0; pp < 4; pp++) {
                uint32_t ad = sb2 + (uint32_t)((pp * 16 + b_r) * 144 + (kc * 16 + b_c) * 2);
                LDSM4(kf[pp], ad);
                LDSM4(lf[pp], ad + MATB);
            }
            // term-major: reuse distance 8
#pragma unroll
            for (int ng = 0; ng < 8; ng++)
                MMA_OP(sfr[ng], qhf[kc], (kf[ng >> 1] + (ng & 1) * 2));
#pragma unroll
            for (int ng = 0; ng < 8; ng++)
                MMA_OP(sfr[ng], qhf[kc], (lf[ng >> 1] + (ng & 1) * 2));
#pragma unroll
            for (int ng = 0; ng < 8; ng++)
                MMA_OP(sfr[ng], qlf[kc], (kf[ng >> 1] + (ng & 1) * 2));
        }

        if (t * 64 + 64 > SEQ) {
            int tig2 = 2 * (lane & 3);
#pragma unroll
            for (int ng = 0; ng < 8; ng++) {
                int key0 = t * 64 + ng * 8 + tig2;
                if (key0     >= SEQ) { sfr[ng][0] = -1e30f; sfr[ng][2] = -1e30f; }
                if (key0 + 1 >= SEQ) { sfr[ng][1] = -1e30f; sfr[ng][3] = -1e30f; }
            }
        }

        float mx0 = -1e30f, mx1 = -1e30f;
#pragma unroll
        for (int ng = 0; ng < 8; ng++) {
            mx0 = fmaxf(mx0, fmaxf(sfr[ng][0], sfr[ng][1]));
            mx1 = fmaxf(mx1, fmaxf(sfr[ng][2], sfr[ng][3]));
        }
        mx0 = fmaxf(mx0, __shfl_xor_sync(0xffffffff, mx0, 1));
        mx0 = fmaxf(mx0, __shfl_xor_sync(0xffffffff, mx0, 2));
        mx1 = fmaxf(mx1, __shfl_xor_sync(0xffffffff, mx1, 1));
        mx1 = fmaxf(mx1, __shfl_xor_sync(0xffffffff, mx1, 2));
        float mn0 = fmaxf(m_lo, mx0), mn1 = fmaxf(m_hi, mx1);
        float al0 = ex2f((m_lo - mn0) * SCL), al1 = ex2f((m_hi - mn1) * SCL);
        m_lo = mn0; m_hi = mn1;

        float s0 = 0.f, s1 = 0.f;
#pragma unroll
        for (int ng = 0; ng < 8; ng++) {
            sfr[ng][0] = ex2f((sfr[ng][0] - mn0) * SCL);
            sfr[ng][1] = ex2f((sfr[ng][1] - mn0) * SCL);
            sfr[ng][2] = ex2f((sfr[ng][2] - mn1) * SCL);
            sfr[ng][3] = ex2f((sfr[ng][3] - mn1) * SCL);
            s0 += sfr[ng][0] + sfr[ng][1];
            s1 += sfr[ng][2] + sfr[ng][3];
        }
        s0 += __shfl_xor_sync(0xffffffff, s0, 1);
        s0 += __shfl_xor_sync(0xffffffff, s0, 2);
        s1 += __shfl_xor_sync(0xffffffff, s1, 1);
        s1 += __shfl_xor_sync(0xffffffff, s1, 2);
        l_lo = l_lo * al0 + s0;
        l_hi = l_hi * al1 + s1;

#pragma unroll
        for (int ng = 0; ng < 8; ng++) {
            off_[ng][0] *= al0; off_[ng][1] *= al0;
            off_[ng][2] *= al1; off_[ng][3] *= al1;
        }

        uint32_t ph[4][4], pl[4][4];
#pragma unroll
        for (int kc = 0; kc < 4; kc++) {
            split2(sfr[2*kc][0],   sfr[2*kc][1],   ph[kc][0], pl[kc][0]);
            split2(sfr[2*kc][2],   sfr[2*kc][3],   ph[kc][1], pl[kc][1]);
            split2(sfr[2*kc+1][0], sfr[2*kc+1][1], ph[kc][2], pl[kc][2]);
            split2(sfr[2*kc+1][2], sfr[2*kc+1][3], ph[kc][3], pl[kc][3]);
        }

#pragma unroll
        for (int kc = 0; kc < 4; kc++) {
            uint32_t vf[4][4], wf[4][4];
#pragma unroll
            for (int dp = 0; dp < 4; dp++) {
                uint32_t ad = sb2 + (uint32_t)(2 * MATB +
                               (kc * 16 + a_r) * 144 + (dp * 16 + a_c) * 2);
                LDSM4T(vf[dp], ad);
                LDSM4T(wf[dp], ad + MATB);
            }
            // term-major: reuse distance 8
#pragma unroll
            for (int ng = 0; ng < 8; ng++)
                MMA_OP(off_[ng], ph[kc], (vf[ng >> 1] + (ng & 1) * 2));
#pragma unroll
            for (int ng = 0; ng < 8; ng++)
                MMA_OP(off_[ng], pl[kc], (vf[ng >> 1] + (ng & 1) * 2));
#pragma unroll
            for (int ng = 0; ng < 8; ng++)
                MMA_OP(off_[ng], ph[kc], (wf[ng >> 1] + (ng & 1) * 2));
        }

        __syncthreads();
        if (t + 2 < NT) {
            load_kv(t & 1, t + 2);
            asm volatile("cp.async.commit_group;");
        }
    }

    float inv0 = 1.f / l_lo, inv1 = 1.f / l_hi;
    int q0 = qt * 64 + w * 16 + (lane >> 2);
    int col = 2 * (lane & 3);
#pragma unroll
    for (int ng = 0; ng < 8; ng++) {
        int n0 = ng * 8 + col;
        if (q0 < SEQ) {
            uint32_t hi, lo;
            split2(off_[ng][0] * inv0, off_[ng][1] * inv0, hi, lo);
            *(uint32_t*)(oh + (bbase + q0) * ED + hoff + n0) = hi;
            *(uint32_t*)(ol + (bbase + q0) * ED + hoff + n0) = lo;
        }
        if (q0 + 8 < SEQ) {
            uint32_t hi, lo;
            split2(off_[ng][2] * inv1, off_[ng][3] * inv1, hi, lo);
            *(uint32_t*)(oh + (bbase + q0 + 8) * ED + hoff + n0) = hi;
            *(uint32_t*)(ol + (bbase + q0 + 8) * ED + hoff + n0) = lo;
        }
    }
}

// ---------------- launch ----------------
extern "C" void kernel_launch(void* const* d_in, const int* in_sizes, int n_in,
                              void* d_out, int out_size)
{
    const float* hs = (const float*)d_in[0];
    const float* Wq = (const float*)d_in[1];
    const float* bq = (const float*)d_in[2];
    const float* Wk = (const float*)d_in[3];
    const float* bk = (const float*)d_in[4];
    const float* Wv = (const float*)d_in[5];
    const float* bv = (const float*)d_in[6];
    const float* Wo = (const float*)d_in[7];
    const float* bo = (const float*)d_in[8];
    float* out = (float*)d_out;

    float *qb, *kb;
    cudaGetSymbolAddress((void**)&qb, g_q);
    cudaGetSymbolAddress((void**)&kb, g_k);
    __nv_bfloat16 *hsh, *hsl, *oh, *ol, *wh, *wl;
    __nv_bfloat16 *qhp, *qlp, *khp, *klp, *vhp, *vlp;
    cudaGetSymbolAddress((void**)&hsh, g_hsh);
    cudaGetSymbolAddress((void**)&hsl, g_hsl);
    cudaGetSymbolAddress((void**)&oh, g_oh);
    cudaGetSymbolAddress((void**)&ol, g_ol);
    cudaGetSymbolAddress((void**)&wh, g_wh);
    cudaGetSymbolAddress((void**)&wl, g_wl);
    cudaGetSymbolAddress((void**)&qhp, g_qh);
    cudaGetSymbolAddress((void**)&qlp, g_ql);
    cudaGetSymbolAddress((void**)&khp, g_kh);
    cudaGetSymbolAddress((void**)&klp, g_kl);
    cudaGetSymbolAddress((void**)&vhp, g_vh);
    cudaGetSymbolAddress((void**)&vlp, g_vl);

    cudaFuncSetAttribute(gemm_bf16_split<0>,
                         cudaFuncAttributeMaxDynamicSharedMemorySize, SMEM_ELEMS * 2);
    cudaFuncSetAttribute(gemm_bf16_split<1>,
                         cudaFuncAttributeMaxDynamicSharedMemorySize, SMEM_ELEMS * 2);
    cudaFuncSetAttribute(attn_mma,
                         cudaFuncAttributeMaxDynamicSharedMemorySize, ATT_SMEM);

    const size_t WSZ = (size_t)ED * ED;
    const int n4_hs = MROWS * ED / 4;
    const int n4_w  = ED * ED / 4;

    cvt_split_kernel<<<(n4_hs + 255) / 256, 256>>>(hs, hsh, hsl, n4_hs);
    cvt_split4_kernel<<<(4 * n4_w + 255) / 256, 256>>>(Wq, Wk, Wv, Wo, wh, wl, n4_w);

    dim3 ggrid(ED / BN, (MROWS + BM - 1) / BM);
    size_t gsmem = SMEM_ELEMS * 2;

    gemm_bf16_split<0><<<ggrid, 256, gsmem>>>(hsh, hsl, wh + 0*WSZ, wl + 0*WSZ, bq,
                                              qb, nullptr, nullptr, MROWS);
    gemm_bf16_split<0><<<ggrid, 256, gsmem>>>(hsh, hsl, wh + 1*WSZ, wl + 1*WSZ, bk,
                                              kb, nullptr, nullptr, MROWS);
    gemm_bf16_split<1><<<ggrid, 256, gsmem>>>(hsh, hsl, wh + 2*WSZ, wl + 2*WSZ, bv,
                                              nullptr, vhp, vlp, MROWS);

    int rt = BATCH * SEQ * NH * 32;
    rope_split_kernel<<<(rt + 255) / 256, 256>>>(qb, kb, qhp, qlp, khp, klp);

    attn_mma<<<dim3(QT, NH, BATCH), 128, ATT_SMEM>>>(qhp, qlp, khp, klp, vhp, vlp, oh, ol);

    gemm_bf16_split<0><<<ggrid, 256, gsmem>>>(oh, ol, wh + 3*WSZ, wl + 3*WSZ, bo,
                                              out, nullptr, nullptr, MROWS);
}

// round 7
// speedup vs baseline: 4.7235x; 1.0271x over previous
#include <cuda_runtime.h>
#include <cuda_bf16.h>
#include <cstdint>
#include <math.h>

#define ED   1024
#define NH   16
#define HD   64
#define SEQ  577
#define BATCH 16
#define MROWS (BATCH * SEQ)   // 9232
#define NT   10
#define QT   10

// ---------------- scratch ----------------
__device__ float g_q[(size_t)MROWS * ED];
__device__ float g_k[(size_t)MROWS * ED];

__device__ __nv_bfloat16 g_hsh[(size_t)MROWS * ED];
__device__ __nv_bfloat16 g_hsl[(size_t)MROWS * ED];
__device__ __nv_bfloat16 g_oh[(size_t)MROWS * ED];
__device__ __nv_bfloat16 g_ol[(size_t)MROWS * ED];
__device__ __nv_bfloat16 g_wh[4][(size_t)ED * ED];
__device__ __nv_bfloat16 g_wl[4][(size_t)ED * ED];
__device__ __nv_bfloat16 g_qh[(size_t)MROWS * ED];
__device__ __nv_bfloat16 g_ql[(size_t)MROWS * ED];
__device__ __nv_bfloat16 g_kh[(size_t)MROWS * ED];
__device__ __nv_bfloat16 g_kl[(size_t)MROWS * ED];
__device__ __nv_bfloat16 g_vh[(size_t)MROWS * ED];
__device__ __nv_bfloat16 g_vl[(size_t)MROWS * ED];

// ---------------- helpers ----------------
__device__ __forceinline__ float ex2f(float x) {
    float r;
    asm("ex2.approx.ftz.f32 %0, %1;" : "=f"(r) : "f"(x));
    return r;
}
__device__ __forceinline__ uint32_t packbf2(__nv_bfloat16 a, __nv_bfloat16 b) {
    __nv_bfloat162 v = __halves2bfloat162(a, b);
    return *(uint32_t*)&v;
}
__device__ __forceinline__ void split2(float a, float b, uint32_t& hi, uint32_t& lo) {
    __nv_bfloat16 ha = __float2bfloat16(a), hb = __float2bfloat16(b);
    __nv_bfloat16 la = __float2bfloat16(a - __bfloat162float(ha));
    __nv_bfloat16 lb = __float2bfloat16(b - __bfloat162float(hb));
    hi = packbf2(ha, hb);
    lo = packbf2(la, lb);
}

// ---------------- fp32 -> bf16 hi/lo split ----------------
__global__ void cvt_split_kernel(const float* __restrict__ x,
                                 __nv_bfloat16* __restrict__ h,
                                 __nv_bfloat16* __restrict__ l, int n4)
{
    int i = blockIdx.x * blockDim.x + threadIdx.x;
    if (i >= n4) return;
    float4 v = ((const float4*)x)[i];
    uint32_t h01, l01, h23, l23;
    split2(v.x, v.y, h01, l01);
    split2(v.z, v.w, h23, l23);
    ((uint32_t*)h)[2*i]   = h01;
    ((uint32_t*)h)[2*i+1] = h23;
    ((uint32_t*)l)[2*i]   = l01;
    ((uint32_t*)l)[2*i+1] = l23;
}

__global__ void cvt_split4_kernel(const float* __restrict__ w0, const float* __restrict__ w1,
                                  const float* __restrict__ w2, const float* __restrict__ w3,
                                  __nv_bfloat16* __restrict__ wh, __nv_bfloat16* __restrict__ wl,
                                  int n4_per)
{
    int i = blockIdx.x * blockDim.x + threadIdx.x;
    if (i >= 4 * n4_per) return;
    int sel = i / n4_per;
    int rem = i - sel * n4_per;
    const float* src = (sel == 0) ? w0 : (sel == 1) ? w1 : (sel == 2) ? w2 : w3;
    size_t base = (size_t)sel * (size_t)ED * ED;
    float4 v = ((const float4*)src)[rem];
    uint32_t h01, l01, h23, l23;
    split2(v.x, v.y, h01, l01);
    split2(v.z, v.w, h23, l23);
    ((uint32_t*)(wh + base))[2*rem]   = h01;
    ((uint32_t*)(wh + base))[2*rem+1] = h23;
    ((uint32_t*)(wl + base))[2*rem]   = l01;
    ((uint32_t*)(wl + base))[2*rem+1] = l23;
}

// ---------------- MMA / ldmatrix / cp.async primitives ----------------
#define MMA_OP(d, a, b) asm volatile( \
    "mma.sync.aligned.m16n8k16.row.col.f32.bf16.bf16.f32 " \
    "{%0,%1,%2,%3},{%4,%5,%6,%7},{%8,%9},{%0,%1,%2,%3};" \
    : "+f"(d[0]), "+f"(d[1]), "+f"(d[2]), "+f"(d[3]) \
    : "r"(a[0]), "r"(a[1]), "r"(a[2]), "r"(a[3]), "r"(b[0]), "r"(b[1]))

#define LDSM4(r, addr) asm volatile( \
    "ldmatrix.sync.aligned.m8n8.x4.shared.b16 {%0,%1,%2,%3}, [%4];" \
    : "=r"(r[0]), "=r"(r[1]), "=r"(r[2]), "=r"(r[3]) : "r"(addr))

#define LDSM4T(r, addr) asm volatile( \
    "ldmatrix.sync.aligned.m8n8.x4.trans.shared.b16 {%0,%1,%2,%3}, [%4];" \
    : "=r"(r[0]), "=r"(r[1]), "=r"(r[2]), "=r"(r[3]) : "r"(addr))

__device__ __forceinline__ void cp16(uint32_t dst, const void* src, bool pred) {
    int sz = pred ? 16 : 0;
    asm volatile("cp.async.cg.shared.global [%0], [%1], 16, %2;\n"
                 :: "r"(dst), "l"(src), "r"(sz));
}

// ---------------- split-bf16 GEMM, 64x64 warp tiles ----------------
// C[m][n] = sum_k A[m][k]*W[n][k] + bias[n]
// BM=128, BN=128, 4 warps (warp = 64x64), BK=32, 2-stage.
#define BM 128
#define BN 128
#define BK 32
#define SAST 40                        // padded row stride (bf16), 80B
#define HL_ELEMS (128 * SAST)          // 5120 elems per hi/lo matrix
#define HL_B     (HL_ELEMS * 2)        // 10240 bytes
#define STG_B    (4 * HL_B)            // 40960 bytes (Ah,Al,Wh,Wl)
#define GSMEM    (2 * STG_B)           // 81920 bytes

template <int SPLIT_OUT>
__global__ __launch_bounds__(128) void gemm_bf16_split(
    const __nv_bfloat16* __restrict__ Ah, const __nv_bfloat16* __restrict__ Al,
    const __nv_bfloat16* __restrict__ Wh, const __nv_bfloat16* __restrict__ Wl,
    const float* __restrict__ bias, float* __restrict__ C,
    __nv_bfloat16* __restrict__ Ch, __nv_bfloat16* __restrict__ Cl, int M)
{
    extern __shared__ __align__(16) char smem[];
    const uint32_t sbase = (uint32_t)__cvta_generic_to_shared(smem);

    const int tid  = threadIdx.x;
    const int lane = tid & 31;
    const int wid  = tid >> 5;
    const int wm   = wid & 1;       // 2 warps over M (64 rows each)
    const int wn   = wid >> 1;      // 2 warps over N (64 cols each)
    const int bm   = blockIdx.y * BM;
    const int bn   = blockIdx.x * BN;

    const int a_r = (lane & 7) + ((lane >> 3) & 1) * 8;
    const int a_c = ((lane >> 4) & 1) * 8;
    const int g   = lane >> 3;
    const int b_r = (lane & 7) + (g >> 1) * 8;
    const int b_c = (g & 1) * 8;

    uint32_t aoff[4], boff[4];
#pragma unroll
    for (int i = 0; i < 4; i++)
        aoff[i] = (uint32_t)(((wm * 64 + i * 16 + a_r) * SAST + a_c) * 2);
#pragma unroll
    for (int j = 0; j < 4; j++)
        boff[j] = (uint32_t)(2 * HL_B + ((wn * 64 + j * 16 + b_r) * SAST + b_c) * 2);

    float c[4][8][4];
#pragma unroll
    for (int i = 0; i < 4; i++)
#pragma unroll
        for (int j = 0; j < 8; j++)
#pragma unroll
            for (int r = 0; r < 4; r++) c[i][j][r] = 0.f;

    // stage loader: 2048 cp16 per stage, 16 per thread
    auto load_stage = [&](int s, int kt) {
        int k0 = kt * BK;
        uint32_t stb = sbase + (uint32_t)(s * STG_B);
#pragma unroll
        for (int i = 0; i < 16; i++) {
            int idx = tid + 128 * i;
            if (idx < 1024) {
                int hl = idx >> 9, rem = idx & 511;
                int row = rem >> 2, seg = rem & 3;
                const __nv_bfloat16* src =
                    (hl ? Al : Ah) + (size_t)(bm + row) * ED + k0 + seg * 8;
                cp16(stb + (uint32_t)(hl * HL_B + (row * SAST + seg * 8) * 2),
                     src, (bm + row) < M);
            } else {
                int j = idx - 1024;
                int hl = j >> 9, rem = j & 511;
                int row = rem >> 2, seg = rem & 3;
                const __nv_bfloat16* src =
                    (hl ? Wl : Wh) + (size_t)(bn + row) * ED + k0 + seg * 8;
                cp16(stb + (uint32_t)(2 * HL_B + hl * HL_B + (row * SAST + seg * 8) * 2),
                     src, true);
            }
        }
    };

    const int NK = ED / BK;  // 32
    load_stage(0, 0);
    asm volatile("cp.async.commit_group;");
    load_stage(1, 1);
    asm volatile("cp.async.commit_group;");

    for (int ks = 0; ks < NK; ks++) {
        if (ks < NK - 1) { asm volatile("cp.async.wait_group 1;"); }
        else             { asm volatile("cp.async.wait_group 0;"); }
        __syncthreads();

        const uint32_t sa = sbase + (uint32_t)((ks & 1) * STG_B);
#pragma unroll
        for (int h = 0; h < 2; h++) {
            uint32_t ah[4][4], al[4][4];
#pragma unroll
            for (int i = 0; i < 4; i++) {
                LDSM4(ah[i], sa + aoff[i] + h * 32);
                LDSM4(al[i], sa + (uint32_t)HL_B + aoff[i] + h * 32);
            }
            uint32_t bh[2][4], bl[2][4];
            LDSM4(bh[0], sa + boff[0] + h * 32);
            LDSM4(bl[0], sa + (uint32_t)HL_B + boff[0] + h * 32);
#pragma unroll
            for (int jj = 0; jj < 4; jj++) {
                int cur = jj & 1, nxt = cur ^ 1;
                if (jj < 3) {
                    LDSM4(bh[nxt], sa + boff[jj + 1] + h * 32);
                    LDSM4(bl[nxt], sa + (uint32_t)HL_B + boff[jj + 1] + h * 32);
                }
#pragma unroll
                for (int i = 0; i < 4; i++) {
                    MMA_OP(c[i][2*jj],   ah[i], (bh[cur] + 0));
                    MMA_OP(c[i][2*jj+1], ah[i], (bh[cur] + 2));
                }
#pragma unroll
                for (int i = 0; i < 4; i++) {
                    MMA_OP(c[i][2*jj],   ah[i], (bl[cur] + 0));
                    MMA_OP(c[i][2*jj+1], ah[i], (bl[cur] + 2));
                }
#pragma unroll
                for (int i = 0; i < 4; i++) {
                    MMA_OP(c[i][2*jj],   al[i], (bh[cur] + 0));
                    MMA_OP(c[i][2*jj+1], al[i], (bh[cur] + 2));
                }
            }
        }

        __syncthreads();
        if (ks + 2 < NK) {
            load_stage(ks & 1, ks + 2);
            asm volatile("cp.async.commit_group;");
        }
    }

    // epilogue
#pragma unroll
    for (int i = 0; i < 4; i++) {
        int m0 = bm + wm * 64 + i * 16 + (lane >> 2);
#pragma unroll
        for (int jn = 0; jn < 8; jn++) {
            int n0 = bn + wn * 64 + jn * 8 + (lane & 3) * 2;
            float bx = bias[n0], by = bias[n0 + 1];
            if (SPLIT_OUT) {
                if (m0 < M) {
                    uint32_t hi, lo;
                    split2(c[i][jn][0] + bx, c[i][jn][1] + by, hi, lo);
                    *(uint32_t*)(Ch + (size_t)m0 * ED + n0) = hi;
                    *(uint32_t*)(Cl + (size_t)m0 * ED + n0) = lo;
                }
                if (m0 + 8 < M) {
                    uint32_t hi, lo;
                    split2(c[i][jn][2] + bx, c[i][jn][3] + by, hi, lo);
                    *(uint32_t*)(Ch + (size_t)(m0 + 8) * ED + n0) = hi;
                    *(uint32_t*)(Cl + (size_t)(m0 + 8) * ED + n0) = lo;
                }
            } else {
                if (m0 < M) {
                    float2 v = make_float2(c[i][jn][0] + bx, c[i][jn][1] + by);
                    *(float2*)&C[(size_t)m0 * ED + n0] = v;
                }
                if (m0 + 8 < M) {
                    float2 v = make_float2(c[i][jn][2] + bx, c[i][jn][3] + by);
                    *(float2*)&C[(size_t)(m0 + 8) * ED + n0] = v;
                }
            }
        }
    }
}

// ---------------- 2D RoPE fused with hi/lo split ----------------
__global__ void rope_split_kernel(const float* __restrict__ q, const float* __restrict__ k,
                                  __nv_bfloat16* __restrict__ qh, __nv_bfloat16* __restrict__ ql,
                                  __nv_bfloat16* __restrict__ kh, __nv_bfloat16* __restrict__ kl)
{
    int t = blockIdx.x * blockDim.x + threadIdx.x;
    const int total = BATCH * SEQ * NH * 32;
    if (t >= total) return;

    int d = t & 31;
    int h = (t >> 5) & 15;
    int s = (t >> 9) % SEQ;
    int b = t / (SEQ << 9);

    size_t base = ((size_t)(b * SEQ + s) * ED) + (size_t)h * HD;

    float q1 = q[base + d], q2 = q[base + d + 32];
    float k1 = k[base + d], k2 = k[base + d + 32];

    if (s > 0) {
        int p = s - 1;
        int gh = p / 24, gw = p % 24;
        float invf = exp2f(-(float)(d & 15) * (13.287712379549449f / 16.f));
        float s1, c1, s2, c2;
        sincosf((float)gh * invf, &s1, &c1);
        sincosf((float)gw * invf, &s2, &c2);
        float nq1 = q1 * c1 - q2 * s1;
        float nq2 = q2 * c2 + q1 * s2;
        float nk1 = k1 * c1 - k2 * s1;
        float nk2 = k2 * c2 + k1 * s2;
        q1 = nq1; q2 = nq2; k1 = nk1; k2 = nk2;
    }

    __nv_bfloat16 hq1 = __float2bfloat16(q1), hq2 = __float2bfloat16(q2);
    __nv_bfloat16 hk1 = __float2bfloat16(k1), hk2 = __float2bfloat16(k2);
    qh[base + d]      = hq1;
    qh[base + d + 32] = hq2;
    ql[base + d]      = __float2bfloat16(q1 - __bfloat162float(hq1));
    ql[base + d + 32] = __float2bfloat16(q2 - __bfloat162float(hq2));
    kh[base + d]      = hk1;
    kh[base + d + 32] = hk2;
    kl[base + d]      = __float2bfloat16(k1 - __bfloat162float(hk1));
    kl[base + d + 32] = __float2bfloat16(k2 - __bfloat162float(hk2));
}

// ---------------- tensor-core flash attention (unchanged from R6) ----------------
#define TSTR 72
#define MATB (64 * TSTR * 2)
#define STGB (4 * MATB)
#define ATT_SMEM (2 * STGB)

__global__ __launch_bounds__(128) void attn_mma(
    const __nv_bfloat16* __restrict__ qh, const __nv_bfloat16* __restrict__ ql,
    const __nv_bfloat16* __restrict__ kh, const __nv_bfloat16* __restrict__ kl,
    const __nv_bfloat16* __restrict__ vh, const __nv_bfloat16* __restrict__ vl,
    __nv_bfloat16* __restrict__ oh, __nv_bfloat16* __restrict__ ol)
{
    extern __shared__ __align__(16) __nv_bfloat16 asmem[];
    const uint32_t sbase = (uint32_t)__cvta_generic_to_shared(asmem);

    const int tid  = threadIdx.x;
    const int lane = tid & 31;
    const int w    = tid >> 5;
    const int b    = blockIdx.z;
    const int h    = blockIdx.y;
    const int qt   = blockIdx.x;
    const size_t hoff = (size_t)h * HD;
    const size_t bbase = (size_t)b * SEQ;

    const int a_r = (lane & 7) + ((lane >> 3) & 1) * 8;
    const int a_c = ((lane >> 4) & 1) * 8;
    const int g   = lane >> 3;
    const int b_r = (lane & 7) + (g >> 1) * 8;
    const int b_c = (g & 1) * 8;

    for (int c = tid; c < 1024; c += 128) {
        int mat = c >> 9, row = (c >> 3) & 63, seg = c & 7;
        int qrow = qt * 64 + row;
        if (qrow >= SEQ) qrow = SEQ - 1;
        const __nv_bfloat16* src = (mat ? ql : qh) + (bbase + qrow) * ED + hoff + seg * 8;
        cp16(sbase + mat * MATB + row * 144 + seg * 16, src, true);
    }
    asm volatile("cp.async.commit_group;");
    asm volatile("cp.async.wait_group 0;");
    __syncthreads();

    uint32_t qhf[4][4], qlf[4][4];
#pragma unroll
    for (int kc = 0; kc < 4; kc++) {
        uint32_t base0 = sbase + (uint32_t)((w * 16 + a_r) * 144 + (kc * 16 + a_c) * 2);
        LDSM4(qhf[kc], base0);
        LDSM4(qlf[kc], base0 + MATB);
    }
    __syncthreads();

    auto load_kv = [&](int s, int t) {
        const __nv_bfloat16* mats[4] = {kh, kl, vh, vl};
        for (int c = tid; c < 2048; c += 128) {
            int mat = c >> 9, row = (c >> 3) & 63, seg = c & 7;
            int kr = t * 64 + row;
            int krc = (kr < SEQ) ? kr : 0;
            const __nv_bfloat16* src = mats[mat] + (bbase + krc) * ED + hoff + seg * 8;
            cp16(sbase + s * STGB + mat * MATB + row * 144 + seg * 16, src, kr < SEQ);
        }
    };
    load_kv(0, 0);
    asm volatile("cp.async.commit_group;");
    load_kv(1, 1);
    asm volatile("cp.async.commit_group;");

    float off_[8][4];
#pragma unroll
    for (int ng = 0; ng < 8; ng++)
#pragma unroll
        for (int r = 0; r < 4; r++) off_[ng][r] = 0.f;
    float m_lo = -1e30f, m_hi = -1e30f, l_lo = 0.f, l_hi = 0.f;

    const float SCL = 0.18033688011112042f;

    for (int t = 0; t < NT; t++) {
        if (t < NT - 1) { asm volatile("cp.async.wait_group 1;"); }
        else            { asm volatile("cp.async.wait_group 0;"); }
        __syncthreads();
        const uint32_t sb2 = sbase + (uint32_t)((t & 1) * STGB);

        float sfr[8][4];
#pragma unroll
        for (int ng = 0; ng < 8; ng++)
#pragma unroll
            for (int r = 0; r < 4; r++) sfr[ng][r] = 0.f;

#pragma unroll
        for (int kc = 0; kc < 4; kc++) {
            uint32_t kf[4][4], lf[4][4];
#pragma unroll
            for (int pp = 0; pp < 4; pp++) {
                uint32_t ad = sb2 + (uint32_t)((pp * 16 + b_r) * 144 + (kc * 16 + b_c) * 2);
                LDSM4(kf[pp], ad);
                LDSM4(lf[pp], ad + MATB);
            }
#pragma unroll
            for (int ng = 0; ng < 8; ng++)
                MMA_OP(sfr[ng], qhf[kc], (kf[ng >> 1] + (ng & 1) * 2));
#pragma unroll
            for (int ng = 0; ng < 8; ng++)
                MMA_OP(sfr[ng], qhf[kc], (lf[ng >> 1] + (ng & 1) * 2));
#pragma unroll
            for (int ng = 0; ng < 8; ng++)
                MMA_OP(sfr[ng], qlf[kc], (kf[ng >> 1] + (ng & 1) * 2));
        }

        if (t * 64 + 64 > SEQ) {
            int tig2 = 2 * (lane & 3);
#pragma unroll
            for (int ng = 0; ng < 8; ng++) {
                int key0 = t * 64 + ng * 8 + tig2;
                if (key0     >= SEQ) { sfr[ng][0] = -1e30f; sfr[ng][2] = -1e30f; }
                if (key0 + 1 >= SEQ) { sfr[ng][1] = -1e30f; sfr[ng][3] = -1e30f; }
            }
        }

        float mx0 = -1e30f, mx1 = -1e30f;
#pragma unroll
        for (int ng = 0; ng < 8; ng++) {
            mx0 = fmaxf(mx0, fmaxf(sfr[ng][0], sfr[ng][1]));
            mx1 = fmaxf(mx1, fmaxf(sfr[ng][2], sfr[ng][3]));
        }
        mx0 = fmaxf(mx0, __shfl_xor_sync(0xffffffff, mx0, 1));
        mx0 = fmaxf(mx0, __shfl_xor_sync(0xffffffff, mx0, 2));
        mx1 = fmaxf(mx1, __shfl_xor_sync(0xffffffff, mx1, 1));
        mx1 = fmaxf(mx1, __shfl_xor_sync(0xffffffff, mx1, 2));
        float mn0 = fmaxf(m_lo, mx0), mn1 = fmaxf(m_hi, mx1);
        float al0 = ex2f((m_lo - mn0) * SCL), al1 = ex2f((m_hi - mn1) * SCL);
        m_lo = mn0; m_hi = mn1;

        float s0 = 0.f, s1 = 0.f;
#pragma unroll
        for (int ng = 0; ng < 8; ng++) {
            sfr[ng][0] = ex2f((sfr[ng][0] - mn0) * SCL);
            sfr[ng][1] = ex2f((sfr[ng][1] - mn0) * SCL);
            sfr[ng][2] = ex2f((sfr[ng][2] - mn1) * SCL);
            sfr[ng][3] = ex2f((sfr[ng][3] - mn1) * SCL);
            s0 += sfr[ng][0] + sfr[ng][1];
            s1 += sfr[ng][2] + sfr[ng][3];
        }
        s0 += __shfl_xor_sync(0xffffffff, s0, 1);
        s0 += __shfl_xor_sync(0xffffffff, s0, 2);
        s1 += __shfl_xor_sync(0xffffffff, s1, 1);
        s1 += __shfl_xor_sync(0xffffffff, s1, 2);
        l_lo = l_lo * al0 + s0;
        l_hi = l_hi * al1 + s1;

#pragma unroll
        for (int ng = 0; ng < 8; ng++) {
            off_[ng][0] *= al0; off_[ng][1] *= al0;
            off_[ng][2] *= al1; off_[ng][3] *= al1;
        }

        uint32_t ph[4][4], pl[4][4];
#pragma unroll
        for (int kc = 0; kc < 4; kc++) {
            split2(sfr[2*kc][0],   sfr[2*kc][1],   ph[kc][0], pl[kc][0]);
            split2(sfr[2*kc][2],   sfr[2*kc][3],   ph[kc][1], pl[kc][1]);
            split2(sfr[2*kc+1][0], sfr[2*kc+1][1], ph[kc][2], pl[kc][2]);
            split2(sfr[2*kc+1][2], sfr[2*kc+1][3], ph[kc][3], pl[kc][3]);
        }

#pragma unroll
        for (int kc = 0; kc < 4; kc++) {
            uint32_t vf[4][4], wf[4][4];
#pragma unroll
            for (int dp = 0; dp < 4; dp++) {
                uint32_t ad = sb2 + (uint32_t)(2 * MATB +
                               (kc * 16 + a_r) * 144 + (dp * 16 + a_c) * 2);
                LDSM4T(vf[dp], ad);
                LDSM4T(wf[dp], ad + MATB);
            }
#pragma unroll
            for (int ng = 0; ng < 8; ng++)
                MMA_OP(off_[ng], ph[kc], (vf[ng >> 1] + (ng & 1) * 2));
#pragma unroll
            for (int ng = 0; ng < 8; ng++)
                MMA_OP(off_[ng], pl[kc], (vf[ng >> 1] + (ng & 1) * 2));
#pragma unroll
            for (int ng = 0; ng < 8; ng++)
                MMA_OP(off_[ng], ph[kc], (wf[ng >> 1] + (ng & 1) * 2));
        }

        __syncthreads();
        if (t + 2 < NT) {
            load_kv(t & 1, t + 2);
            asm volatile("cp.async.commit_group;");
        }
    }

    float inv0 = 1.f / l_lo, inv1 = 1.f / l_hi;
    int q0 = qt * 64 + w * 16 + (lane >> 2);
    int col = 2 * (lane & 3);
#pragma unroll
    for (int ng = 0; ng < 8; ng++) {
        int n0 = ng * 8 + col;
        if (q0 < SEQ) {
            uint32_t hi, lo;
            split2(off_[ng][0] * inv0, off_[ng][1] * inv0, hi, lo);
            *(uint32_t*)(oh + (bbase + q0) * ED + hoff + n0) = hi;
            *(uint32_t*)(ol + (bbase + q0) * ED + hoff + n0) = lo;
        }
        if (q0 + 8 < SEQ) {
            uint32_t hi, lo;
            split2(off_[ng][2] * inv1, off_[ng][3] * inv1, hi, lo);
            *(uint32_t*)(oh + (bbase + q0 + 8) * ED + hoff + n0) = hi;
            *(uint32_t*)(ol + (bbase + q0 + 8) * ED + hoff + n0) = lo;
        }
    }
}

// ---------------- launch ----------------
extern "C" void kernel_launch(void* const* d_in, const int* in_sizes, int n_in,
                              void* d_out, int out_size)
{
    const float* hs = (const float*)d_in[0];
    const float* Wq = (const float*)d_in[1];
    const float* bq = (const float*)d_in[2];
    const float* Wk = (const float*)d_in[3];
    const float* bk = (const float*)d_in[4];
    const float* Wv = (const float*)d_in[5];
    const float* bv = (const float*)d_in[6];
    const float* Wo = (const float*)d_in[7];
    const float* bo = (const float*)d_in[8];
    float* out = (float*)d_out;

    float *qb, *kb;
    cudaGetSymbolAddress((void**)&qb, g_q);
    cudaGetSymbolAddress((void**)&kb, g_k);
    __nv_bfloat16 *hsh, *hsl, *oh, *ol, *wh, *wl;
    __nv_bfloat16 *qhp, *qlp, *khp, *klp, *vhp, *vlp;
    cudaGetSymbolAddress((void**)&hsh, g_hsh);
    cudaGetSymbolAddress((void**)&hsl, g_hsl);
    cudaGetSymbolAddress((void**)&oh, g_oh);
    cudaGetSymbolAddress((void**)&ol, g_ol);
    cudaGetSymbolAddress((void**)&wh, g_wh);
    cudaGetSymbolAddress((void**)&wl, g_wl);
    cudaGetSymbolAddress((void**)&qhp, g_qh);
    cudaGetSymbolAddress((void**)&qlp, g_ql);
    cudaGetSymbolAddress((void**)&khp, g_kh);
    cudaGetSymbolAddress((void**)&klp, g_kl);
    cudaGetSymbolAddress((void**)&vhp, g_vh);
    cudaGetSymbolAddress((void**)&vlp, g_vl);

    cudaFuncSetAttribute(gemm_bf16_split<0>,
                         cudaFuncAttributeMaxDynamicSharedMemorySize, GSMEM);
    cudaFuncSetAttribute(gemm_bf16_split<1>,
                         cudaFuncAttributeMaxDynamicSharedMemorySize, GSMEM);
    cudaFuncSetAttribute(attn_mma,
                         cudaFuncAttributeMaxDynamicSharedMemorySize, ATT_SMEM);

    const size_t WSZ = (size_t)ED * ED;
    const int n4_hs = MROWS * ED / 4;
    const int n4_w  = ED * ED / 4;

    cvt_split_kernel<<<(n4_hs + 255) / 256, 256>>>(hs, hsh, hsl, n4_hs);
    cvt_split4_kernel<<<(4 * n4_w + 255) / 256, 256>>>(Wq, Wk, Wv, Wo, wh, wl, n4_w);

    dim3 ggrid(ED / BN, (MROWS + BM - 1) / BM);   // (8, 73)

    gemm_bf16_split<0><<<ggrid, 128, GSMEM>>>(hsh, hsl, wh + 0*WSZ, wl + 0*WSZ, bq,
                                              qb, nullptr, nullptr, MROWS);
    gemm_bf16_split<0><<<ggrid, 128, GSMEM>>>(hsh, hsl, wh + 1*WSZ, wl + 1*WSZ, bk,
                                              kb, nullptr, nullptr, MROWS);
    gemm_bf16_split<1><<<ggrid, 128, GSMEM>>>(hsh, hsl, wh + 2*WSZ, wl + 2*WSZ, bv,
                                              nullptr, vhp, vlp, MROWS);

    int rt = BATCH * SEQ * NH * 32;
    rope_split_kernel<<<(rt + 255) / 256, 256>>>(qb, kb, qhp, qlp, khp, klp);

    attn_mma<<<dim3(QT, NH, BATCH), 128, ATT_SMEM>>>(qhp, qlp, khp, klp, vhp, vlp, oh, ol);

    gemm_bf16_split<0><<<ggrid, 128, GSMEM>>>(oh, ol, wh + 3*WSZ, wl + 3*WSZ, bo,
                                              out, nullptr, nullptr, MROWS);
}

// round 8
// speedup vs baseline: 4.8080x; 1.0179x over previous
#include <cuda_runtime.h>
#include <cuda_bf16.h>
#include <cstdint>
#include <math.h>

#define ED   1024
#define NH   16
#define HD   64
#define SEQ  577
#define BATCH 16
#define MROWS (BATCH * SEQ)   // 9232
#define NT   10
#define QT   10

// ---------------- scratch ----------------
__device__ __nv_bfloat16 g_hsh[(size_t)MROWS * ED];
__device__ __nv_bfloat16 g_hsl[(size_t)MROWS * ED];
__device__ __nv_bfloat16 g_oh[(size_t)MROWS * ED];
__device__ __nv_bfloat16 g_ol[(size_t)MROWS * ED];
__device__ __nv_bfloat16 g_wh[4][(size_t)ED * ED];
__device__ __nv_bfloat16 g_wl[4][(size_t)ED * ED];
__device__ __nv_bfloat16 g_qh[(size_t)MROWS * ED];
__device__ __nv_bfloat16 g_ql[(size_t)MROWS * ED];
__device__ __nv_bfloat16 g_kh[(size_t)MROWS * ED];
__device__ __nv_bfloat16 g_kl[(size_t)MROWS * ED];
__device__ __nv_bfloat16 g_vh[(size_t)MROWS * ED];
__device__ __nv_bfloat16 g_vl[(size_t)MROWS * ED];

// ---------------- helpers ----------------
__device__ __forceinline__ float ex2f(float x) {
    float r;
    asm("ex2.approx.ftz.f32 %0, %1;" : "=f"(r) : "f"(x));
    return r;
}
__device__ __forceinline__ uint32_t packbf2(__nv_bfloat16 a, __nv_bfloat16 b) {
    __nv_bfloat162 v = __halves2bfloat162(a, b);
    return *(uint32_t*)&v;
}
__device__ __forceinline__ void split2(float a, float b, uint32_t& hi, uint32_t& lo) {
    __nv_bfloat16 ha = __float2bfloat16(a), hb = __float2bfloat16(b);
    __nv_bfloat16 la = __float2bfloat16(a - __bfloat162float(ha));
    __nv_bfloat16 lb = __float2bfloat16(b - __bfloat162float(hb));
    hi = packbf2(ha, hb);
    lo = packbf2(la, lb);
}

// ---------------- fp32 -> bf16 hi/lo split ----------------
__global__ void cvt_split_kernel(const float* __restrict__ x,
                                 __nv_bfloat16* __restrict__ h,
                                 __nv_bfloat16* __restrict__ l, int n4)
{
    int i = blockIdx.x * blockDim.x + threadIdx.x;
    if (i >= n4) return;
    float4 v = ((const float4*)x)[i];
    uint32_t h01, l01, h23, l23;
    split2(v.x, v.y, h01, l01);
    split2(v.z, v.w, h23, l23);
    ((uint32_t*)h)[2*i]   = h01;
    ((uint32_t*)h)[2*i+1] = h23;
    ((uint32_t*)l)[2*i]   = l01;
    ((uint32_t*)l)[2*i+1] = l23;
}

__global__ void cvt_split4_kernel(const float* __restrict__ w0, const float* __restrict__ w1,
                                  const float* __restrict__ w2, const float* __restrict__ w3,
                                  __nv_bfloat16* __restrict__ wh, __nv_bfloat16* __restrict__ wl,
                                  int n4_per)
{
    int i = blockIdx.x * blockDim.x + threadIdx.x;
    if (i >= 4 * n4_per) return;
    int sel = i / n4_per;
    int rem = i - sel * n4_per;
    const float* src = (sel == 0) ? w0 : (sel == 1) ? w1 : (sel == 2) ? w2 : w3;
    size_t base = (size_t)sel * (size_t)ED * ED;
    float4 v = ((const float4*)src)[rem];
    uint32_t h01, l01, h23, l23;
    split2(v.x, v.y, h01, l01);
    split2(v.z, v.w, h23, l23);
    ((uint32_t*)(wh + base))[2*rem]   = h01;
    ((uint32_t*)(wh + base))[2*rem+1] = h23;
    ((uint32_t*)(wl + base))[2*rem]   = l01;
    ((uint32_t*)(wl + base))[2*rem+1] = l23;
}

// ---------------- MMA / ldmatrix / cp.async primitives ----------------
#define MMA_OP(d, a, b) asm volatile( \
    "mma.sync.aligned.m16n8k16.row.col.f32.bf16.bf16.f32 " \
    "{%0,%1,%2,%3},{%4,%5,%6,%7},{%8,%9},{%0,%1,%2,%3};" \
    : "+f"(d[0]), "+f"(d[1]), "+f"(d[2]), "+f"(d[3]) \
    : "r"(a[0]), "r"(a[1]), "r"(a[2]), "r"(a[3]), "r"(b[0]), "r"(b[1]))

#define LDSM4(r, addr) asm volatile( \
    "ldmatrix.sync.aligned.m8n8.x4.shared.b16 {%0,%1,%2,%3}, [%4];" \
    : "=r"(r[0]), "=r"(r[1]), "=r"(r[2]), "=r"(r[3]) : "r"(addr))

#define LDSM4T(r, addr) asm volatile( \
    "ldmatrix.sync.aligned.m8n8.x4.trans.shared.b16 {%0,%1,%2,%3}, [%4];" \
    : "=r"(r[0]), "=r"(r[1]), "=r"(r[2]), "=r"(r[3]) : "r"(addr))

__device__ __forceinline__ void cp16(uint32_t dst, const void* src, bool pred) {
    int sz = pred ? 16 : 0;
    asm volatile("cp.async.cg.shared.global [%0], [%1], 16, %2;\n"
                 :: "r"(dst), "l"(src), "r"(sz));
}

// ---------------- split-bf16 GEMM, 64x64 warp tiles, A-streamed ----------------
// C[m][n] = sum_k A[m][k]*W[n][k] + bias[n]
// BM=128, BN=128, 4 warps, BK=32, 2-stage.
// MODE 0: float C. MODE 1: split bf16 (Ch, Cl). MODE 2: split + 2D-RoPE.
#define BM 128
#define BN 128
#define BK 32
#define SAST 40
#define HL_ELEMS (128 * SAST)
#define HL_B     (HL_ELEMS * 2)        // 10240 bytes
#define STG_B    (4 * HL_B)            // 40960 bytes
#define GSMEM    (2 * STG_B)           // 81920 bytes
#define ROPE_LC  (13.287712379549449f / 16.f)   // ln2(10000)/16

template <int MODE>
__global__ __launch_bounds__(128) void gemm_bf16_split(
    const __nv_bfloat16* __restrict__ Ah, const __nv_bfloat16* __restrict__ Al,
    const __nv_bfloat16* __restrict__ Wh, const __nv_bfloat16* __restrict__ Wl,
    const float* __restrict__ bias, float* __restrict__ C,
    __nv_bfloat16* __restrict__ Ch, __nv_bfloat16* __restrict__ Cl, int M)
{
    extern __shared__ __align__(16) char smem[];
    const uint32_t sbase = (uint32_t)__cvta_generic_to_shared(smem);

    const int tid  = threadIdx.x;
    const int lane = tid & 31;
    const int wid  = tid >> 5;
    const int wm   = wid & 1;
    const int wn   = wid >> 1;
    const int bm   = blockIdx.y * BM;
    const int bn   = blockIdx.x * BN;

    const int a_r = (lane & 7) + ((lane >> 3) & 1) * 8;
    const int a_c = ((lane >> 4) & 1) * 8;
    const int g   = lane >> 3;
    const int b_r = (lane & 7) + (g >> 1) * 8;
    const int b_c = (g & 1) * 8;

    uint32_t aoff[4], boff[4];
#pragma unroll
    for (int i = 0; i < 4; i++)
        aoff[i] = (uint32_t)(((wm * 64 + i * 16 + a_r) * SAST + a_c) * 2);
#pragma unroll
    for (int j = 0; j < 4; j++)
        boff[j] = (uint32_t)(2 * HL_B + ((wn * 64 + j * 16 + b_r) * SAST + b_c) * 2);

    float c[4][8][4];
#pragma unroll
    for (int i = 0; i < 4; i++)
#pragma unroll
        for (int j = 0; j < 8; j++)
#pragma unroll
            for (int r = 0; r < 4; r++) c[i][j][r] = 0.f;

    auto load_stage = [&](int s, int kt) {
        int k0 = kt * BK;
        uint32_t stb = sbase + (uint32_t)(s * STG_B);
#pragma unroll
        for (int i = 0; i < 16; i++) {
            int idx = tid + 128 * i;
            if (idx < 1024) {
                int hl = idx >> 9, rem = idx & 511;
                int row = rem >> 2, seg = rem & 3;
                const __nv_bfloat16* src =
                    (hl ? Al : Ah) + (size_t)(bm + row) * ED + k0 + seg * 8;
                cp16(stb + (uint32_t)(hl * HL_B + (row * SAST + seg * 8) * 2),
                     src, (bm + row) < M);
            } else {
                int j = idx - 1024;
                int hl = j >> 9, rem = j & 511;
                int row = rem >> 2, seg = rem & 3;
                const __nv_bfloat16* src =
                    (hl ? Wl : Wh) + (size_t)(bn + row) * ED + k0 + seg * 8;
                cp16(stb + (uint32_t)(2 * HL_B + hl * HL_B + (row * SAST + seg * 8) * 2),
                     src, true);
            }
        }
    };

    const int NK = ED / BK;  // 32
    load_stage(0, 0);
    asm volatile("cp.async.commit_group;");
    load_stage(1, 1);
    asm volatile("cp.async.commit_group;");

    for (int ks = 0; ks < NK; ks++) {
        if (ks < NK - 1) { asm volatile("cp.async.wait_group 1;"); }
        else             { asm volatile("cp.async.wait_group 0;"); }
        __syncthreads();

        const uint32_t sa = sbase + (uint32_t)((ks & 1) * STG_B);

        uint32_t ah[2][4], al[2][4];        // A double buffer (i-stream)
        uint32_t bh[4][4], bl[4][4];        // all B for current half-K

        // B for h=0
#pragma unroll
        for (int j = 0; j < 4; j++) {
            LDSM4(bh[j], sa + boff[j]);
            LDSM4(bl[j], sa + (uint32_t)HL_B + boff[j]);
        }
        // A i=0, h=0
        LDSM4(ah[0], sa + aoff[0]);
        LDSM4(al[0], sa + (uint32_t)HL_B + aoff[0]);

#pragma unroll
        for (int h = 0; h < 2; h++) {
            if (h == 1) {
#pragma unroll
                for (int j = 0; j < 4; j++) {
                    LDSM4(bh[j], sa + boff[j] + 32);
                    LDSM4(bl[j], sa + (uint32_t)HL_B + boff[j] + 32);
                }
            }
#pragma unroll
            for (int i = 0; i < 4; i++) {
                const int step = h * 4 + i;
                const int cur = step & 1, nxt = cur ^ 1;
                if (step < 7) {
                    const int i2 = (step + 1) & 3;
                    const uint32_t hofs = ((step + 1) >> 2) * 32;
                    LDSM4(ah[nxt], sa + aoff[i2] + hofs);
                    LDSM4(al[nxt], sa + (uint32_t)HL_B + aoff[i2] + hofs);
                }
#pragma unroll
                for (int jj = 0; jj < 4; jj++) {
                    MMA_OP(c[i][2*jj],   ah[cur], (bh[jj] + 0));
                    MMA_OP(c[i][2*jj+1], ah[cur], (bh[jj] + 2));
                }
#pragma unroll
                for (int jj = 0; jj < 4; jj++) {
                    MMA_OP(c[i][2*jj],   ah[cur], (bl[jj] + 0));
                    MMA_OP(c[i][2*jj+1], ah[cur], (bl[jj] + 2));
                }
#pragma unroll
                for (int jj = 0; jj < 4; jj++) {
                    MMA_OP(c[i][2*jj],   al[cur], (bh[jj] + 0));
                    MMA_OP(c[i][2*jj+1], al[cur], (bh[jj] + 2));
                }
            }
        }

        __syncthreads();
        if (ks + 2 < NK) {
            load_stage(ks & 1, ks + 2);
            asm volatile("cp.async.commit_group;");
        }
    }

    // ---------------- epilogue ----------------
    if (MODE == 2) {
        // fused 2D-RoPE + split. Warp's 64 cols = one head; col d pairs with
        // d+32 as fragment jn <-> jn+4 (same thread, same r).
        float invf[2][2];
#pragma unroll
        for (int jp = 0; jp < 2; jp++)
#pragma unroll
            for (int t = 0; t < 2; t++)
                invf[jp][t] = ex2f(-(float)(jp * 8 + (lane & 3) * 2 + t) * ROPE_LC);

#pragma unroll
        for (int i = 0; i < 4; i++) {
            int row0 = bm + wm * 64 + i * 16 + (lane >> 2);
#pragma unroll
            for (int half = 0; half < 2; half++) {
                int row = row0 + half * 8;
                if (row >= M) continue;
                int pr = row % SEQ;
                bool rot = pr > 0;
                float snh[2][2], csh[2][2], snw[2][2], csw[2][2];
                if (rot) {
                    int p = pr - 1;
                    float fgh = (float)(p / 24), fgw = (float)(p % 24);
#pragma unroll
                    for (int jp = 0; jp < 2; jp++)
#pragma unroll
                        for (int t = 0; t < 2; t++) {
                            __sincosf(fgh * invf[jp][t], &snh[jp][t], &csh[jp][t]);
                            __sincosf(fgw * invf[jp][t], &snw[jp][t], &csw[jp][t]);
                        }
                }
#pragma unroll
                for (int jn = 0; jn < 4; jn++) {
                    int n0 = bn + wn * 64 + jn * 8 + (lane & 3) * 2;
                    int jp = jn & 1;
                    float x1[2], x2[2];
#pragma unroll
                    for (int t = 0; t < 2; t++) {
                        float a = c[i][jn][half*2 + t]     + bias[n0 + t];
                        float b = c[i][jn+4][half*2 + t]   + bias[n0 + 32 + t];
                        if (rot) {
                            float na = a * csh[jp][t] - b * snh[jp][t];
                            float nb = b * csw[jp][t] + a * snw[jp][t];
                            a = na; b = nb;
                        }
                        x1[t] = a; x2[t] = b;
                    }
                    uint32_t hi, lo;
                    split2(x1[0], x1[1], hi, lo);
                    *(uint32_t*)(Ch + (size_t)row * ED + n0) = hi;
                    *(uint32_t*)(Cl + (size_t)row * ED + n0) = lo;
                    split2(x2[0], x2[1], hi, lo);
                    *(uint32_t*)(Ch + (size_t)row * ED + n0 + 32) = hi;
                    *(uint32_t*)(Cl + (size_t)row * ED + n0 + 32) = lo;
                }
            }
        }
    } else {
#pragma unroll
        for (int i = 0; i < 4; i++) {
            int m0 = bm + wm * 64 + i * 16 + (lane >> 2);
#pragma unroll
            for (int jn = 0; jn < 8; jn++) {
                int n0 = bn + wn * 64 + jn * 8 + (lane & 3) * 2;
                float bx = bias[n0], by = bias[n0 + 1];
                if (MODE == 1) {
                    if (m0 < M) {
                        uint32_t hi, lo;
                        split2(c[i][jn][0] + bx, c[i][jn][1] + by, hi, lo);
                        *(uint32_t*)(Ch + (size_t)m0 * ED + n0) = hi;
                        *(uint32_t*)(Cl + (size_t)m0 * ED + n0) = lo;
                    }
                    if (m0 + 8 < M) {
                        uint32_t hi, lo;
                        split2(c[i][jn][2] + bx, c[i][jn][3] + by, hi, lo);
                        *(uint32_t*)(Ch + (size_t)(m0 + 8) * ED + n0) = hi;
                        *(uint32_t*)(Cl + (size_t)(m0 + 8) * ED + n0) = lo;
                    }
                } else {
                    if (m0 < M) {
                        float2 v = make_float2(c[i][jn][0] + bx, c[i][jn][1] + by);
                        *(float2*)&C[(size_t)m0 * ED + n0] = v;
                    }
                    if (m0 + 8 < M) {
                        float2 v = make_float2(c[i][jn][2] + bx, c[i][jn][3] + by);
                        *(float2*)&C[(size_t)(m0 + 8) * ED + n0] = v;
                    }
                }
            }
        }
    }
}

// ---------------- tensor-core flash attention ----------------
#define TSTR 72
#define MATB (64 * TSTR * 2)
#define STGB (4 * MATB)
#define ATT_SMEM (2 * STGB)

__global__ __launch_bounds__(128) void attn_mma(
    const __nv_bfloat16* __restrict__ qh, const __nv_bfloat16* __restrict__ ql,
    const __nv_bfloat16* __restrict__ kh, const __nv_bfloat16* __restrict__ kl,
    const __nv_bfloat16* __restrict__ vh, const __nv_bfloat16* __restrict__ vl,
    __nv_bfloat16* __restrict__ oh, __nv_bfloat16* __restrict__ ol)
{
    extern __shared__ __align__(16) __nv_bfloat16 asmem[];
    const uint32_t sbase = (uint32_t)__cvta_generic_to_shared(asmem);

    const int tid  = threadIdx.x;
    const int lane = tid & 31;
    const int w    = tid >> 5;
    const int b    = blockIdx.z;
    const int h    = blockIdx.y;
    const int qt   = blockIdx.x;
    const size_t hoff = (size_t)h * HD;
    const size_t bbase = (size_t)b * SEQ;

    const int a_r = (lane & 7) + ((lane >> 3) & 1) * 8;
    const int a_c = ((lane >> 4) & 1) * 8;
    const int g   = lane >> 3;
    const int b_r = (lane & 7) + (g >> 1) * 8;
    const int b_c = (g & 1) * 8;

    for (int c = tid; c < 1024; c += 128) {
        int mat = c >> 9, row = (c >> 3) & 63, seg = c & 7;
        int qrow = qt * 64 + row;
        if (qrow >= SEQ) qrow = SEQ - 1;
        const __nv_bfloat16* src = (mat ? ql : qh) + (bbase + qrow) * ED + hoff + seg * 8;
        cp16(sbase + mat * MATB + row * 144 + seg * 16, src, true);
    }
    asm volatile("cp.async.commit_group;");
    asm volatile("cp.async.wait_group 0;");
    __syncthreads();

    uint32_t qhf[4][4], qlf[4][4];
#pragma unroll
    for (int kc = 0; kc < 4; kc++) {
        uint32_t base0 = sbase + (uint32_t)((w * 16 + a_r) * 144 + (kc * 16 + a_c) * 2);
        LDSM4(qhf[kc], base0);
        LDSM4(qlf[kc], base0 + MATB);
    }
    __syncthreads();

    auto load_kv = [&](int s, int t) {
        const __nv_bfloat16* mats[4] = {kh, kl, vh, vl};
        for (int c = tid; c < 2048; c += 128) {
            int mat = c >> 9, row = (c >> 3) & 63, seg = c & 7;
            int kr = t * 64 + row;
            int krc = (kr < SEQ) ? kr : 0;
            const __nv_bfloat16* src = mats[mat] + (bbase + krc) * ED + hoff + seg * 8;
            cp16(sbase + s * STGB + mat * MATB + row * 144 + seg * 16, src, kr < SEQ);
        }
    };
    load_kv(0, 0);
    asm volatile("cp.async.commit_group;");
    load_kv(1, 1);
    asm volatile("cp.async.commit_group;");

    float off_[8][4];
#pragma unroll
    for (int ng = 0; ng < 8; ng++)
#pragma unroll
        for (int r = 0; r < 4; r++) off_[ng][r] = 0.f;
    float m_lo = -1e30f, m_hi = -1e30f, l_lo = 0.f, l_hi = 0.f;

    const float SCL = 0.18033688011112042f;

    for (int t = 0; t < NT; t++) {
        if (t < NT - 1) { asm volatile("cp.async.wait_group 1;"); }
        else            { asm volatile("cp.async.wait_group 0;"); }
        __syncthreads();
        const uint32_t sb2 = sbase + (uint32_t)((t & 1) * STGB);

        float sfr[8][4];
#pragma unroll
        for (int ng = 0; ng < 8; ng++)
#pragma unroll
            for (int r = 0; r < 4; r++) sfr[ng][r] = 0.f;

#pragma unroll
        for (int kc = 0; kc < 4; kc++) {
            uint32_t kf[4][4], lf[4][4];
#pragma unroll
            for (int pp = 0; pp < 4; pp++) {
                uint32_t ad = sb2 + (uint32_t)((pp * 16 + b_r) * 144 + (kc * 16 + b_c) * 2);
                LDSM4(kf[pp], ad);
                LDSM4(lf[pp], ad + MATB);
            }
#pragma unroll
            for (int ng = 0; ng < 8; ng++)
                MMA_OP(sfr[ng], qhf[kc], (kf[ng >> 1] + (ng & 1) * 2));
#pragma unroll
            for (int ng = 0; ng < 8; ng++)
                MMA_OP(sfr[ng], qhf[kc], (lf[ng >> 1] + (ng & 1) * 2));
#pragma unroll
            for (int ng = 0; ng < 8; ng++)
                MMA_OP(sfr[ng], qlf[kc], (kf[ng >> 1] + (ng & 1) * 2));
        }

        if (t * 64 + 64 > SEQ) {
            int tig2 = 2 * (lane & 3);
#pragma unroll
            for (int ng = 0; ng < 8; ng++) {
                int key0 = t * 64 + ng * 8 + tig2;
                if (key0     >= SEQ) { sfr[ng][0] = -1e30f; sfr[ng][2] = -1e30f; }
                if (key0 + 1 >= SEQ) { sfr[ng][1] = -1e30f; sfr[ng][3] = -1e30f; }
            }
        }

        float mx0 = -1e30f, mx1 = -1e30f;
#pragma unroll
        for (int ng = 0; ng < 8; ng++) {
            mx0 = fmaxf(mx0, fmaxf(sfr[ng][0], sfr[ng][1]));
            mx1 = fmaxf(mx1, fmaxf(sfr[ng][2], sfr[ng][3]));
        }
        mx0 = fmaxf(mx0, __shfl_xor_sync(0xffffffff, mx0, 1));
        mx0 = fmaxf(mx0, __shfl_xor_sync(0xffffffff, mx0, 2));
        mx1 = fmaxf(mx1, __shfl_xor_sync(0xffffffff, mx1, 1));
        mx1 = fmaxf(mx1, __shfl_xor_sync(0xffffffff, mx1, 2));
        float mn0 = fmaxf(m_lo, mx0), mn1 = fmaxf(m_hi, mx1);
        float al0 = ex2f((m_lo - mn0) * SCL), al1 = ex2f((m_hi - mn1) * SCL);
        m_lo = mn0; m_hi = mn1;

        float s0 = 0.f, s1 = 0.f;
#pragma unroll
        for (int ng = 0; ng < 8; ng++) {
            sfr[ng][0] = ex2f((sfr[ng][0] - mn0) * SCL);
            sfr[ng][1] = ex2f((sfr[ng][1] - mn0) * SCL);
            sfr[ng][2] = ex2f((sfr[ng][2] - mn1) * SCL);
            sfr[ng][3] = ex2f((sfr[ng][3] - mn1) * SCL);
            s0 += sfr[ng][0] + sfr[ng][1];
            s1 += sfr[ng][2] + sfr[ng][3];
        }
        s0 += __shfl_xor_sync(0xffffffff, s0, 1);
        s0 += __shfl_xor_sync(0xffffffff, s0, 2);
        s1 += __shfl_xor_sync(0xffffffff, s1, 1);
        s1 += __shfl_xor_sync(0xffffffff, s1, 2);
        l_lo = l_lo * al0 + s0;
        l_hi = l_hi * al1 + s1;

#pragma unroll
        for (int ng = 0; ng < 8; ng++) {
            off_[ng][0] *= al0; off_[ng][1] *= al0;
            off_[ng][2] *= al1; off_[ng][3] *= al1;
        }

        uint32_t ph[4][4], pl[4][4];
#pragma unroll
        for (int kc = 0; kc < 4; kc++) {
            split2(sfr[2*kc][0],   sfr[2*kc][1],   ph[kc][0], pl[kc][0]);
            split2(sfr[2*kc][2],   sfr[2*kc][3],   ph[kc][1], pl[kc][1]);
            split2(sfr[2*kc+1][0], sfr[2*kc+1][1], ph[kc][2], pl[kc][2]);
            split2(sfr[2*kc+1][2], sfr[2*kc+1][3], ph[kc][3], pl[kc][3]);
        }

#pragma unroll
        for (int kc = 0; kc < 4; kc++) {
            uint32_t vf[4][4], wf[4][4];
#pragma unroll
            for (int dp = 0; dp < 4; dp++) {
                uint32_t ad = sb2 + (uint32_t)(2 * MATB +
                               (kc * 16 + a_r) * 144 + (dp * 16 + a_c) * 2);
                LDSM4T(vf[dp], ad);
                LDSM4T(wf[dp], ad + MATB);
            }
#pragma unroll
            for (int ng = 0; ng < 8; ng++)
                MMA_OP(off_[ng], ph[kc], (vf[ng >> 1] + (ng & 1) * 2));
#pragma unroll
            for (int ng = 0; ng < 8; ng++)
                MMA_OP(off_[ng], pl[kc], (vf[ng >> 1] + (ng & 1) * 2));
#pragma unroll
            for (int ng = 0; ng < 8; ng++)
                MMA_OP(off_[ng], ph[kc], (wf[ng >> 1] + (ng & 1) * 2));
        }

        __syncthreads();
        if (t + 2 < NT) {
            load_kv(t & 1, t + 2);
            asm volatile("cp.async.commit_group;");
        }
    }

    float inv0 = 1.f / l_lo, inv1 = 1.f / l_hi;
    int q0 = qt * 64 + w * 16 + (lane >> 2);
    int col = 2 * (lane & 3);
#pragma unroll
    for (int ng = 0; ng < 8; ng++) {
        int n0 = ng * 8 + col;
        if (q0 < SEQ) {
            uint32_t hi, lo;
            split2(off_[ng][0] * inv0, off_[ng][1] * inv0, hi, lo);
            *(uint32_t*)(oh + (bbase + q0) * ED + hoff + n0) = hi;
            *(uint32_t*)(ol + (bbase + q0) * ED + hoff + n0) = lo;
        }
        if (q0 + 8 < SEQ) {
            uint32_t hi, lo;
            split2(off_[ng][2] * inv1, off_[ng][3] * inv1, hi, lo);
            *(uint32_t*)(oh + (bbase + q0 + 8) * ED + hoff + n0) = hi;
            *(uint32_t*)(ol + (bbase + q0 + 8) * ED + hoff + n0) = lo;
        }
    }
}

// ---------------- launch ----------------
extern "C" void kernel_launch(void* const* d_in, const int* in_sizes, int n_in,
                              void* d_out, int out_size)
{
    const float* hs = (const float*)d_in[0];
    const float* Wq = (const float*)d_in[1];
    const float* bq = (const float*)d_in[2];
    const float* Wk = (const float*)d_in[3];
    const float* bk = (const float*)d_in[4];
    const float* Wv = (const float*)d_in[5];
    const float* bv = (const float*)d_in[6];
    const float* Wo = (const float*)d_in[7];
    const float* bo = (const float*)d_in[8];
    float* out = (float*)d_out;

    __nv_bfloat16 *hsh, *hsl, *oh, *ol, *wh, *wl;
    __nv_bfloat16 *qhp, *qlp, *khp, *klp, *vhp, *vlp;
    cudaGetSymbolAddress((void**)&hsh, g_hsh);
    cudaGetSymbolAddress((void**)&hsl, g_hsl);
    cudaGetSymbolAddress((void**)&oh, g_oh);
    cudaGetSymbolAddress((void**)&ol, g_ol);
    cudaGetSymbolAddress((void**)&wh, g_wh);
    cudaGetSymbolAddress((void**)&wl, g_wl);
    cudaGetSymbolAddress((void**)&qhp, g_qh);
    cudaGetSymbolAddress((void**)&qlp, g_ql);
    cudaGetSymbolAddress((void**)&khp, g_kh);
    cudaGetSymbolAddress((void**)&klp, g_kl);
    cudaGetSymbolAddress((void**)&vhp, g_vh);
    cudaGetSymbolAddress((void**)&vlp, g_vl);

    cudaFuncSetAttribute(gemm_bf16_split<0>,
                         cudaFuncAttributeMaxDynamicSharedMemorySize, GSMEM);
    cudaFuncSetAttribute(gemm_bf16_split<1>,
                         cudaFuncAttributeMaxDynamicSharedMemorySize, GSMEM);
    cudaFuncSetAttribute(gemm_bf16_split<2>,
                         cudaFuncAttributeMaxDynamicSharedMemorySize, GSMEM);
    cudaFuncSetAttribute(attn_mma,
                         cudaFuncAttributeMaxDynamicSharedMemorySize, ATT_SMEM);

    const size_t WSZ = (size_t)ED * ED;
    const int n4_hs = MROWS * ED / 4;
    const int n4_w  = ED * ED / 4;

    cvt_split_kernel<<<(n4_hs + 255) / 256, 256>>>(hs, hsh, hsl, n4_hs);
    cvt_split4_kernel<<<(4 * n4_w + 255) / 256, 256>>>(Wq, Wk, Wv, Wo, wh, wl, n4_w);

    dim3 ggrid(ED / BN, (MROWS + BM - 1) / BM);   // (8, 73)

    gemm_bf16_split<2><<<ggrid, 128, GSMEM>>>(hsh, hsl, wh + 0*WSZ, wl + 0*WSZ, bq,
                                              nullptr, qhp, qlp, MROWS);
    gemm_bf16_split<2><<<ggrid, 128, GSMEM>>>(hsh, hsl, wh + 1*WSZ, wl + 1*WSZ, bk,
                                              nullptr, khp, klp, MROWS);
    gemm_bf16_split<1><<<ggrid, 128, GSMEM>>>(hsh, hsl, wh + 2*WSZ, wl + 2*WSZ, bv,
                                              nullptr, vhp, vlp, MROWS);

    attn_mma<<<dim3(QT, NH, BATCH), 128, ATT_SMEM>>>(qhp, qlp, khp, klp, vhp, vlp, oh, ol);

    gemm_bf16_split<0><<<ggrid, 128, GSMEM>>>(oh, ol, wh + 3*WSZ, wl + 3*WSZ, bo,
                                              out, nullptr, nullptr, MROWS);
}

// round 9
// speedup vs baseline: 4.9330x; 1.0260x over previous
#include <cuda_runtime.h>
#include <cuda_bf16.h>
#include <cstdint>
#include <math.h>

#define ED   1024
#define NH   16
#define HD   64
#define SEQ  577
#define BATCH 16
#define MROWS (BATCH * SEQ)   // 9232
#define NT   10
#define QT   10

// ---------------- scratch ----------------
__device__ __nv_bfloat16 g_hsh[(size_t)MROWS * ED];
__device__ __nv_bfloat16 g_hsl[(size_t)MROWS * ED];
__device__ __nv_bfloat16 g_oh[(size_t)MROWS * ED];
__device__ __nv_bfloat16 g_ol[(size_t)MROWS * ED];
__device__ __nv_bfloat16 g_wh[4][(size_t)ED * ED];
__device__ __nv_bfloat16 g_wl[4][(size_t)ED * ED];
__device__ __nv_bfloat16 g_qh[(size_t)MROWS * ED];
__device__ __nv_bfloat16 g_ql[(size_t)MROWS * ED];
__device__ __nv_bfloat16 g_kh[(size_t)MROWS * ED];
__device__ __nv_bfloat16 g_kl[(size_t)MROWS * ED];
__device__ __nv_bfloat16 g_vh[(size_t)MROWS * ED];
__device__ __nv_bfloat16 g_vl[(size_t)MROWS * ED];

// ---------------- helpers ----------------
__device__ __forceinline__ float ex2f(float x) {
    float r;
    asm("ex2.approx.ftz.f32 %0, %1;" : "=f"(r) : "f"(x));
    return r;
}
__device__ __forceinline__ uint32_t packbf2(__nv_bfloat16 a, __nv_bfloat16 b) {
    __nv_bfloat162 v = __halves2bfloat162(a, b);
    return *(uint32_t*)&v;
}
__device__ __forceinline__ void split2(float a, float b, uint32_t& hi, uint32_t& lo) {
    __nv_bfloat16 ha = __float2bfloat16(a), hb = __float2bfloat16(b);
    __nv_bfloat16 la = __float2bfloat16(a - __bfloat162float(ha));
    __nv_bfloat16 lb = __float2bfloat16(b - __bfloat162float(hb));
    hi = packbf2(ha, hb);
    lo = packbf2(la, lb);
}

// ---------------- fp32 -> bf16 hi/lo split ----------------
__global__ void cvt_split_kernel(const float* __restrict__ x,
                                 __nv_bfloat16* __restrict__ h,
                                 __nv_bfloat16* __restrict__ l, int n4)
{
    int i = blockIdx.x * blockDim.x + threadIdx.x;
    if (i >= n4) return;
    float4 v = ((const float4*)x)[i];
    uint32_t h01, l01, h23, l23;
    split2(v.x, v.y, h01, l01);
    split2(v.z, v.w, h23, l23);
    ((uint32_t*)h)[2*i]   = h01;
    ((uint32_t*)h)[2*i+1] = h23;
    ((uint32_t*)l)[2*i]   = l01;
    ((uint32_t*)l)[2*i+1] = l23;
}

__global__ void cvt_split4_kernel(const float* __restrict__ w0, const float* __restrict__ w1,
                                  const float* __restrict__ w2, const float* __restrict__ w3,
                                  __nv_bfloat16* __restrict__ wh, __nv_bfloat16* __restrict__ wl,
                                  int n4_per)
{
    int i = blockIdx.x * blockDim.x + threadIdx.x;
    if (i >= 4 * n4_per) return;
    int sel = i / n4_per;
    int rem = i - sel * n4_per;
    const float* src = (sel == 0) ? w0 : (sel == 1) ? w1 : (sel == 2) ? w2 : w3;
    size_t base = (size_t)sel * (size_t)ED * ED;
    float4 v = ((const float4*)src)[rem];
    uint32_t h01, l01, h23, l23;
    split2(v.x, v.y, h01, l01);
    split2(v.z, v.w, h23, l23);
    ((uint32_t*)(wh + base))[2*rem]   = h01;
    ((uint32_t*)(wh + base))[2*rem+1] = h23;
    ((uint32_t*)(wl + base))[2*rem]   = l01;
    ((uint32_t*)(wl + base))[2*rem+1] = l23;
}

// ---------------- MMA / ldmatrix / cp.async primitives ----------------
#define MMA_OP(d, a, b) asm volatile( \
    "mma.sync.aligned.m16n8k16.row.col.f32.bf16.bf16.f32 " \
    "{%0,%1,%2,%3},{%4,%5,%6,%7},{%8,%9},{%0,%1,%2,%3};" \
    : "+f"(d[0]), "+f"(d[1]), "+f"(d[2]), "+f"(d[3]) \
    : "r"(a[0]), "r"(a[1]), "r"(a[2]), "r"(a[3]), "r"(b[0]), "r"(b[1]))

#define LDSM4(r, addr) asm volatile( \
    "ldmatrix.sync.aligned.m8n8.x4.shared.b16 {%0,%1,%2,%3}, [%4];" \
    : "=r"(r[0]), "=r"(r[1]), "=r"(r[2]), "=r"(r[3]) : "r"(addr))

#define LDSM4T(r, addr) asm volatile( \
    "ldmatrix.sync.aligned.m8n8.x4.trans.shared.b16 {%0,%1,%2,%3}, [%4];" \
    : "=r"(r[0]), "=r"(r[1]), "=r"(r[2]), "=r"(r[3]) : "r"(addr))

__device__ __forceinline__ void cp16(uint32_t dst, const void* src, bool pred) {
    int sz = pred ? 16 : 0;
    asm volatile("cp.async.cg.shared.global [%0], [%1], 16, %2;\n"
                 :: "r"(dst), "l"(src), "r"(sz));
}

// ---------------- split-bf16 GEMM, 32x64 warp tiles, 3 CTAs/SM ----------------
// C[m][n] = sum_k A[m][k]*W[n][k] + bias[n]
// BM=64, BN=128, 4 warps (warp = 32x64), BK=32, 2-stage.
// MODE 0: float C. MODE 1: split bf16. MODE 2: split + 2D-RoPE.
#define BM 64
#define BN 128
#define BK 32
#define SAST 40
#define HLA_B (64 * SAST * 2)          // 5120 bytes per A hi/lo
#define HLB_B (128 * SAST * 2)         // 10240 bytes per B hi/lo
#define B_OFS (2 * HLA_B)              // 10240
#define STG_B (2 * HLA_B + 2 * HLB_B)  // 30720
#define GSMEM (2 * STG_B)              // 61440
#define ROPE_LC  (13.287712379549449f / 16.f)

template <int MODE>
__global__ __launch_bounds__(128, 3) void gemm_bf16_split(
    const __nv_bfloat16* __restrict__ Ah, const __nv_bfloat16* __restrict__ Al,
    const __nv_bfloat16* __restrict__ Wh, const __nv_bfloat16* __restrict__ Wl,
    const float* __restrict__ bias, float* __restrict__ C,
    __nv_bfloat16* __restrict__ Ch, __nv_bfloat16* __restrict__ Cl, int M)
{
    extern __shared__ __align__(16) char smem[];
    const uint32_t sbase = (uint32_t)__cvta_generic_to_shared(smem);

    const int tid  = threadIdx.x;
    const int lane = tid & 31;
    const int wid  = tid >> 5;
    const int wm   = wid & 1;       // 2 warps over M (32 rows each)
    const int wn   = wid >> 1;      // 2 warps over N (64 cols each)
    const int bm   = blockIdx.y * BM;
    const int bn   = blockIdx.x * BN;

    const int a_r = (lane & 7) + ((lane >> 3) & 1) * 8;
    const int a_c = ((lane >> 4) & 1) * 8;
    const int g   = lane >> 3;
    const int b_r = (lane & 7) + (g >> 1) * 8;
    const int b_c = (g & 1) * 8;

    uint32_t aoff[2], boff[4];
#pragma unroll
    for (int i = 0; i < 2; i++)
        aoff[i] = (uint32_t)(((wm * 32 + i * 16 + a_r) * SAST + a_c) * 2);
#pragma unroll
    for (int j = 0; j < 4; j++)
        boff[j] = (uint32_t)(B_OFS + ((wn * 64 + j * 16 + b_r) * SAST + b_c) * 2);

    float c[2][8][4];
#pragma unroll
    for (int i = 0; i < 2; i++)
#pragma unroll
        for (int j = 0; j < 8; j++)
#pragma unroll
            for (int r = 0; r < 4; r++) c[i][j][r] = 0.f;

    // stage loader: 512 A-chunks + 1024 B-chunks of 16B, 12 per thread
    auto load_stage = [&](int s, int kt) {
        int k0 = kt * BK;
        uint32_t stb = sbase + (uint32_t)(s * STG_B);
#pragma unroll
        for (int i = 0; i < 12; i++) {
            int idx = tid + 128 * i;
            if (idx < 512) {
                int hl = idx >> 8, rem = idx & 255;
                int row = rem >> 2, seg = rem & 3;
                const __nv_bfloat16* src =
                    (hl ? Al : Ah) + (size_t)(bm + row) * ED + k0 + seg * 8;
                cp16(stb + (uint32_t)(hl * HLA_B + (row * SAST + seg * 8) * 2),
                     src, (bm + row) < M);
            } else {
                int j = idx - 512;
                int hl = j >> 9, rem = j & 511;
                int row = rem >> 2, seg = rem & 3;
                const __nv_bfloat16* src =
                    (hl ? Wl : Wh) + (size_t)(bn + row) * ED + k0 + seg * 8;
                cp16(stb + (uint32_t)(B_OFS + hl * HLB_B + (row * SAST + seg * 8) * 2),
                     src, true);
            }
        }
    };

    const int NK = ED / BK;  // 32
    load_stage(0, 0);
    asm volatile("cp.async.commit_group;");
    load_stage(1, 1);
    asm volatile("cp.async.commit_group;");

    for (int ks = 0; ks < NK; ks++) {
        if (ks < NK - 1) { asm volatile("cp.async.wait_group 1;"); }
        else             { asm volatile("cp.async.wait_group 0;"); }
        __syncthreads();

        const uint32_t sa = sbase + (uint32_t)((ks & 1) * STG_B);
#pragma unroll
        for (int h = 0; h < 2; h++) {
            uint32_t ah[2][4], alf[2][4], bh[4][4], blf[4][4];
#pragma unroll
            for (int i = 0; i < 2; i++) {
                LDSM4(ah[i],  sa + aoff[i] + h * 32);
                LDSM4(alf[i], sa + (uint32_t)HLA_B + aoff[i] + h * 32);
            }
#pragma unroll
            for (int j = 0; j < 4; j++) {
                LDSM4(bh[j],  sa + boff[j] + h * 32);
                LDSM4(blf[j], sa + (uint32_t)HLB_B + boff[j] + h * 32);
            }
            // term-major: hh, hl, lh (per-accumulator order preserved)
#pragma unroll
            for (int i = 0; i < 2; i++)
#pragma unroll
                for (int jj = 0; jj < 4; jj++) {
                    MMA_OP(c[i][2*jj],   ah[i], (bh[jj] + 0));
                    MMA_OP(c[i][2*jj+1], ah[i], (bh[jj] + 2));
                }
#pragma unroll
            for (int i = 0; i < 2; i++)
#pragma unroll
                for (int jj = 0; jj < 4; jj++) {
                    MMA_OP(c[i][2*jj],   ah[i], (blf[jj] + 0));
                    MMA_OP(c[i][2*jj+1], ah[i], (blf[jj] + 2));
                }
#pragma unroll
            for (int i = 0; i < 2; i++)
#pragma unroll
                for (int jj = 0; jj < 4; jj++) {
                    MMA_OP(c[i][2*jj],   alf[i], (bh[jj] + 0));
                    MMA_OP(c[i][2*jj+1], alf[i], (bh[jj] + 2));
                }
        }

        __syncthreads();
        if (ks + 2 < NK) {
            load_stage(ks & 1, ks + 2);
            asm volatile("cp.async.commit_group;");
        }
    }

    // ---------------- epilogue ----------------
    if (MODE == 2) {
        float invf[2][2];
#pragma unroll
        for (int jp = 0; jp < 2; jp++)
#pragma unroll
            for (int t = 0; t < 2; t++)
                invf[jp][t] = ex2f(-(float)(jp * 8 + (lane & 3) * 2 + t) * ROPE_LC);

#pragma unroll
        for (int i = 0; i < 2; i++) {
            int row0 = bm + wm * 32 + i * 16 + (lane >> 2);
#pragma unroll
            for (int half = 0; half < 2; half++) {
                int row = row0 + half * 8;
                if (row >= M) continue;
                int pr = row % SEQ;
                bool rot = pr > 0;
                float snh[2][2], csh[2][2], snw[2][2], csw[2][2];
                if (rot) {
                    int p = pr - 1;
                    float fgh = (float)(p / 24), fgw = (float)(p % 24);
#pragma unroll
                    for (int jp = 0; jp < 2; jp++)
#pragma unroll
                        for (int t = 0; t < 2; t++) {
                            __sincosf(fgh * invf[jp][t], &snh[jp][t], &csh[jp][t]);
                            __sincosf(fgw * invf[jp][t], &snw[jp][t], &csw[jp][t]);
                        }
                }
#pragma unroll
                for (int jn = 0; jn < 4; jn++) {
                    int n0 = bn + wn * 64 + jn * 8 + (lane & 3) * 2;
                    int jp = jn & 1;
                    float x1[2], x2[2];
#pragma unroll
                    for (int t = 0; t < 2; t++) {
                        float a = c[i][jn][half*2 + t]   + bias[n0 + t];
                        float b = c[i][jn+4][half*2 + t] + bias[n0 + 32 + t];
                        if (rot) {
                            float na = a * csh[jp][t] - b * snh[jp][t];
                            float nb = b * csw[jp][t] + a * snw[jp][t];
                            a = na; b = nb;
                        }
                        x1[t] = a; x2[t] = b;
                    }
                    uint32_t hi, lo;
                    split2(x1[0], x1[1], hi, lo);
                    *(uint32_t*)(Ch + (size_t)row * ED + n0) = hi;
                    *(uint32_t*)(Cl + (size_t)row * ED + n0) = lo;
                    split2(x2[0], x2[1], hi, lo);
                    *(uint32_t*)(Ch + (size_t)row * ED + n0 + 32) = hi;
                    *(uint32_t*)(Cl + (size_t)row * ED + n0 + 32) = lo;
                }
            }
        }
    } else {
#pragma unroll
        for (int i = 0; i < 2; i++) {
            int m0 = bm + wm * 32 + i * 16 + (lane >> 2);
#pragma unroll
            for (int jn = 0; jn < 8; jn++) {
                int n0 = bn + wn * 64 + jn * 8 + (lane & 3) * 2;
                float bx = bias[n0], by = bias[n0 + 1];
                if (MODE == 1) {
                    if (m0 < M) {
                        uint32_t hi, lo;
                        split2(c[i][jn][0] + bx, c[i][jn][1] + by, hi, lo);
                        *(uint32_t*)(Ch + (size_t)m0 * ED + n0) = hi;
                        *(uint32_t*)(Cl + (size_t)m0 * ED + n0) = lo;
                    }
                    if (m0 + 8 < M) {
                        uint32_t hi, lo;
                        split2(c[i][jn][2] + bx, c[i][jn][3] + by, hi, lo);
                        *(uint32_t*)(Ch + (size_t)(m0 + 8) * ED + n0) = hi;
                        *(uint32_t*)(Cl + (size_t)(m0 + 8) * ED + n0) = lo;
                    }
                } else {
                    if (m0 < M) {
                        float2 v = make_float2(c[i][jn][0] + bx, c[i][jn][1] + by);
                        *(float2*)&C[(size_t)m0 * ED + n0] = v;
                    }
                    if (m0 + 8 < M) {
                        float2 v = make_float2(c[i][jn][2] + bx, c[i][jn][3] + by);
                        *(float2*)&C[(size_t)(m0 + 8) * ED + n0] = v;
                    }
                }
            }
        }
    }
}

// ---------------- tensor-core flash attention (unchanged) ----------------
#define TSTR 72
#define MATB (64 * TSTR * 2)
#define STGB (4 * MATB)
#define ATT_SMEM (2 * STGB)

__global__ __launch_bounds__(128) void attn_mma(
    const __nv_bfloat16* __restrict__ qh, const __nv_bfloat16* __restrict__ ql,
    const __nv_bfloat16* __restrict__ kh, const __nv_bfloat16* __restrict__ kl,
    const __nv_bfloat16* __restrict__ vh, const __nv_bfloat16* __restrict__ vl,
    __nv_bfloat16* __restrict__ oh, __nv_bfloat16* __restrict__ ol)
{
    extern __shared__ __align__(16) __nv_bfloat16 asmem[];
    const uint32_t sbase = (uint32_t)__cvta_generic_to_shared(asmem);

    const int tid  = threadIdx.x;
    const int lane = tid & 31;
    const int w    = tid >> 5;
    const int b    = blockIdx.z;
    const int h    = blockIdx.y;
    const int qt   = blockIdx.x;
    const size_t hoff = (size_t)h * HD;
    const size_t bbase = (size_t)b * SEQ;

    const int a_r = (lane & 7) + ((lane >> 3) & 1) * 8;
    const int a_c = ((lane >> 4) & 1) * 8;
    const int g   = lane >> 3;
    const int b_r = (lane & 7) + (g >> 1) * 8;
    const int b_c = (g & 1) * 8;

    for (int c = tid; c < 1024; c += 128) {
        int mat = c >> 9, row = (c >> 3) & 63, seg = c & 7;
        int qrow = qt * 64 + row;
        if (qrow >= SEQ) qrow = SEQ - 1;
        const __nv_bfloat16* src = (mat ? ql : qh) + (bbase + qrow) * ED + hoff + seg * 8;
        cp16(sbase + mat * MATB + row * 144 + seg * 16, src, true);
    }
    asm volatile("cp.async.commit_group;");
    asm volatile("cp.async.wait_group 0;");
    __syncthreads();

    uint32_t qhf[4][4], qlf[4][4];
#pragma unroll
    for (int kc = 0; kc < 4; kc++) {
        uint32_t base0 = sbase + (uint32_t)((w * 16 + a_r) * 144 + (kc * 16 + a_c) * 2);
        LDSM4(qhf[kc], base0);
        LDSM4(qlf[kc], base0 + MATB);
    }
    __syncthreads();

    auto load_kv = [&](int s, int t) {
        const __nv_bfloat16* mats[4] = {kh, kl, vh, vl};
        for (int c = tid; c < 2048; c += 128) {
            int mat = c >> 9, row = (c >> 3) & 63, seg = c & 7;
            int kr = t * 64 + row;
            int krc = (kr < SEQ) ? kr : 0;
            const __nv_bfloat16* src = mats[mat] + (bbase + krc) * ED + hoff + seg * 8;
            cp16(sbase + s * STGB + mat * MATB + row * 144 + seg * 16, src, kr < SEQ);
        }
    };
    load_kv(0, 0);
    asm volatile("cp.async.commit_group;");
    load_kv(1, 1);
    asm volatile("cp.async.commit_group;");

    float off_[8][4];
#pragma unroll
    for (int ng = 0; ng < 8; ng++)
#pragma unroll
        for (int r = 0; r < 4; r++) off_[ng][r] = 0.f;
    float m_lo = -1e30f, m_hi = -1e30f, l_lo = 0.f, l_hi = 0.f;

    const float SCL = 0.18033688011112042f;

    for (int t = 0; t < NT; t++) {
        if (t < NT - 1) { asm volatile("cp.async.wait_group 1;"); }
        else            { asm volatile("cp.async.wait_group 0;"); }
        __syncthreads();
        const uint32_t sb2 = sbase + (uint32_t)((t & 1) * STGB);

        float sfr[8][4];
#pragma unroll
        for (int ng = 0; ng < 8; ng++)
#pragma unroll
            for (int r = 0; r < 4; r++) sfr[ng][r] = 0.f;

#pragma unroll
        for (int kc = 0; kc < 4; kc++) {
            uint32_t kf[4][4], lf[4][4];
#pragma unroll
            for (int pp = 0; pp < 4; pp++) {
                uint32_t ad = sb2 + (uint32_t)((pp * 16 + b_r) * 144 + (kc * 16 + b_c) * 2);
                LDSM4(kf[pp], ad);
                LDSM4(lf[pp], ad + MATB);
            }
#pragma unroll
            for (int ng = 0; ng < 8; ng++)
                MMA_OP(sfr[ng], qhf[kc], (kf[ng >> 1] + (ng & 1) * 2));
#pragma unroll
            for (int ng = 0; ng < 8; ng++)
                MMA_OP(sfr[ng], qhf[kc], (lf[ng >> 1] + (ng & 1) * 2));
#pragma unroll
            for (int ng = 0; ng < 8; ng++)
                MMA_OP(sfr[ng], qlf[kc], (kf[ng >> 1] + (ng & 1) * 2));
        }

        if (t * 64 + 64 > SEQ) {
            int tig2 = 2 * (lane & 3);
#pragma unroll
            for (int ng = 0; ng < 8; ng++) {
                int key0 = t * 64 + ng * 8 + tig2;
                if (key0     >= SEQ) { sfr[ng][0] = -1e30f; sfr[ng][2] = -1e30f; }
                if (key0 + 1 >= SEQ) { sfr[ng][1] = -1e30f; sfr[ng][3] = -1e30f; }
            }
        }

        float mx0 = -1e30f, mx1 = -1e30f;
#pragma unroll
        for (int ng = 0; ng < 8; ng++) {
            mx0 = fmaxf(mx0, fmaxf(sfr[ng][0], sfr[ng][1]));
            mx1 = fmaxf(mx1, fmaxf(sfr[ng][2], sfr[ng][3]));
        }
        mx0 = fmaxf(mx0, __shfl_xor_sync(0xffffffff, mx0, 1));
        mx0 = fmaxf(mx0, __shfl_xor_sync(0xffffffff, mx0, 2));
        mx1 = fmaxf(mx1, __shfl_xor_sync(0xffffffff, mx1, 1));
        mx1 = fmaxf(mx1, __shfl_xor_sync(0xffffffff, mx1, 2));
        float mn0 = fmaxf(m_lo, mx0), mn1 = fmaxf(m_hi, mx1);
        float al0 = ex2f((m_lo - mn0) * SCL), al1 = ex2f((m_hi - mn1) * SCL);
        m_lo = mn0; m_hi = mn1;

        float s0 = 0.f, s1 = 0.f;
#pragma unroll
        for (int ng = 0; ng < 8; ng++) {
            sfr[ng][0] = ex2f((sfr[ng][0] - mn0) * SCL);
            sfr[ng][1] = ex2f((sfr[ng][1] - mn0) * SCL);
            sfr[ng][2] = ex2f((sfr[ng][2] - mn1) * SCL);
            sfr[ng][3] = ex2f((sfr[ng][3] - mn1) * SCL);
            s0 += sfr[ng][0] + sfr[ng][1];
            s1 += sfr[ng][2] + sfr[ng][3];
        }
        s0 += __shfl_xor_sync(0xffffffff, s0, 1);
        s0 += __shfl_xor_sync(0xffffffff, s0, 2);
        s1 += __shfl_xor_sync(0xffffffff, s1, 1);
        s1 += __shfl_xor_sync(0xffffffff, s1, 2);
        l_lo = l_lo * al0 + s0;
        l_hi = l_hi * al1 + s1;

#pragma unroll
        for (int ng = 0; ng < 8; ng++) {
            off_[ng][0] *= al0; off_[ng][1] *= al0;
            off_[ng][2] *= al1; off_[ng][3] *= al1;
        }

        uint32_t ph[4][4], pl[4][4];
#pragma unroll
        for (int kc = 0; kc < 4; kc++) {
            split2(sfr[2*kc][0],   sfr[2*kc][1],   ph[kc][0], pl[kc][0]);
            split2(sfr[2*kc][2],   sfr[2*kc][3],   ph[kc][1], pl[kc][1]);
            split2(sfr[2*kc+1][0], sfr[2*kc+1][1], ph[kc][2], pl[kc][2]);
            split2(sfr[2*kc+1][2], sfr[2*kc+1][3], ph[kc][3], pl[kc][3]);
        }

#pragma unroll
        for (int kc = 0; kc < 4; kc++) {
            uint32_t vf[4][4], wf[4][4];
#pragma unroll
            for (int dp = 0; dp < 4; dp++) {
                uint32_t ad = sb2 + (uint32_t)(2 * MATB +
                               (kc * 16 + a_r) * 144 + (dp * 16 + a_c) * 2);
                LDSM4T(vf[dp], ad);
                LDSM4T(wf[dp], ad + MATB);
            }
#pragma unroll
            for (int ng = 0; ng < 8; ng++)
                MMA_OP(off_[ng], ph[kc], (vf[ng >> 1] + (ng & 1) * 2));
#pragma unroll
            for (int ng = 0; ng < 8; ng++)
                MMA_OP(off_[ng], pl[kc], (vf[ng >> 1] + (ng & 1) * 2));
#pragma unroll
            for (int ng = 0; ng < 8; ng++)
                MMA_OP(off_[ng], ph[kc], (wf[ng >> 1] + (ng & 1) * 2));
        }

        __syncthreads();
        if (t + 2 < NT) {
            load_kv(t & 1, t + 2);
            asm volatile("cp.async.commit_group;");
        }
    }

    float inv0 = 1.f / l_lo, inv1 = 1.f / l_hi;
    int q0 = qt * 64 + w * 16 + (lane >> 2);
    int col = 2 * (lane & 3);
#pragma unroll
    for (int ng = 0; ng < 8; ng++) {
        int n0 = ng * 8 + col;
        if (q0 < SEQ) {
            uint32_t hi, lo;
            split2(off_[ng][0] * inv0, off_[ng][1] * inv0, hi, lo);
            *(uint32_t*)(oh + (bbase + q0) * ED + hoff + n0) = hi;
            *(uint32_t*)(ol + (bbase + q0) * ED + hoff + n0) = lo;
        }
        if (q0 + 8 < SEQ) {
            uint32_t hi, lo;
            split2(off_[ng][2] * inv1, off_[ng][3] * inv1, hi, lo);
            *(uint32_t*)(oh + (bbase + q0 + 8) * ED + hoff + n0) = hi;
            *(uint32_t*)(ol + (bbase + q0 + 8) * ED + hoff + n0) = lo;
        }
    }
}

// ---------------- launch ----------------
extern "C" void kernel_launch(void* const* d_in, const int* in_sizes, int n_in,
                              void* d_out, int out_size)
{
    const float* hs = (const float*)d_in[0];
    const float* Wq = (const float*)d_in[1];
    const float* bq = (const float*)d_in[2];
    const float* Wk = (const float*)d_in[3];
    const float* bk = (const float*)d_in[4];
    const float* Wv = (const float*)d_in[5];
    const float* bv = (const float*)d_in[6];
    const float* Wo = (const float*)d_in[7];
    const float* bo = (const float*)d_in[8];
    float* out = (float*)d_out;

    __nv_bfloat16 *hsh, *hsl, *oh, *ol, *wh, *wl;
    __nv_bfloat16 *qhp, *qlp, *khp, *klp, *vhp, *vlp;
    cudaGetSymbolAddress((void**)&hsh, g_hsh);
    cudaGetSymbolAddress((void**)&hsl, g_hsl);
    cudaGetSymbolAddress((void**)&oh, g_oh);
    cudaGetSymbolAddress((void**)&ol, g_ol);
    cudaGetSymbolAddress((void**)&wh, g_wh);
    cudaGetSymbolAddress((void**)&wl, g_wl);
    cudaGetSymbolAddress((void**)&qhp, g_qh);
    cudaGetSymbolAddress((void**)&qlp, g_ql);
    cudaGetSymbolAddress((void**)&khp, g_kh);
    cudaGetSymbolAddress((void**)&klp, g_kl);
    cudaGetSymbolAddress((void**)&vhp, g_vh);
    cudaGetSymbolAddress((void**)&vlp, g_vl);

    cudaFuncSetAttribute(gemm_bf16_split<0>,
                         cudaFuncAttributeMaxDynamicSharedMemorySize, GSMEM);
    cudaFuncSetAttribute(gemm_bf16_split<1>,
                         cudaFuncAttributeMaxDynamicSharedMemorySize, GSMEM);
    cudaFuncSetAttribute(gemm_bf16_split<2>,
                         cudaFuncAttributeMaxDynamicSharedMemorySize, GSMEM);
    cudaFuncSetAttribute(attn_mma,
                         cudaFuncAttributeMaxDynamicSharedMemorySize, ATT_SMEM);

    const size_t WSZ = (size_t)ED * ED;
    const int n4_hs = MROWS * ED / 4;
    const int n4_w  = ED * ED / 4;

    cvt_split_kernel<<<(n4_hs + 255) / 256, 256>>>(hs, hsh, hsl, n4_hs);
    cvt_split4_kernel<<<(4 * n4_w + 255) / 256, 256>>>(Wq, Wk, Wv, Wo, wh, wl, n4_w);

    dim3 ggrid(ED / BN, (MROWS + BM - 1) / BM);   // (8, 145)

    gemm_bf16_split<2><<<ggrid, 128, GSMEM>>>(hsh, hsl, wh + 0*WSZ, wl + 0*WSZ, bq,
                                              nullptr, qhp, qlp, MROWS);
    gemm_bf16_split<2><<<ggrid, 128, GSMEM>>>(hsh, hsl, wh + 1*WSZ, wl + 1*WSZ, bk,
                                              nullptr, khp, klp, MROWS);
    gemm_bf16_split<1><<<ggrid, 128, GSMEM>>>(hsh, hsl, wh + 2*WSZ, wl + 2*WSZ, bv,
                                              nullptr, vhp, vlp, MROWS);

    attn_mma<<<dim3(QT, NH, BATCH), 128, ATT_SMEM>>>(qhp, qlp, khp, klp, vhp, vlp, oh, ol);

    gemm_bf16_split<0><<<ggrid, 128, GSMEM>>>(oh, ol, wh + 3*WSZ, wl + 3*WSZ, bo,
                                              out, nullptr, nullptr, MROWS);
}

// round 10
// speedup vs baseline: 11.9926x; 2.4311x over previous
#include <cuda_runtime.h>
#include <cuda_fp16.h>
#include <cstdint>
#include <math.h>

#define ED   1024
#define NH   16
#define HD   64
#define SEQ  577
#define BATCH 16
#define MROWS (BATCH * SEQ)   // 9232
#define NT   10
#define QT   10

// ---------------- scratch (fp16, single precision-level) ----------------
__device__ __half g_hs[(size_t)MROWS * ED];
__device__ __half g_w[4][(size_t)ED * ED];
__device__ __half g_qb[(size_t)MROWS * ED];
__device__ __half g_kb[(size_t)MROWS * ED];
__device__ __half g_vb[(size_t)MROWS * ED];
__device__ __half g_ob[(size_t)MROWS * ED];

// ---------------- helpers ----------------
__device__ __forceinline__ float ex2f(float x) {
    float r;
    asm("ex2.approx.ftz.f32 %0, %1;" : "=f"(r) : "f"(x));
    return r;
}
__device__ __forceinline__ uint32_t pack2h(float a, float b) {
    __half2 h = __floats2half2_rn(a, b);
    return *(uint32_t*)&h;
}

// ---------------- fp32 -> fp16 convert ----------------
__global__ void cvt_half_kernel(const float* __restrict__ x,
                                __half* __restrict__ o, int n4)
{
    int i = blockIdx.x * blockDim.x + threadIdx.x;
    if (i >= n4) return;
    float4 v = ((const float4*)x)[i];
    uint2 r;
    r.x = pack2h(v.x, v.y);
    r.y = pack2h(v.z, v.w);
    ((uint2*)o)[i] = r;
}

__global__ void cvt_half4_kernel(const float* __restrict__ w0, const float* __restrict__ w1,
                                 const float* __restrict__ w2, const float* __restrict__ w3,
                                 __half* __restrict__ wо, int n4_per)
{
    int i = blockIdx.x * blockDim.x + threadIdx.x;
    if (i >= 4 * n4_per) return;
    int sel = i / n4_per;
    int rem = i - sel * n4_per;
    const float* src = (sel == 0) ? w0 : (sel == 1) ? w1 : (sel == 2) ? w2 : w3;
    float4 v = ((const float4*)src)[rem];
    uint2 r;
    r.x = pack2h(v.x, v.y);
    r.y = pack2h(v.z, v.w);
    ((uint2*)(wо + (size_t)sel * ED * ED))[rem] = r;
}

// ---------------- MMA / ldmatrix / cp.async primitives ----------------
#define MMA_OP(d, a, b) asm volatile( \
    "mma.sync.aligned.m16n8k16.row.col.f32.f16.f16.f32 " \
    "{%0,%1,%2,%3},{%4,%5,%6,%7},{%8,%9},{%0,%1,%2,%3};" \
    : "+f"(d[0]), "+f"(d[1]), "+f"(d[2]), "+f"(d[3]) \
    : "r"(a[0]), "r"(a[1]), "r"(a[2]), "r"(a[3]), "r"(b[0]), "r"(b[1]))

#define LDSM4(r, addr) asm volatile( \
    "ldmatrix.sync.aligned.m8n8.x4.shared.b16 {%0,%1,%2,%3}, [%4];" \
    : "=r"(r[0]), "=r"(r[1]), "=r"(r[2]), "=r"(r[3]) : "r"(addr))

#define LDSM4T(r, addr) asm volatile( \
    "ldmatrix.sync.aligned.m8n8.x4.trans.shared.b16 {%0,%1,%2,%3}, [%4];" \
    : "=r"(r[0]), "=r"(r[1]), "=r"(r[2]), "=r"(r[3]) : "r"(addr))

__device__ __forceinline__ void cp16(uint32_t dst, const void* src, bool pred) {
    int sz = pred ? 16 : 0;
    asm volatile("cp.async.cg.shared.global [%0], [%1], 16, %2;\n"
                 :: "r"(dst), "l"(src), "r"(sz));
}

// ---------------- fp16 GEMM: C = A W^T + bias ----------------
// BM=64, BN=128, BK=64, 4 warps (warp 32x64), 2 stages, 3 CTAs/SM.
// MODE 0: float C. MODE 1: fp16 C. MODE 2: fp16 + fused 2D-RoPE.
#define BM 64
#define BN 128
#define BK 64
#define SAST 72                       // 144B row stride
#define A_BYTES (64 * SAST * 2)       // 9216
#define B_BYTES (128 * SAST * 2)      // 18432
#define STG_B   (A_BYTES + B_BYTES)   // 27648
#define GSMEM   (2 * STG_B)           // 55296
#define ROPE_LC (13.287712379549449f / 16.f)

template <int MODE>
__global__ __launch_bounds__(128, 3) void gemm_f16(
    const __half* __restrict__ A, const __half* __restrict__ W,
    const float* __restrict__ bias, float* __restrict__ C,
    __half* __restrict__ Ch, int M)
{
    extern __shared__ __align__(16) char smem[];
    const uint32_t sbase = (uint32_t)__cvta_generic_to_shared(smem);

    const int tid  = threadIdx.x;
    const int lane = tid & 31;
    const int wid  = tid >> 5;
    const int wm   = wid & 1;       // 2 warps over M (32 rows)
    const int wn   = wid >> 1;      // 2 warps over N (64 cols)
    const int bm   = blockIdx.y * BM;
    const int bn   = blockIdx.x * BN;

    const int a_r = (lane & 7) + ((lane >> 3) & 1) * 8;
    const int a_c = ((lane >> 4) & 1) * 8;
    const int g   = lane >> 3;
    const int b_r = (lane & 7) + (g >> 1) * 8;
    const int b_c = (g & 1) * 8;

    uint32_t aoff[2], boff[4];
#pragma unroll
    for (int i = 0; i < 2; i++)
        aoff[i] = (uint32_t)(((wm * 32 + i * 16 + a_r) * SAST + a_c) * 2);
#pragma unroll
    for (int j = 0; j < 4; j++)
        boff[j] = (uint32_t)(A_BYTES + ((wn * 64 + j * 16 + b_r) * SAST + b_c) * 2);

    float c[2][8][4];
#pragma unroll
    for (int i = 0; i < 2; i++)
#pragma unroll
        for (int j = 0; j < 8; j++)
#pragma unroll
            for (int r = 0; r < 4; r++) c[i][j][r] = 0.f;

    // stage loader: A 512 + B 1024 chunks of 16B, 12 per thread
    auto load_stage = [&](int s, int kt) {
        int k0 = kt * BK;
        uint32_t stb = sbase + (uint32_t)(s * STG_B);
#pragma unroll
        for (int i = 0; i < 12; i++) {
            int idx = tid + 128 * i;
            if (idx < 512) {
                int row = idx >> 3, seg = idx & 7;
                const __half* src = A + (size_t)(bm + row) * ED + k0 + seg * 8;
                cp16(stb + (uint32_t)((row * SAST + seg * 8) * 2),
                     src, (bm + row) < M);
            } else {
                int j = idx - 512;
                int row = j >> 3, seg = j & 7;
                const __half* src = W + (size_t)(bn + row) * ED + k0 + seg * 8;
                cp16(stb + (uint32_t)(A_BYTES + (row * SAST + seg * 8) * 2),
                     src, true);
            }
        }
    };

    const int NK = ED / BK;  // 16
    load_stage(0, 0);
    asm volatile("cp.async.commit_group;");
    load_stage(1, 1);
    asm volatile("cp.async.commit_group;");

    for (int ks = 0; ks < NK; ks++) {
        if (ks < NK - 1) { asm volatile("cp.async.wait_group 1;"); }
        else             { asm volatile("cp.async.wait_group 0;"); }
        __syncthreads();

        const uint32_t sa = sbase + (uint32_t)((ks & 1) * STG_B);
#pragma unroll
        for (int kk = 0; kk < 4; kk++) {
            uint32_t af[2][4], bf[4][4];
#pragma unroll
            for (int i = 0; i < 2; i++)
                LDSM4(af[i], sa + aoff[i] + kk * 32);
#pragma unroll
            for (int j = 0; j < 4; j++)
                LDSM4(bf[j], sa + boff[j] + kk * 32);
#pragma unroll
            for (int i = 0; i < 2; i++)
#pragma unroll
                for (int jj = 0; jj < 4; jj++) {
                    MMA_OP(c[i][2*jj],   af[i], (bf[jj] + 0));
                    MMA_OP(c[i][2*jj+1], af[i], (bf[jj] + 2));
                }
        }

        __syncthreads();
        if (ks + 2 < NK) {
            load_stage(ks & 1, ks + 2);
            asm volatile("cp.async.commit_group;");
        }
    }

    // ---------------- epilogue ----------------
    if (MODE == 2) {
        // fused 2D-RoPE. Warp's 64 cols = one head; col d pairs with d+32
        // as fragment jn <-> jn+4 (same thread, same r).
        float invf[2][2];
#pragma unroll
        for (int jp = 0; jp < 2; jp++)
#pragma unroll
            for (int t = 0; t < 2; t++)
                invf[jp][t] = ex2f(-(float)(jp * 8 + (lane & 3) * 2 + t) * ROPE_LC);

#pragma unroll
        for (int i = 0; i < 2; i++) {
            int row0 = bm + wm * 32 + i * 16 + (lane >> 2);
#pragma unroll
            for (int half = 0; half < 2; half++) {
                int row = row0 + half * 8;
                if (row >= M) continue;
                int pr = row % SEQ;
                bool rot = pr > 0;
                float snh[2][2], csh[2][2], snw[2][2], csw[2][2];
                if (rot) {
                    int p = pr - 1;
                    float fgh = (float)(p / 24), fgw = (float)(p % 24);
#pragma unroll
                    for (int jp = 0; jp < 2; jp++)
#pragma unroll
                        for (int t = 0; t < 2; t++) {
                            __sincosf(fgh * invf[jp][t], &snh[jp][t], &csh[jp][t]);
                            __sincosf(fgw * invf[jp][t], &snw[jp][t], &csw[jp][t]);
                        }
                }
#pragma unroll
                for (int jn = 0; jn < 4; jn++) {
                    int n0 = bn + wn * 64 + jn * 8 + (lane & 3) * 2;
                    int jp = jn & 1;
                    float x1[2], x2[2];
#pragma unroll
                    for (int t = 0; t < 2; t++) {
                        float a = c[i][jn][half*2 + t]   + bias[n0 + t];
                        float b = c[i][jn+4][half*2 + t] + bias[n0 + 32 + t];
                        if (rot) {
                            float na = a * csh[jp][t] - b * snh[jp][t];
                            float nb = b * csw[jp][t] + a * snw[jp][t];
                            a = na; b = nb;
                        }
                        x1[t] = a; x2[t] = b;
                    }
                    *(uint32_t*)(Ch + (size_t)row * ED + n0)      = pack2h(x1[0], x1[1]);
                    *(uint32_t*)(Ch + (size_t)row * ED + n0 + 32) = pack2h(x2[0], x2[1]);
                }
            }
        }
    } else {
#pragma unroll
        for (int i = 0; i < 2; i++) {
            int m0 = bm + wm * 32 + i * 16 + (lane >> 2);
#pragma unroll
            for (int jn = 0; jn < 8; jn++) {
                int n0 = bn + wn * 64 + jn * 8 + (lane & 3) * 2;
                float bx = bias[n0], by = bias[n0 + 1];
                if (MODE == 1) {
                    if (m0 < M)
                        *(uint32_t*)(Ch + (size_t)m0 * ED + n0) =
                            pack2h(c[i][jn][0] + bx, c[i][jn][1] + by);
                    if (m0 + 8 < M)
                        *(uint32_t*)(Ch + (size_t)(m0 + 8) * ED + n0) =
                            pack2h(c[i][jn][2] + bx, c[i][jn][3] + by);
                } else {
                    if (m0 < M) {
                        float2 v = make_float2(c[i][jn][0] + bx, c[i][jn][1] + by);
                        *(float2*)&C[(size_t)m0 * ED + n0] = v;
                    }
                    if (m0 + 8 < M) {
                        float2 v = make_float2(c[i][jn][2] + bx, c[i][jn][3] + by);
                        *(float2*)&C[(size_t)(m0 + 8) * ED + n0] = v;
                    }
                }
            }
        }
    }
}

// ---------------- fp16 tensor-core flash attention ----------------
#define TSTR 72
#define MATB (64 * TSTR * 2)          // 9216
#define STGB (2 * MATB)               // 18432 (K, V)
#define ATT_SMEM (2 * STGB)           // 36864

__global__ __launch_bounds__(128) void attn_mma(
    const __half* __restrict__ q, const __half* __restrict__ k,
    const __half* __restrict__ v, __half* __restrict__ o)
{
    extern __shared__ __align__(16) __half asmem[];
    const uint32_t sbase = (uint32_t)__cvta_generic_to_shared(asmem);

    const int tid  = threadIdx.x;
    const int lane = tid & 31;
    const int w    = tid >> 5;
    const int b    = blockIdx.z;
    const int h    = blockIdx.y;
    const int qt   = blockIdx.x;
    const size_t hoff = (size_t)h * HD;
    const size_t bbase = (size_t)b * SEQ;

    const int a_r = (lane & 7) + ((lane >> 3) & 1) * 8;
    const int a_c = ((lane >> 4) & 1) * 8;
    const int g   = lane >> 3;
    const int b_r = (lane & 7) + (g >> 1) * 8;
    const int b_c = (g & 1) * 8;

    // Q tile into stage0 area, then into regs
    for (int c = tid; c < 512; c += 128) {
        int row = c >> 3, seg = c & 7;
        int qrow = qt * 64 + row;
        if (qrow >= SEQ) qrow = SEQ - 1;
        const __half* src = q + (bbase + qrow) * ED + hoff + seg * 8;
        cp16(sbase + row * 144 + seg * 16, src, true);
    }
    asm volatile("cp.async.commit_group;");
    asm volatile("cp.async.wait_group 0;");
    __syncthreads();

    uint32_t qf[4][4];
#pragma unroll
    for (int kc = 0; kc < 4; kc++)
        LDSM4(qf[kc], sbase + (uint32_t)((w * 16 + a_r) * 144 + (kc * 16 + a_c) * 2));
    __syncthreads();

    auto load_kv = [&](int s, int t) {
        for (int c = tid; c < 1024; c += 128) {
            int mat = c >> 9, row = (c >> 3) & 63, seg = c & 7;
            int kr = t * 64 + row;
            int krc = (kr < SEQ) ? kr : 0;
            const __half* src = (mat ? v : k) + (bbase + krc) * ED + hoff + seg * 8;
            cp16(sbase + s * STGB + mat * MATB + row * 144 + seg * 16, src, kr < SEQ);
        }
    };
    load_kv(0, 0);
    asm volatile("cp.async.commit_group;");
    load_kv(1, 1);
    asm volatile("cp.async.commit_group;");

    float off_[8][4];
#pragma unroll
    for (int ng = 0; ng < 8; ng++)
#pragma unroll
        for (int r = 0; r < 4; r++) off_[ng][r] = 0.f;
    float m_lo = -1e30f, m_hi = -1e30f, l_lo = 0.f, l_hi = 0.f;

    const float SCL = 0.18033688011112042f;   // 0.125 * log2(e)

    for (int t = 0; t < NT; t++) {
        if (t < NT - 1) { asm volatile("cp.async.wait_group 1;"); }
        else            { asm volatile("cp.async.wait_group 0;"); }
        __syncthreads();
        const uint32_t sb2 = sbase + (uint32_t)((t & 1) * STGB);

        float sfr[8][4];
#pragma unroll
        for (int ng = 0; ng < 8; ng++)
#pragma unroll
            for (int r = 0; r < 4; r++) sfr[ng][r] = 0.f;

#pragma unroll
        for (int kc = 0; kc < 4; kc++) {
            uint32_t kf[4][4];
#pragma unroll
            for (int pp = 0; pp < 4; pp++)
                LDSM4(kf[pp], sb2 + (uint32_t)((pp * 16 + b_r) * 144 + (kc * 16 + b_c) * 2));
#pragma unroll
            for (int ng = 0; ng < 8; ng++)
                MMA_OP(sfr[ng], qf[kc], (kf[ng >> 1] + (ng & 1) * 2));
        }

        if (t * 64 + 64 > SEQ) {
            int tig2 = 2 * (lane & 3);
#pragma unroll
            for (int ng = 0; ng < 8; ng++) {
                int key0 = t * 64 + ng * 8 + tig2;
                if (key0     >= SEQ) { sfr[ng][0] = -1e30f; sfr[ng][2] = -1e30f; }
                if (key0 + 1 >= SEQ) { sfr[ng][1] = -1e30f; sfr[ng][3] = -1e30f; }
            }
        }

        float mx0 = -1e30f, mx1 = -1e30f;
#pragma unroll
        for (int ng = 0; ng < 8; ng++) {
            mx0 = fmaxf(mx0, fmaxf(sfr[ng][0], sfr[ng][1]));
            mx1 = fmaxf(mx1, fmaxf(sfr[ng][2], sfr[ng][3]));
        }
        mx0 = fmaxf(mx0, __shfl_xor_sync(0xffffffff, mx0, 1));
        mx0 = fmaxf(mx0, __shfl_xor_sync(0xffffffff, mx0, 2));
        mx1 = fmaxf(mx1, __shfl_xor_sync(0xffffffff, mx1, 1));
        mx1 = fmaxf(mx1, __shfl_xor_sync(0xffffffff, mx1, 2));
        float mn0 = fmaxf(m_lo, mx0), mn1 = fmaxf(m_hi, mx1);
        float al0 = ex2f((m_lo - mn0) * SCL), al1 = ex2f((m_hi - mn1) * SCL);
        m_lo = mn0; m_hi = mn1;

        float s0 = 0.f, s1 = 0.f;
#pragma unroll
        for (int ng = 0; ng < 8; ng++) {
            sfr[ng][0] = ex2f((sfr[ng][0] - mn0) * SCL);
            sfr[ng][1] = ex2f((sfr[ng][1] - mn0) * SCL);
            sfr[ng][2] = ex2f((sfr[ng][2] - mn1) * SCL);
            sfr[ng][3] = ex2f((sfr[ng][3] - mn1) * SCL);
            s0 += sfr[ng][0] + sfr[ng][1];
            s1 += sfr[ng][2] + sfr[ng][3];
        }
        s0 += __shfl_xor_sync(0xffffffff, s0, 1);
        s0 += __shfl_xor_sync(0xffffffff, s0, 2);
        s1 += __shfl_xor_sync(0xffffffff, s1, 1);
        s1 += __shfl_xor_sync(0xffffffff, s1, 2);
        l_lo = l_lo * al0 + s0;
        l_hi = l_hi * al1 + s1;

#pragma unroll
        for (int ng = 0; ng < 8; ng++) {
            off_[ng][0] *= al0; off_[ng][1] *= al0;
            off_[ng][2] *= al1; off_[ng][3] *= al1;
        }

        // P -> fp16 fragments
        uint32_t ph[4][4];
#pragma unroll
        for (int kc = 0; kc < 4; kc++) {
            ph[kc][0] = pack2h(sfr[2*kc][0],   sfr[2*kc][1]);
            ph[kc][1] = pack2h(sfr[2*kc][2],   sfr[2*kc][3]);
            ph[kc][2] = pack2h(sfr[2*kc+1][0], sfr[2*kc+1][1]);
            ph[kc][3] = pack2h(sfr[2*kc+1][2], sfr[2*kc+1][3]);
        }

#pragma unroll
        for (int kc = 0; kc < 4; kc++) {
            uint32_t vf[4][4];
#pragma unroll
            for (int dp = 0; dp < 4; dp++)
                LDSM4T(vf[dp], sb2 + (uint32_t)(MATB +
                              (kc * 16 + a_r) * 144 + (dp * 16 + a_c) * 2));
#pragma unroll
            for (int ng = 0; ng < 8; ng++)
                MMA_OP(off_[ng], ph[kc], (vf[ng >> 1] + (ng & 1) * 2));
        }

        __syncthreads();
        if (t + 2 < NT) {
            load_kv(t & 1, t + 2);
            asm volatile("cp.async.commit_group;");
        }
    }

    float inv0 = 1.f / l_lo, inv1 = 1.f / l_hi;
    int q0 = qt * 64 + w * 16 + (lane >> 2);
    int col = 2 * (lane & 3);
#pragma unroll
    for (int ng = 0; ng < 8; ng++) {
        int n0 = ng * 8 + col;
        if (q0 < SEQ)
            *(uint32_t*)(o + (bbase + q0) * ED + hoff + n0) =
                pack2h(off_[ng][0] * inv0, off_[ng][1] * inv0);
        if (q0 + 8 < SEQ)
            *(uint32_t*)(o + (bbase + q0 + 8) * ED + hoff + n0) =
                pack2h(off_[ng][2] * inv1, off_[ng][3] * inv1);
    }
}

// ---------------- launch ----------------
extern "C" void kernel_launch(void* const* d_in, const int* in_sizes, int n_in,
                              void* d_out, int out_size)
{
    const float* hs = (const float*)d_in[0];
    const float* Wq = (const float*)d_in[1];
    const float* bq = (const float*)d_in[2];
    const float* Wk = (const float*)d_in[3];
    const float* bk = (const float*)d_in[4];
    const float* Wv = (const float*)d_in[5];
    const float* bv = (const float*)d_in[6];
    const float* Wo = (const float*)d_in[7];
    const float* bo = (const float*)d_in[8];
    float* out = (float*)d_out;

    __half *hsp, *wp, *qp, *kp, *vp, *op;
    cudaGetSymbolAddress((void**)&hsp, g_hs);
    cudaGetSymbolAddress((void**)&wp, g_w);
    cudaGetSymbolAddress((void**)&qp, g_qb);
    cudaGetSymbolAddress((void**)&kp, g_kb);
    cudaGetSymbolAddress((void**)&vp, g_vb);
    cudaGetSymbolAddress((void**)&op, g_ob);

    cudaFuncSetAttribute(gemm_f16<0>,
                         cudaFuncAttributeMaxDynamicSharedMemorySize, GSMEM);
    cudaFuncSetAttribute(gemm_f16<1>,
                         cudaFuncAttributeMaxDynamicSharedMemorySize, GSMEM);
    cudaFuncSetAttribute(gemm_f16<2>,
                         cudaFuncAttributeMaxDynamicSharedMemorySize, GSMEM);
    cudaFuncSetAttribute(attn_mma,
                         cudaFuncAttributeMaxDynamicSharedMemorySize, ATT_SMEM);

    const size_t WSZ = (size_t)ED * ED;
    const int n4_hs = MROWS * ED / 4;
    const int n4_w  = ED * ED / 4;

    cvt_half_kernel<<<(n4_hs + 255) / 256, 256>>>(hs, hsp, n4_hs);
    cvt_half4_kernel<<<(4 * n4_w + 255) / 256, 256>>>(Wq, Wk, Wv, Wo, wp, n4_w);

    dim3 ggrid(ED / BN, (MROWS + BM - 1) / BM);   // (8, 145)

    gemm_f16<2><<<ggrid, 128, GSMEM>>>(hsp, wp + 0*WSZ, bq, nullptr, qp, MROWS);
    gemm_f16<2><<<ggrid, 128, GSMEM>>>(hsp, wp + 1*WSZ, bk, nullptr, kp, MROWS);
    gemm_f16<1><<<ggrid, 128, GSMEM>>>(hsp, wp + 2*WSZ, bv, nullptr, vp, MROWS);

    attn_mma<<<dim3(QT, NH, BATCH), 128, ATT_SMEM>>>(qp, kp, vp, op);

    gemm_f16<0><<<ggrid, 128, GSMEM>>>(op, wp + 3*WSZ, bo, out, nullptr, MROWS);
}

// round 11
// speedup vs baseline: 12.7755x; 1.0653x over previous
#include <cuda_runtime.h>
#include <cuda_fp16.h>
#include <cstdint>
#include <math.h>

#define ED   1024
#define NH   16
#define HD   64
#define SEQ  577
#define BATCH 16
#define MROWS (BATCH * SEQ)   // 9232
#define NT   10
#define QT   10

// ---------------- scratch ----------------
__device__ __half g_hs[(size_t)MROWS * ED];
__device__ __half g_w[4][(size_t)ED * ED];
__device__ __half g_qb[(size_t)MROWS * ED];
__device__ __half g_kb[(size_t)MROWS * ED];
__device__ __half g_vb[(size_t)MROWS * ED];
__device__ __half g_ob[(size_t)MROWS * ED];

// ---------------- helpers ----------------
__device__ __forceinline__ float ex2f(float x) {
    float r;
    asm("ex2.approx.ftz.f32 %0, %1;" : "=f"(r) : "f"(x));
    return r;
}
__device__ __forceinline__ uint32_t pack2h(float a, float b) {
    __half2 h = __floats2half2_rn(a, b);
    return *(uint32_t*)&h;
}

// ---------------- fp32 -> fp16 convert ----------------
__global__ void cvt_half_kernel(const float* __restrict__ x,
                                __half* __restrict__ o, int n4)
{
    int i = blockIdx.x * blockDim.x + threadIdx.x;
    if (i >= n4) return;
    float4 v = ((const float4*)x)[i];
    uint2 r;
    r.x = pack2h(v.x, v.y);
    r.y = pack2h(v.z, v.w);
    ((uint2*)o)[i] = r;
}

__global__ void cvt_half4_kernel(const float* __restrict__ w0, const float* __restrict__ w1,
                                 const float* __restrict__ w2, const float* __restrict__ w3,
                                 __half* __restrict__ wo, int n4_per)
{
    int i = blockIdx.x * blockDim.x + threadIdx.x;
    if (i >= 4 * n4_per) return;
    int sel = i / n4_per;
    int rem = i - sel * n4_per;
    const float* src = (sel == 0) ? w0 : (sel == 1) ? w1 : (sel == 2) ? w2 : w3;
    float4 v = ((const float4*)src)[rem];
    uint2 r;
    r.x = pack2h(v.x, v.y);
    r.y = pack2h(v.z, v.w);
    ((uint2*)(wo + (size_t)sel * ED * ED))[rem] = r;
}

// ---------------- MMA / ldmatrix / cp.async primitives ----------------
#define MMA_OP(d, a, b) asm volatile( \
    "mma.sync.aligned.m16n8k16.row.col.f32.f16.f16.f32 " \
    "{%0,%1,%2,%3},{%4,%5,%6,%7},{%8,%9},{%0,%1,%2,%3};" \
    : "+f"(d[0]), "+f"(d[1]), "+f"(d[2]), "+f"(d[3]) \
    : "r"(a[0]), "r"(a[1]), "r"(a[2]), "r"(a[3]), "r"(b[0]), "r"(b[1]))

#define LDSM4(r, addr) asm volatile( \
    "ldmatrix.sync.aligned.m8n8.x4.shared.b16 {%0,%1,%2,%3}, [%4];" \
    : "=r"(r[0]), "=r"(r[1]), "=r"(r[2]), "=r"(r[3]) : "r"(addr))

#define LDSM4T(r, addr) asm volatile( \
    "ldmatrix.sync.aligned.m8n8.x4.trans.shared.b16 {%0,%1,%2,%3}, [%4];" \
    : "=r"(r[0]), "=r"(r[1]), "=r"(r[2]), "=r"(r[3]) : "r"(addr))

__device__ __forceinline__ void cp16(uint32_t dst, const void* src, bool pred) {
    int sz = pred ? 16 : 0;
    asm volatile("cp.async.cg.shared.global [%0], [%1], 16, %2;\n"
                 :: "r"(dst), "l"(src), "r"(sz));
}

// ---------------- fp16 GEMM: C = A W^T + bias ----------------
// BM=128, BN=128, BK=64, 256 threads (8 warps of 32x64), 3 stages, 2 CTAs/SM.
// MODE 0: float C. MODE 1: fp16 C. MODE 2: fp16 + fused 2D-RoPE.
#define BM 128
#define BN 128
#define BK 64
#define SAST 72                       // 144B row stride
#define A_BYTES (128 * SAST * 2)      // 18432
#define B_BYTES (128 * SAST * 2)      // 18432
#define STG_B   (A_BYTES + B_BYTES)   // 36864
#define GSMEM   (3 * STG_B)           // 110592
#define ROPE_LC (13.287712379549449f / 16.f)

template <int MODE>
__global__ __launch_bounds__(256, 2) void gemm_f16(
    const __half* __restrict__ A, const __half* __restrict__ W,
    const float* __restrict__ bias, float* __restrict__ C,
    __half* __restrict__ Ch, int M)
{
    extern __shared__ __align__(16) char smem[];
    const uint32_t sbase = (uint32_t)__cvta_generic_to_shared(smem);

    const int tid  = threadIdx.x;
    const int lane = tid & 31;
    const int wid  = tid >> 5;
    const int wm   = wid & 3;       // 4 warps over M (32 rows)
    const int wn   = wid >> 2;      // 2 warps over N (64 cols)
    const int bm   = blockIdx.y * BM;
    const int bn   = blockIdx.x * BN;

    const int a_r = (lane & 7) + ((lane >> 3) & 1) * 8;
    const int a_c = ((lane >> 4) & 1) * 8;
    const int g   = lane >> 3;
    const int b_r = (lane & 7) + (g >> 1) * 8;
    const int b_c = (g & 1) * 8;

    uint32_t aoff[2], boff[4];
#pragma unroll
    for (int i = 0; i < 2; i++)
        aoff[i] = (uint32_t)(((wm * 32 + i * 16 + a_r) * SAST + a_c) * 2);
#pragma unroll
    for (int j = 0; j < 4; j++)
        boff[j] = (uint32_t)(A_BYTES + ((wn * 64 + j * 16 + b_r) * SAST + b_c) * 2);

    float c[2][8][4];
#pragma unroll
    for (int i = 0; i < 2; i++)
#pragma unroll
        for (int j = 0; j < 8; j++)
#pragma unroll
            for (int r = 0; r < 4; r++) c[i][j][r] = 0.f;

    // stage loader: A 1024 + B 1024 chunks of 16B, 8 per thread
    auto load_stage = [&](int s, int kt) {
        int k0 = kt * BK;
        uint32_t stb = sbase + (uint32_t)(s * STG_B);
#pragma unroll
        for (int i = 0; i < 8; i++) {
            int idx = tid + 256 * i;
            if (idx < 1024) {
                int row = idx >> 3, seg = idx & 7;
                const __half* src = A + (size_t)(bm + row) * ED + k0 + seg * 8;
                cp16(stb + (uint32_t)((row * SAST + seg * 8) * 2),
                     src, (bm + row) < M);
            } else {
                int j = idx - 1024;
                int row = j >> 3, seg = j & 7;
                const __half* src = W + (size_t)(bn + row) * ED + k0 + seg * 8;
                cp16(stb + (uint32_t)(A_BYTES + (row * SAST + seg * 8) * 2),
                     src, true);
            }
        }
    };

    const int NK = ED / BK;  // 16
    load_stage(0, 0);
    asm volatile("cp.async.commit_group;");
    load_stage(1, 1);
    asm volatile("cp.async.commit_group;");

    for (int ks = 0; ks < NK; ks++) {
        if (ks < NK - 1) { asm volatile("cp.async.wait_group 1;"); }
        else             { asm volatile("cp.async.wait_group 0;"); }
        __syncthreads();

        // prefetch ks+2 into the stage freed by ks-1 (sync above covers it)
        if (ks + 2 < NK) load_stage((ks + 2) % 3, ks + 2);
        asm volatile("cp.async.commit_group;");

        const uint32_t sa = sbase + (uint32_t)((ks % 3) * STG_B);
#pragma unroll
        for (int kk = 0; kk < 4; kk++) {
            uint32_t af[2][4], bf[4][4];
#pragma unroll
            for (int i = 0; i < 2; i++)
                LDSM4(af[i], sa + aoff[i] + kk * 32);
#pragma unroll
            for (int j = 0; j < 4; j++)
                LDSM4(bf[j], sa + boff[j] + kk * 32);
#pragma unroll
            for (int i = 0; i < 2; i++)
#pragma unroll
                for (int jj = 0; jj < 4; jj++) {
                    MMA_OP(c[i][2*jj],   af[i], (bf[jj] + 0));
                    MMA_OP(c[i][2*jj+1], af[i], (bf[jj] + 2));
                }
        }
    }

    // ---------------- epilogue ----------------
    if (MODE == 2) {
        // fused 2D-RoPE. Warp's 64 cols = one head; col d pairs with d+32
        // as fragment jn <-> jn+4 (same thread, same r).
        float invf[2][2];
#pragma unroll
        for (int jp = 0; jp < 2; jp++)
#pragma unroll
            for (int t = 0; t < 2; t++)
                invf[jp][t] = ex2f(-(float)(jp * 8 + (lane & 3) * 2 + t) * ROPE_LC);

#pragma unroll
        for (int i = 0; i < 2; i++) {
            int row0 = bm + wm * 32 + i * 16 + (lane >> 2);
#pragma unroll
            for (int half = 0; half < 2; half++) {
                int row = row0 + half * 8;
                if (row >= M) continue;
                int pr = row % SEQ;
                bool rot = pr > 0;
                float snh[2][2], csh[2][2], snw[2][2], csw[2][2];
                if (rot) {
                    int p = pr - 1;
                    float fgh = (float)(p / 24), fgw = (float)(p % 24);
#pragma unroll
                    for (int jp = 0; jp < 2; jp++)
#pragma unroll
                        for (int t = 0; t < 2; t++) {
                            __sincosf(fgh * invf[jp][t], &snh[jp][t], &csh[jp][t]);
                            __sincosf(fgw * invf[jp][t], &snw[jp][t], &csw[jp][t]);
                        }
                }
#pragma unroll
                for (int jn = 0; jn < 4; jn++) {
                    int n0 = bn + wn * 64 + jn * 8 + (lane & 3) * 2;
                    int jp = jn & 1;
                    float x1[2], x2[2];
#pragma unroll
                    for (int t = 0; t < 2; t++) {
                        float a = c[i][jn][half*2 + t]   + bias[n0 + t];
                        float b = c[i][jn+4][half*2 + t] + bias[n0 + 32 + t];
                        if (rot) {
                            float na = a * csh[jp][t] - b * snh[jp][t];
                            float nb = b * csw[jp][t] + a * snw[jp][t];
                            a = na; b = nb;
                        }
                        x1[t] = a; x2[t] = b;
                    }
                    *(uint32_t*)(Ch + (size_t)row * ED + n0)      = pack2h(x1[0], x1[1]);
                    *(uint32_t*)(Ch + (size_t)row * ED + n0 + 32) = pack2h(x2[0], x2[1]);
                }
            }
        }
    } else {
#pragma unroll
        for (int i = 0; i < 2; i++) {
            int m0 = bm + wm * 32 + i * 16 + (lane >> 2);
#pragma unroll
            for (int jn = 0; jn < 8; jn++) {
                int n0 = bn + wn * 64 + jn * 8 + (lane & 3) * 2;
                float bx = bias[n0], by = bias[n0 + 1];
                if (MODE == 1) {
                    if (m0 < M)
                        *(uint32_t*)(Ch + (size_t)m0 * ED + n0) =
                            pack2h(c[i][jn][0] + bx, c[i][jn][1] + by);
                    if (m0 + 8 < M)
                        *(uint32_t*)(Ch + (size_t)(m0 + 8) * ED + n0) =
                            pack2h(c[i][jn][2] + bx, c[i][jn][3] + by);
                } else {
                    if (m0 < M) {
                        float2 v = make_float2(c[i][jn][0] + bx, c[i][jn][1] + by);
                        *(float2*)&C[(size_t)m0 * ED + n0] = v;
                    }
                    if (m0 + 8 < M) {
                        float2 v = make_float2(c[i][jn][2] + bx, c[i][jn][3] + by);
                        *(float2*)&C[(size_t)(m0 + 8) * ED + n0] = v;
                    }
                }
            }
        }
    }
}

// ---------------- fp16 tensor-core flash attention (unchanged from R10) ----------------
#define TSTR 72
#define MATB (64 * TSTR * 2)          // 9216
#define STGB (2 * MATB)               // 18432 (K, V)
#define ATT_SMEM (2 * STGB)           // 36864

__global__ __launch_bounds__(128) void attn_mma(
    const __half* __restrict__ q, const __half* __restrict__ k,
    const __half* __restrict__ v, __half* __restrict__ o)
{
    extern __shared__ __align__(16) __half asmem[];
    const uint32_t sbase = (uint32_t)__cvta_generic_to_shared(asmem);

    const int tid  = threadIdx.x;
    const int lane = tid & 31;
    const int w    = tid >> 5;
    const int b    = blockIdx.z;
    const int h    = blockIdx.y;
    const int qt   = blockIdx.x;
    const size_t hoff = (size_t)h * HD;
    const size_t bbase = (size_t)b * SEQ;

    const int a_r = (lane & 7) + ((lane >> 3) & 1) * 8;
    const int a_c = ((lane >> 4) & 1) * 8;
    const int g   = lane >> 3;
    const int b_r = (lane & 7) + (g >> 1) * 8;
    const int b_c = (g & 1) * 8;

    for (int c = tid; c < 512; c += 128) {
        int row = c >> 3, seg = c & 7;
        int qrow = qt * 64 + row;
        if (qrow >= SEQ) qrow = SEQ - 1;
        const __half* src = q + (bbase + qrow) * ED + hoff + seg * 8;
        cp16(sbase + row * 144 + seg * 16, src, true);
    }
    asm volatile("cp.async.commit_group;");
    asm volatile("cp.async.wait_group 0;");
    __syncthreads();

    uint32_t qf[4][4];
#pragma unroll
    for (int kc = 0; kc < 4; kc++)
        LDSM4(qf[kc], sbase + (uint32_t)((w * 16 + a_r) * 144 + (kc * 16 + a_c) * 2));
    __syncthreads();

    auto load_kv = [&](int s, int t) {
        for (int c = tid; c < 1024; c += 128) {
            int mat = c >> 9, row = (c >> 3) & 63, seg = c & 7;
            int kr = t * 64 + row;
            int krc = (kr < SEQ) ? kr : 0;
            const __half* src = (mat ? v : k) + (bbase + krc) * ED + hoff + seg * 8;
            cp16(sbase + s * STGB + mat * MATB + row * 144 + seg * 16, src, kr < SEQ);
        }
    };
    load_kv(0, 0);
    asm volatile("cp.async.commit_group;");
    load_kv(1, 1);
    asm volatile("cp.async.commit_group;");

    float off_[8][4];
#pragma unroll
    for (int ng = 0; ng < 8; ng++)
#pragma unroll
        for (int r = 0; r < 4; r++) off_[ng][r] = 0.f;
    float m_lo = -1e30f, m_hi = -1e30f, l_lo = 0.f, l_hi = 0.f;

    const float SCL = 0.18033688011112042f;   // 0.125 * log2(e)

    for (int t = 0; t < NT; t++) {
        if (t < NT - 1) { asm volatile("cp.async.wait_group 1;"); }
        else            { asm volatile("cp.async.wait_group 0;"); }
        __syncthreads();
        const uint32_t sb2 = sbase + (uint32_t)((t & 1) * STGB);

        float sfr[8][4];
#pragma unroll
        for (int ng = 0; ng < 8; ng++)
#pragma unroll
            for (int r = 0; r < 4; r++) sfr[ng][r] = 0.f;

#pragma unroll
        for (int kc = 0; kc < 4; kc++) {
            uint32_t kf[4][4];
#pragma unroll
            for (int pp = 0; pp < 4; pp++)
                LDSM4(kf[pp], sb2 + (uint32_t)((pp * 16 + b_r) * 144 + (kc * 16 + b_c) * 2));
#pragma unroll
            for (int ng = 0; ng < 8; ng++)
                MMA_OP(sfr[ng], qf[kc], (kf[ng >> 1] + (ng & 1) * 2));
        }

        if (t * 64 + 64 > SEQ) {
            int tig2 = 2 * (lane & 3);
#pragma unroll
            for (int ng = 0; ng < 8; ng++) {
                int key0 = t * 64 + ng * 8 + tig2;
                if (key0     >= SEQ) { sfr[ng][0] = -1e30f; sfr[ng][2] = -1e30f; }
                if (key0 + 1 >= SEQ) { sfr[ng][1] = -1e30f; sfr[ng][3] = -1e30f; }
            }
        }

        float mx0 = -1e30f, mx1 = -1e30f;
#pragma unroll
        for (int ng = 0; ng < 8; ng++) {
            mx0 = fmaxf(mx0, fmaxf(sfr[ng][0], sfr[ng][1]));
            mx1 = fmaxf(mx1, fmaxf(sfr[ng][2], sfr[ng][3]));
        }
        mx0 = fmaxf(mx0, __shfl_xor_sync(0xffffffff, mx0, 1));
        mx0 = fmaxf(mx0, __shfl_xor_sync(0xffffffff, mx0, 2));
        mx1 = fmaxf(mx1, __shfl_xor_sync(0xffffffff, mx1, 1));
        mx1 = fmaxf(mx1, __shfl_xor_sync(0xffffffff, mx1, 2));
        float mn0 = fmaxf(m_lo, mx0), mn1 = fmaxf(m_hi, mx1);
        float al0 = ex2f((m_lo - mn0) * SCL), al1 = ex2f((m_hi - mn1) * SCL);
        m_lo = mn0; m_hi = mn1;

        float s0 = 0.f, s1 = 0.f;
#pragma unroll
        for (int ng = 0; ng < 8; ng++) {
            sfr[ng][0] = ex2f((sfr[ng][0] - mn0) * SCL);
            sfr[ng][1] = ex2f((sfr[ng][1] - mn0) * SCL);
            sfr[ng][2] = ex2f((sfr[ng][2] - mn1) * SCL);
            sfr[ng][3] = ex2f((sfr[ng][3] - mn1) * SCL);
            s0 += sfr[ng][0] + sfr[ng][1];
            s1 += sfr[ng][2] + sfr[ng][3];
        }
        s0 += __shfl_xor_sync(0xffffffff, s0, 1);
        s0 += __shfl_xor_sync(0xffffffff, s0, 2);
        s1 += __shfl_xor_sync(0xffffffff, s1, 1);
        s1 += __shfl_xor_sync(0xffffffff, s1, 2);
        l_lo = l_lo * al0 + s0;
        l_hi = l_hi * al1 + s1;

#pragma unroll
        for (int ng = 0; ng < 8; ng++) {
            off_[ng][0] *= al0; off_[ng][1] *= al0;
            off_[ng][2] *= al1; off_[ng][3] *= al1;
        }

        uint32_t ph[4][4];
#pragma unroll
        for (int kc = 0; kc < 4; kc++) {
            ph[kc][0] = pack2h(sfr[2*kc][0],   sfr[2*kc][1]);
            ph[kc][1] = pack2h(sfr[2*kc][2],   sfr[2*kc][3]);
            ph[kc][2] = pack2h(sfr[2*kc+1][0], sfr[2*kc+1][1]);
            ph[kc][3] = pack2h(sfr[2*kc+1][2], sfr[2*kc+1][3]);
        }

#pragma unroll
        for (int kc = 0; kc < 4; kc++) {
            uint32_t vf[4][4];
#pragma unroll
            for (int dp = 0; dp < 4; dp++)
                LDSM4T(vf[dp], sb2 + (uint32_t)(MATB +
                              (kc * 16 + a_r) * 144 + (dp * 16 + a_c) * 2));
#pragma unroll
            for (int ng = 0; ng < 8; ng++)
                MMA_OP(off_[ng], ph[kc], (vf[ng >> 1] + (ng & 1) * 2));
        }

        __syncthreads();
        if (t + 2 < NT) {
            load_kv(t & 1, t + 2);
            asm volatile("cp.async.commit_group;");
        }
    }

    float inv0 = 1.f / l_lo, inv1 = 1.f / l_hi;
    int q0 = qt * 64 + w * 16 + (lane >> 2);
    int col = 2 * (lane & 3);
#pragma unroll
    for (int ng = 0; ng < 8; ng++) {
        int n0 = ng * 8 + col;
        if (q0 < SEQ)
            *(uint32_t*)(o + (bbase + q0) * ED + hoff + n0) =
                pack2h(off_[ng][0] * inv0, off_[ng][1] * inv0);
        if (q0 + 8 < SEQ)
            *(uint32_t*)(o + (bbase + q0 + 8) * ED + hoff + n0) =
                pack2h(off_[ng][2] * inv1, off_[ng][3] * inv1);
    }
}

// ---------------- launch ----------------
extern "C" void kernel_launch(void* const* d_in, const int* in_sizes, int n_in,
                              void* d_out, int out_size)
{
    const float* hs = (const float*)d_in[0];
    const float* Wq = (const float*)d_in[1];
    const float* bq = (const float*)d_in[2];
    const float* Wk = (const float*)d_in[3];
    const float* bk = (const float*)d_in[4];
    const float* Wv = (const float*)d_in[5];
    const float* bv = (const float*)d_in[6];
    const float* Wo = (const float*)d_in[7];
    const float* bo = (const float*)d_in[8];
    float* out = (float*)d_out;

    __half *hsp, *wp, *qp, *kp, *vp, *op;
    cudaGetSymbolAddress((void**)&hsp, g_hs);
    cudaGetSymbolAddress((void**)&wp, g_w);
    cudaGetSymbolAddress((void**)&qp, g_qb);
    cudaGetSymbolAddress((void**)&kp, g_kb);
    cudaGetSymbolAddress((void**)&vp, g_vb);
    cudaGetSymbolAddress((void**)&op, g_ob);

    cudaFuncSetAttribute(gemm_f16<0>,
                         cudaFuncAttributeMaxDynamicSharedMemorySize, GSMEM);
    cudaFuncSetAttribute(gemm_f16<1>,
                         cudaFuncAttributeMaxDynamicSharedMemorySize, GSMEM);
    cudaFuncSetAttribute(gemm_f16<2>,
                         cudaFuncAttributeMaxDynamicSharedMemorySize, GSMEM);
    cudaFuncSetAttribute(attn_mma,
                         cudaFuncAttributeMaxDynamicSharedMemorySize, ATT_SMEM);

    const size_t WSZ = (size_t)ED * ED;
    const int n4_hs = MROWS * ED / 4;
    const int n4_w  = ED * ED / 4;

    cvt_half_kernel<<<(n4_hs + 255) / 256, 256>>>(hs, hsp, n4_hs);
    cvt_half4_kernel<<<(4 * n4_w + 255) / 256, 256>>>(Wq, Wk, Wv, Wo, wp, n4_w);

    dim3 ggrid(ED / BN, (MROWS + BM - 1) / BM);   // (8, 73)

    gemm_f16<2><<<ggrid, 256, GSMEM>>>(hsp, wp + 0*WSZ, bq, nullptr, qp, MROWS);
    gemm_f16<2><<<ggrid, 256, GSMEM>>>(hsp, wp + 1*WSZ, bk, nullptr, kp, MROWS);
    gemm_f16<1><<<ggrid, 256, GSMEM>>>(hsp, wp + 2*WSZ, bv, nullptr, vp, MROWS);

    attn_mma<<<dim3(QT, NH, BATCH), 128, ATT_SMEM>>>(qp, kp, vp, op);

    gemm_f16<0><<<ggrid, 256, GSMEM>>>(op, wp + 3*WSZ, bo, out, nullptr, MROWS);
}

// round 12
// speedup vs baseline: 12.8481x; 1.0057x over previous
#include <cuda_runtime.h>
#include <cuda_fp16.h>
#include <cstdint>
#include <math.h>

#define ED   1024
#define NH   16
#define HD   64
#define SEQ  577
#define BATCH 16
#define MROWS (BATCH * SEQ)   // 9232
#define NT   10
#define QT2  5                // ceil(577/128) query tiles of 128

// ---------------- scratch ----------------
__device__ __half g_hs[(size_t)MROWS * ED];
__device__ __half g_w[4][(size_t)ED * ED];   // Wq, Wk, Wv contiguous + Wo
__device__ __half g_qb[(size_t)MROWS * ED];
__device__ __half g_kb[(size_t)MROWS * ED];
__device__ __half g_vb[(size_t)MROWS * ED];
__device__ __half g_ob[(size_t)MROWS * ED];

// ---------------- helpers ----------------
__device__ __forceinline__ float ex2f(float x) {
    float r;
    asm("ex2.approx.ftz.f32 %0, %1;" : "=f"(r) : "f"(x));
    return r;
}
__device__ __forceinline__ uint32_t pack2h(float a, float b) {
    __half2 h = __floats2half2_rn(a, b);
    return *(uint32_t*)&h;
}

// ---------------- fp32 -> fp16 convert ----------------
__global__ void cvt_half_kernel(const float* __restrict__ x,
                                __half* __restrict__ o, int n4)
{
    int i = blockIdx.x * blockDim.x + threadIdx.x;
    if (i >= n4) return;
    float4 v = ((const float4*)x)[i];
    uint2 r;
    r.x = pack2h(v.x, v.y);
    r.y = pack2h(v.z, v.w);
    ((uint2*)o)[i] = r;
}

__global__ void cvt_half4_kernel(const float* __restrict__ w0, const float* __restrict__ w1,
                                 const float* __restrict__ w2, const float* __restrict__ w3,
                                 __half* __restrict__ wo, int n4_per)
{
    int i = blockIdx.x * blockDim.x + threadIdx.x;
    if (i >= 4 * n4_per) return;
    int sel = i / n4_per;
    int rem = i - sel * n4_per;
    const float* src = (sel == 0) ? w0 : (sel == 1) ? w1 : (sel == 2) ? w2 : w3;
    float4 v = ((const float4*)src)[rem];
    uint2 r;
    r.x = pack2h(v.x, v.y);
    r.y = pack2h(v.z, v.w);
    ((uint2*)(wo + (size_t)sel * ED * ED))[rem] = r;
}

// ---------------- MMA / ldmatrix / cp.async primitives ----------------
#define MMA_OP(d, a, b) asm volatile( \
    "mma.sync.aligned.m16n8k16.row.col.f32.f16.f16.f32 " \
    "{%0,%1,%2,%3},{%4,%5,%6,%7},{%8,%9},{%0,%1,%2,%3};" \
    : "+f"(d[0]), "+f"(d[1]), "+f"(d[2]), "+f"(d[3]) \
    : "r"(a[0]), "r"(a[1]), "r"(a[2]), "r"(a[3]), "r"(b[0]), "r"(b[1]))

#define LDSM4(r, addr) asm volatile( \
    "ldmatrix.sync.aligned.m8n8.x4.shared.b16 {%0,%1,%2,%3}, [%4];" \
    : "=r"(r[0]), "=r"(r[1]), "=r"(r[2]), "=r"(r[3]) : "r"(addr))

#define LDSM4T(r, addr) asm volatile( \
    "ldmatrix.sync.aligned.m8n8.x4.trans.shared.b16 {%0,%1,%2,%3}, [%4];" \
    : "=r"(r[0]), "=r"(r[1]), "=r"(r[2]), "=r"(r[3]) : "r"(addr))

__device__ __forceinline__ void cp16(uint32_t dst, const void* src, bool pred) {
    int sz = pred ? 16 : 0;
    asm volatile("cp.async.cg.shared.global [%0], [%1], 16, %2;\n"
                 :: "r"(dst), "l"(src), "r"(sz));
}

// ---------------- fp16 GEMM config ----------------
// BM=128, BN=128, BK=64, 256 threads (8 warps of 32x64), 3 stages, 2 CTAs/SM.
#define BM 128
#define BN 128
#define BK 64
#define SAST 72                       // 144B row stride
#define A_BYTES (128 * SAST * 2)      // 18432
#define B_BYTES (128 * SAST * 2)      // 18432
#define STG_B   (A_BYTES + B_BYTES)   // 36864
#define GSMEM   (3 * STG_B)           // 110592
#define ROPE_LC (13.287712379549449f / 16.f)

// shared mainloop: accumulates c[2][8][4] for this CTA tile
// (A rows bm.., W rows wrow_base..)
__device__ __forceinline__ void gemm_mainloop(
    const __half* __restrict__ A, const __half* __restrict__ W,
    uint32_t sbase, int tid, int bm, int wrow_base, int M,
    const uint32_t* aoff, const uint32_t* boff, float c[2][8][4])
{
    auto load_stage = [&](int s, int kt) {
        int k0 = kt * BK;
        uint32_t stb = sbase + (uint32_t)(s * STG_B);
#pragma unroll
        for (int i = 0; i < 8; i++) {
            int idx = tid + 256 * i;
            if (idx < 1024) {
                int row = idx >> 3, seg = idx & 7;
                const __half* src = A + (size_t)(bm + row) * ED + k0 + seg * 8;
                cp16(stb + (uint32_t)((row * SAST + seg * 8) * 2),
                     src, (bm + row) < M);
            } else {
                int j = idx - 1024;
                int row = j >> 3, seg = j & 7;
                const __half* src = W + (size_t)(wrow_base + row) * ED + k0 + seg * 8;
                cp16(stb + (uint32_t)(A_BYTES + (row * SAST + seg * 8) * 2),
                     src, true);
            }
        }
    };

    const int NK = ED / BK;  // 16
    load_stage(0, 0);
    asm volatile("cp.async.commit_group;");
    load_stage(1, 1);
    asm volatile("cp.async.commit_group;");

    for (int ks = 0; ks < NK; ks++) {
        if (ks < NK - 1) { asm volatile("cp.async.wait_group 1;"); }
        else             { asm volatile("cp.async.wait_group 0;"); }
        __syncthreads();

        if (ks + 2 < NK) load_stage((ks + 2) % 3, ks + 2);
        asm volatile("cp.async.commit_group;");

        const uint32_t sa = sbase + (uint32_t)((ks % 3) * STG_B);
#pragma unroll
        for (int kk = 0; kk < 4; kk++) {
            uint32_t af[2][4], bf[4][4];
#pragma unroll
            for (int i = 0; i < 2; i++)
                LDSM4(af[i], sa + aoff[i] + kk * 32);
#pragma unroll
            for (int j = 0; j < 4; j++)
                LDSM4(bf[j], sa + boff[j] + kk * 32);
#pragma unroll
            for (int i = 0; i < 2; i++)
#pragma unroll
                for (int jj = 0; jj < 4; jj++) {
                    MMA_OP(c[i][2*jj],   af[i], (bf[jj] + 0));
                    MMA_OP(c[i][2*jj+1], af[i], (bf[jj] + 2));
                }
        }
    }
}

// ---------------- fused QKV GEMM (N = 3072) ----------------
// blockIdx.x in [0,24): sel = bx>>3 chooses Q/K/V; cn = (bx&7)*128 is the
// within-matrix column base. Q,K get fused 2D-RoPE; V plain fp16.
__global__ __launch_bounds__(256, 2) void gemm_qkv(
    const __half* __restrict__ A, const __half* __restrict__ Wqkv,
    const float* __restrict__ bq, const float* __restrict__ bk,
    const float* __restrict__ bv,
    __half* __restrict__ qo, __half* __restrict__ ko, __half* __restrict__ vo,
    int M)
{
    extern __shared__ __align__(16) char smem[];
    const uint32_t sbase = (uint32_t)__cvta_generic_to_shared(smem);

    const int tid  = threadIdx.x;
    const int lane = tid & 31;
    const int wid  = tid >> 5;
    const int wm   = wid & 3;
    const int wn   = wid >> 2;
    const int bm   = blockIdx.y * BM;
    const int bng  = blockIdx.x * BN;          // global N in [0,3072)
    const int sel  = bng >> 10;                // 0=Q,1=K,2=V
    const int cn   = bng & 1023;               // within-matrix col base

    const float* bias = (sel == 0) ? bq : (sel == 1) ? bk : bv;
    __half* out = (sel == 0) ? qo : (sel == 1) ? ko : vo;
    const bool do_rope = (sel < 2);

    const int a_r = (lane & 7) + ((lane >> 3) & 1) * 8;
    const int a_c = ((lane >> 4) & 1) * 8;
    const int g   = lane >> 3;
    const int b_r = (lane & 7) + (g >> 1) * 8;
    const int b_c = (g & 1) * 8;

    uint32_t aoff[2], boff[4];
#pragma unroll
    for (int i = 0; i < 2; i++)
        aoff[i] = (uint32_t)(((wm * 32 + i * 16 + a_r) * SAST + a_c) * 2);
#pragma unroll
    for (int j = 0; j < 4; j++)
        boff[j] = (uint32_t)(A_BYTES + ((wn * 64 + j * 16 + b_r) * SAST + b_c) * 2);

    float c[2][8][4];
#pragma unroll
    for (int i = 0; i < 2; i++)
#pragma unroll
        for (int j = 0; j < 8; j++)
#pragma unroll
            for (int r = 0; r < 4; r++) c[i][j][r] = 0.f;

    gemm_mainloop(A, Wqkv, sbase, tid, bm, bng, M, aoff, boff, c);

    // epilogue: fused RoPE (Q,K) or plain fp16 (V)
    float invf[2][2];
#pragma unroll
    for (int jp = 0; jp < 2; jp++)
#pragma unroll
        for (int t = 0; t < 2; t++)
            invf[jp][t] = ex2f(-(float)(jp * 8 + (lane & 3) * 2 + t) * ROPE_LC);

#pragma unroll
    for (int i = 0; i < 2; i++) {
        int row0 = bm + wm * 32 + i * 16 + (lane >> 2);
#pragma unroll
        for (int half = 0; half < 2; half++) {
            int row = row0 + half * 8;
            if (row >= M) continue;
            int pr = row % SEQ;
            bool rot = do_rope && (pr > 0);
            float snh[2][2], csh[2][2], snw[2][2], csw[2][2];
            if (rot) {
                int p = pr - 1;
                float fgh = (float)(p / 24), fgw = (float)(p % 24);
#pragma unroll
                for (int jp = 0; jp < 2; jp++)
#pragma unroll
                    for (int t = 0; t < 2; t++) {
                        __sincosf(fgh * invf[jp][t], &snh[jp][t], &csh[jp][t]);
                        __sincosf(fgw * invf[jp][t], &snw[jp][t], &csw[jp][t]);
                    }
            }
#pragma unroll
            for (int jn = 0; jn < 4; jn++) {
                int n0 = cn + wn * 64 + jn * 8 + (lane & 3) * 2;
                int jp = jn & 1;
                float x1[2], x2[2];
#pragma unroll
                for (int t = 0; t < 2; t++) {
                    float a = c[i][jn][half*2 + t]   + bias[n0 + t];
                    float b = c[i][jn+4][half*2 + t] + bias[n0 + 32 + t];
                    if (rot) {
                        float na = a * csh[jp][t] - b * snh[jp][t];
                        float nb = b * csw[jp][t] + a * snw[jp][t];
                        a = na; b = nb;
                    }
                    x1[t] = a; x2[t] = b;
                }
                *(uint32_t*)(out + (size_t)row * ED + n0)      = pack2h(x1[0], x1[1]);
                *(uint32_t*)(out + (size_t)row * ED + n0 + 32) = pack2h(x2[0], x2[1]);
            }
        }
    }
}

// ---------------- out-proj GEMM (fp32 out) ----------------
__global__ __launch_bounds__(256, 2) void gemm_out(
    const __half* __restrict__ A, const __half* __restrict__ W,
    const float* __restrict__ bias, float* __restrict__ C, int M)
{
    extern __shared__ __align__(16) char smem[];
    const uint32_t sbase = (uint32_t)__cvta_generic_to_shared(smem);

    const int tid  = threadIdx.x;
    const int lane = tid & 31;
    const int wid  = tid >> 5;
    const int wm   = wid & 3;
    const int wn   = wid >> 2;
    const int bm   = blockIdx.y * BM;
    const int bn   = blockIdx.x * BN;

    const int a_r = (lane & 7) + ((lane >> 3) & 1) * 8;
    const int a_c = ((lane >> 4) & 1) * 8;
    const int g   = lane >> 3;
    const int b_r = (lane & 7) + (g >> 1) * 8;
    const int b_c = (g & 1) * 8;

    uint32_t aoff[2], boff[4];
#pragma unroll
    for (int i = 0; i < 2; i++)
        aoff[i] = (uint32_t)(((wm * 32 + i * 16 + a_r) * SAST + a_c) * 2);
#pragma unroll
    for (int j = 0; j < 4; j++)
        boff[j] = (uint32_t)(A_BYTES + ((wn * 64 + j * 16 + b_r) * SAST + b_c) * 2);

    float c[2][8][4];
#pragma unroll
    for (int i = 0; i < 2; i++)
#pragma unroll
        for (int j = 0; j < 8; j++)
#pragma unroll
            for (int r = 0; r < 4; r++) c[i][j][r] = 0.f;

    gemm_mainloop(A, W, sbase, tid, bm, bn, M, aoff, boff, c);

#pragma unroll
    for (int i = 0; i < 2; i++) {
        int m0 = bm + wm * 32 + i * 16 + (lane >> 2);
#pragma unroll
        for (int jn = 0; jn < 8; jn++) {
            int n0 = bn + wn * 64 + jn * 8 + (lane & 3) * 2;
            float bx = bias[n0], by = bias[n0 + 1];
            if (m0 < M) {
                float2 v = make_float2(c[i][jn][0] + bx, c[i][jn][1] + by);
                *(float2*)&C[(size_t)m0 * ED + n0] = v;
            }
            if (m0 + 8 < M) {
                float2 v = make_float2(c[i][jn][2] + bx, c[i][jn][3] + by);
                *(float2*)&C[(size_t)(m0 + 8) * ED + n0] = v;
            }
        }
    }
}

// ---------------- fp16 flash attention, 128-query tiles ----------------
#define TSTR 72
#define MATB (64 * TSTR * 2)          // 9216
#define STGB (2 * MATB)               // 18432 (K, V)
#define ATT_SMEM (2 * STGB)           // 36864

__global__ __launch_bounds__(256) void attn_mma(
    const __half* __restrict__ q, const __half* __restrict__ k,
    const __half* __restrict__ v, __half* __restrict__ o)
{
    extern __shared__ __align__(16) __half asmem[];
    const uint32_t sbase = (uint32_t)__cvta_generic_to_shared(asmem);

    const int tid  = threadIdx.x;
    const int lane = tid & 31;
    const int w    = tid >> 5;          // 8 warps, 16 q-rows each
    const int b    = blockIdx.z;
    const int h    = blockIdx.y;
    const int qt   = blockIdx.x;
    const size_t hoff = (size_t)h * HD;
    const size_t bbase = (size_t)b * SEQ;

    const int a_r = (lane & 7) + ((lane >> 3) & 1) * 8;
    const int a_c = ((lane >> 4) & 1) * 8;
    const int g   = lane >> 3;
    const int b_r = (lane & 7) + (g >> 1) * 8;
    const int b_c = (g & 1) * 8;

    // Q tile (128 rows) into stage0+stage1 area (18432B), then into regs
    for (int c = tid; c < 1024; c += 256) {
        int row = c >> 3, seg = c & 7;
        int qrow = qt * 128 + row;
        if (qrow >= SEQ) qrow = SEQ - 1;
        const __half* src = q + (bbase + qrow) * ED + hoff + seg * 8;
        cp16(sbase + row * 144 + seg * 16, src, true);
    }
    asm volatile("cp.async.commit_group;");
    asm volatile("cp.async.wait_group 0;");
    __syncthreads();

    uint32_t qf[4][4];
#pragma unroll
    for (int kc = 0; kc < 4; kc++)
        LDSM4(qf[kc], sbase + (uint32_t)((w * 16 + a_r) * 144 + (kc * 16 + a_c) * 2));
    __syncthreads();

    auto load_kv = [&](int s, int t) {
        for (int c = tid; c < 1024; c += 256) {
            int mat = c >> 9, row = (c >> 3) & 63, seg = c & 7;
            int kr = t * 64 + row;
            int krc = (kr < SEQ) ? kr : 0;
            const __half* src = (mat ? v : k) + (bbase + krc) * ED + hoff + seg * 8;
            cp16(sbase + s * STGB + mat * MATB + row * 144 + seg * 16, src, kr < SEQ);
        }
    };
    load_kv(0, 0);
    asm volatile("cp.async.commit_group;");
    load_kv(1, 1);
    asm volatile("cp.async.commit_group;");

    float off_[8][4];
#pragma unroll
    for (int ng = 0; ng < 8; ng++)
#pragma unroll
        for (int r = 0; r < 4; r++) off_[ng][r] = 0.f;
    float m_lo = -1e30f, m_hi = -1e30f, l_lo = 0.f, l_hi = 0.f;

    const float SCL = 0.18033688011112042f;   // 0.125 * log2(e)

    for (int t = 0; t < NT; t++) {
        if (t < NT - 1) { asm volatile("cp.async.wait_group 1;"); }
        else            { asm volatile("cp.async.wait_group 0;"); }
        __syncthreads();
        const uint32_t sb2 = sbase + (uint32_t)((t & 1) * STGB);

        float sfr[8][4];
#pragma unroll
        for (int ng = 0; ng < 8; ng++)
#pragma unroll
            for (int r = 0; r < 4; r++) sfr[ng][r] = 0.f;

#pragma unroll
        for (int kc = 0; kc < 4; kc++) {
            uint32_t kf[4][4];
#pragma unroll
            for (int pp = 0; pp < 4; pp++)
                LDSM4(kf[pp], sb2 + (uint32_t)((pp * 16 + b_r) * 144 + (kc * 16 + b_c) * 2));
#pragma unroll
            for (int ng = 0; ng < 8; ng++)
                MMA_OP(sfr[ng], qf[kc], (kf[ng >> 1] + (ng & 1) * 2));
        }

        if (t * 64 + 64 > SEQ) {
            int tig2 = 2 * (lane & 3);
#pragma unroll
            for (int ng = 0; ng < 8; ng++) {
                int key0 = t * 64 + ng * 8 + tig2;
                if (key0     >= SEQ) { sfr[ng][0] = -1e30f; sfr[ng][2] = -1e30f; }
                if (key0 + 1 >= SEQ) { sfr[ng][1] = -1e30f; sfr[ng][3] = -1e30f; }
            }
        }

        float mx0 = -1e30f, mx1 = -1e30f;
#pragma unroll
        for (int ng = 0; ng < 8; ng++) {
            mx0 = fmaxf(mx0, fmaxf(sfr[ng][0], sfr[ng][1]));
            mx1 = fmaxf(mx1, fmaxf(sfr[ng][2], sfr[ng][3]));
        }
        mx0 = fmaxf(mx0, __shfl_xor_sync(0xffffffff, mx0, 1));
        mx0 = fmaxf(mx0, __shfl_xor_sync(0xffffffff, mx0, 2));
        mx1 = fmaxf(mx1, __shfl_xor_sync(0xffffffff, mx1, 1));
        mx1 = fmaxf(mx1, __shfl_xor_sync(0xffffffff, mx1, 2));
        float mn0 = fmaxf(m_lo, mx0), mn1 = fmaxf(m_hi, mx1);
        float al0 = ex2f((m_lo - mn0) * SCL), al1 = ex2f((m_hi - mn1) * SCL);
        m_lo = mn0; m_hi = mn1;

        float s0 = 0.f, s1 = 0.f;
#pragma unroll
        for (int ng = 0; ng < 8; ng++) {
            sfr[ng][0] = ex2f((sfr[ng][0] - mn0) * SCL);
            sfr[ng][1] = ex2f((sfr[ng][1] - mn0) * SCL);
            sfr[ng][2] = ex2f((sfr[ng][2] - mn1) * SCL);
            sfr[ng][3] = ex2f((sfr[ng][3] - mn1) * SCL);
            s0 += sfr[ng][0] + sfr[ng][1];
            s1 += sfr[ng][2] + sfr[ng][3];
        }
        s0 += __shfl_xor_sync(0xffffffff, s0, 1);
        s0 += __shfl_xor_sync(0xffffffff, s0, 2);
        s1 += __shfl_xor_sync(0xffffffff, s1, 1);
        s1 += __shfl_xor_sync(0xffffffff, s1, 2);
        l_lo = l_lo * al0 + s0;
        l_hi = l_hi * al1 + s1;

#pragma unroll
        for (int ng = 0; ng < 8; ng++) {
            off_[ng][0] *= al0; off_[ng][1] *= al0;
            off_[ng][2] *= al1; off_[ng][3] *= al1;
        }

        uint32_t ph[4][4];
#pragma unroll
        for (int kc = 0; kc < 4; kc++) {
            ph[kc][0] = pack2h(sfr[2*kc][0],   sfr[2*kc][1]);
            ph[kc][1] = pack2h(sfr[2*kc][2],   sfr[2*kc][3]);
            ph[kc][2] = pack2h(sfr[2*kc+1][0], sfr[2*kc+1][1]);
            ph[kc][3] = pack2h(sfr[2*kc+1][2], sfr[2*kc+1][3]);
        }

#pragma unroll
        for (int kc = 0; kc < 4; kc++) {
            uint32_t vf[4][4];
#pragma unroll
            for (int dp = 0; dp < 4; dp++)
                LDSM4T(vf[dp], sb2 + (uint32_t)(MATB +
                              (kc * 16 + a_r) * 144 + (dp * 16 + a_c) * 2));
#pragma unroll
            for (int ng = 0; ng < 8; ng++)
                MMA_OP(off_[ng], ph[kc], (vf[ng >> 1] + (ng & 1) * 2));
        }

        __syncthreads();
        if (t + 2 < NT) {
            load_kv(t & 1, t + 2);
            asm volatile("cp.async.commit_group;");
        }
    }

    float inv0 = 1.f / l_lo, inv1 = 1.f / l_hi;
    int q0 = qt * 128 + w * 16 + (lane >> 2);
    int col = 2 * (lane & 3);
#pragma unroll
    for (int ng = 0; ng < 8; ng++) {
        int n0 = ng * 8 + col;
        if (q0 < SEQ)
            *(uint32_t*)(o + (bbase + q0) * ED + hoff + n0) =
                pack2h(off_[ng][0] * inv0, off_[ng][1] * inv0);
        if (q0 + 8 < SEQ)
            *(uint32_t*)(o + (bbase + q0 + 8) * ED + hoff + n0) =
                pack2h(off_[ng][2] * inv1, off_[ng][3] * inv1);
    }
}

// ---------------- launch ----------------
extern "C" void kernel_launch(void* const* d_in, const int* in_sizes, int n_in,
                              void* d_out, int out_size)
{
    const float* hs = (const float*)d_in[0];
    const float* Wq = (const float*)d_in[1];
    const float* bq = (const float*)d_in[2];
    const float* Wk = (const float*)d_in[3];
    const float* bk = (const float*)d_in[4];
    const float* Wv = (const float*)d_in[5];
    const float* bv = (const float*)d_in[6];
    const float* Wo = (const float*)d_in[7];
    const float* bo = (const float*)d_in[8];
    float* out = (float*)d_out;

    __half *hsp, *wp, *qp, *kp, *vp, *op;
    cudaGetSymbolAddress((void**)&hsp, g_hs);
    cudaGetSymbolAddress((void**)&wp, g_w);
    cudaGetSymbolAddress((void**)&qp, g_qb);
    cudaGetSymbolAddress((void**)&kp, g_kb);
    cudaGetSymbolAddress((void**)&vp, g_vb);
    cudaGetSymbolAddress((void**)&op, g_ob);

    cudaFuncSetAttribute(gemm_qkv,
                         cudaFuncAttributeMaxDynamicSharedMemorySize, GSMEM);
    cudaFuncSetAttribute(gemm_out,
                         cudaFuncAttributeMaxDynamicSharedMemorySize, GSMEM);
    cudaFuncSetAttribute(attn_mma,
                         cudaFuncAttributeMaxDynamicSharedMemorySize, ATT_SMEM);

    const size_t WSZ = (size_t)ED * ED;
    const int n4_hs = MROWS * ED / 4;
    const int n4_w  = ED * ED / 4;

    cvt_half_kernel<<<(n4_hs + 255) / 256, 256>>>(hs, hsp, n4_hs);
    cvt_half4_kernel<<<(4 * n4_w + 255) / 256, 256>>>(Wq, Wk, Wv, Wo, wp, n4_w);

    dim3 qkv_grid(3 * ED / BN, (MROWS + BM - 1) / BM);   // (24, 73)
    gemm_qkv<<<qkv_grid, 256, GSMEM>>>(hsp, wp, bq, bk, bv, qp, kp, vp, MROWS);

    attn_mma<<<dim3(QT2, NH, BATCH), 256, ATT_SMEM>>>(qp, kp, vp, op);

    dim3 out_grid(ED / BN, (MROWS + BM - 1) / BM);       // (8, 73)
    gemm_out<<<out_grid, 256, GSMEM>>>(op, wp + 3*WSZ, bo, out, MROWS);
}